// round 1
// baseline (speedup 1.0000x reference)
#include <cuda_runtime.h>
#include <math.h>
#include <stdint.h>

// Problem dims (fixed by reference)
#define NB 4
#define NT 2048
#define NC 2048
#define NH 16
#define ND 128
#define NBH (NB*NH)          // 64
#define M1 (NB*NT)           // 8192

// ---------------------------------------------------------------------------
// Device scratch (allocation-free rule: __device__ globals)
// ---------------------------------------------------------------------------
__device__ float g_q[16777216];   // [B*H][T][D]
__device__ float g_k[16777216];
__device__ float g_v[16777216];
__device__ float g_att[16777216]; // [B*T][C]

// ---------------------------------------------------------------------------
// Generic fp32 SGEMM, 128x128x16 tiles, 256 threads, 8x8 per thread.
// EPI==0: C = A@B + bias, scattered into g_q/g_k/g_v head-major (QKV GEMM)
// EPI==1: C = g_att@B + bias, plain row-major into C param (output GEMM)
// ---------------------------------------------------------------------------
template<int EPI>
__global__ __launch_bounds__(256)
void sgemm_kernel(const float* __restrict__ A, const float* __restrict__ Bmat,
                  const float* __restrict__ bias, float* __restrict__ C,
                  int M, int N, int K)
{
    __shared__ float Ast[16][132];   // A tile transposed [k][m], padded
    __shared__ float Bs[16][128];    // B tile [k][n]

    const int t  = threadIdx.x;
    const int tx = t & 15, ty = t >> 4;
    const int bn = blockIdx.x, bm = blockIdx.y;

    const float* Ap = (EPI == 1) ? (const float*)g_att : A;

    float acc[8][8];
    #pragma unroll
    for (int i = 0; i < 8; ++i)
        #pragma unroll
        for (int j = 0; j < 8; ++j) acc[i][j] = 0.f;

    const int ar = t >> 2, ac4 = t & 3;   // A-load mapping
    const int br = t >> 5, bc4 = t & 31;  // B-load mapping

    const float* Arow0 = Ap + (size_t)(bm * 128 + ar) * K;
    const float* Arow1 = Arow0 + (size_t)64 * K;

    for (int kt = 0; kt < K; kt += 16) {
        float4 a0 = *(const float4*)(Arow0 + kt + ac4 * 4);
        float4 a1 = *(const float4*)(Arow1 + kt + ac4 * 4);
        float4 b0 = *(const float4*)(Bmat + (size_t)(kt + br) * N + bn * 128 + bc4 * 4);
        float4 b1 = *(const float4*)(Bmat + (size_t)(kt + br + 8) * N + bn * 128 + bc4 * 4);
        __syncthreads();   // previous compute done before overwriting tiles
        Ast[ac4*4+0][ar] = a0.x;  Ast[ac4*4+1][ar] = a0.y;
        Ast[ac4*4+2][ar] = a0.z;  Ast[ac4*4+3][ar] = a0.w;
        Ast[ac4*4+0][ar+64] = a1.x;  Ast[ac4*4+1][ar+64] = a1.y;
        Ast[ac4*4+2][ar+64] = a1.z;  Ast[ac4*4+3][ar+64] = a1.w;
        *(float4*)&Bs[br][bc4*4]     = b0;
        *(float4*)&Bs[br + 8][bc4*4] = b1;
        __syncthreads();

        #pragma unroll
        for (int kk = 0; kk < 16; ++kk) {
            float4 af0 = *(const float4*)&Ast[kk][ty * 4];
            float4 af1 = *(const float4*)&Ast[kk][ty * 4 + 64];
            float4 bf0 = *(const float4*)&Bs[kk][tx * 4];
            float4 bf1 = *(const float4*)&Bs[kk][tx * 4 + 64];
            float av[8] = {af0.x, af0.y, af0.z, af0.w, af1.x, af1.y, af1.z, af1.w};
            float bv[8] = {bf0.x, bf0.y, bf0.z, bf0.w, bf1.x, bf1.y, bf1.z, bf1.w};
            #pragma unroll
            for (int i = 0; i < 8; ++i)
                #pragma unroll
                for (int j = 0; j < 8; ++j)
                    acc[i][j] += av[i] * bv[j];
        }
    }

    // Epilogue
    #pragma unroll
    for (int vm = 0; vm < 2; ++vm) {
        #pragma unroll
        for (int i = 0; i < 4; ++i) {
            int mg = bm * 128 + vm * 64 + ty * 4 + i;
            #pragma unroll
            for (int vn = 0; vn < 2; ++vn) {
                int nloc  = vn * 64 + tx * 4;
                int nbase = bn * 128 + nloc;
                float4 r;
                r.x = acc[vm*4+i][vn*4+0] + bias[nbase+0];
                r.y = acc[vm*4+i][vn*4+1] + bias[nbase+1];
                r.z = acc[vm*4+i][vn*4+2] + bias[nbase+2];
                r.w = acc[vm*4+i][vn*4+3] + bias[nbase+3];
                if (EPI == 0) {
                    // n = which*2048 + h*128 + d  (qkv.reshape(B,T,3,H,D))
                    int which = nbase >> 11;
                    int h     = (nbase >> 7) & 15;
                    int d     = nbase & 127;
                    float* dst = (which == 0) ? (float*)g_q
                               : (which == 1) ? (float*)g_k : (float*)g_v;
                    int b  = mg >> 11;
                    int tq = mg & 2047;
                    size_t off = ((size_t)(b * 16 + h) * NT + tq) * ND + d;
                    *(float4*)&dst[off] = r;
                } else {
                    *(float4*)&C[(size_t)mg * N + nbase] = r;
                }
            }
        }
    }
}

// ---------------------------------------------------------------------------
// RoPE, in-place on g_q / g_k. One thread per (bh, t, f<64) pair, x2 buffers.
// ---------------------------------------------------------------------------
__global__ void rope_kernel()
{
    const int PER = NBH * NT * 64;  // 8388608
    int idx = blockIdx.x * blockDim.x + threadIdx.x;
    float* buf = (idx < PER) ? (float*)g_q : (float*)g_k;
    int r = (idx < PER) ? idx : idx - PER;
    int f    = r & 63;
    int tpos = (r >> 6) & (NT - 1);
    int bh   = r >> 17;
    size_t base = ((size_t)bh * NT + tpos) * ND;
    float theta = powf(10000.0f, -(2.0f * (float)f) * (1.0f / 128.0f));
    float ang = (float)tpos * theta;
    float s, c;
    sincosf(ang, &s, &c);
    float x1 = buf[base + f];
    float x2 = buf[base + f + 64];
    buf[base + f]      = x1 * c - x2 * s;
    buf[base + f + 64] = x1 * s + x2 * c;
}

// ---------------------------------------------------------------------------
// Causal flash attention, fp32. BQ=BK=64, D=128, 256 threads.
// smem: Q/K/V row-major stride 132 (float4-aligned, low-conflict), S stride 65.
// ---------------------------------------------------------------------------
#define ATTN_SMEM ((3 * 64 * 132 + 64 * 65 + 3 * 64) * 4)

__global__ __launch_bounds__(256)
void attn_kernel()
{
    extern __shared__ float sm[];
    float* sQ = sm;
    float* sK = sQ + 64 * 132;
    float* sV = sK + 64 * 132;
    float* sS = sV + 64 * 132;   // [64][65]
    float* sM  = sS + 64 * 65;
    float* sL  = sM + 64;
    float* sAl = sL + 64;

    const int t  = threadIdx.x;
    const int qb = 31 - blockIdx.x;   // heavy q-blocks first
    const int bh = blockIdx.y;
    const float scale = 0.088388347648318447f;  // 1/sqrt(128)

    const float* Qg = g_q + ((size_t)bh * NT + qb * 64) * ND;
    const float* Kg = g_k + (size_t)bh * NT * ND;
    const float* Vg = g_v + (size_t)bh * NT * ND;

    #pragma unroll
    for (int it = 0; it < 8; ++it) {
        int idx = t + it * 256;
        int r = idx >> 5, c4 = idx & 31;
        *(float4*)&sQ[r * 132 + c4 * 4] = *(const float4*)&Qg[r * 128 + c4 * 4];
    }
    if (t < 64) { sM[t] = -1e30f; sL[t] = 0.f; }

    float oacc[32];
    #pragma unroll
    for (int i = 0; i < 32; ++i) oacc[i] = 0.f;

    const int ty = t >> 4, tx = t & 15;  // QK^T mapping (strided 4x4)
    const int i0 = (t >> 3) * 2;          // PV mapping: 2 rows
    const int cg = t & 7;                 // PV col group

    __syncthreads();

    for (int kb = 0; kb <= qb; ++kb) {
        const float* Kt = Kg + (size_t)kb * 64 * 128;
        const float* Vt = Vg + (size_t)kb * 64 * 128;
        #pragma unroll
        for (int it = 0; it < 8; ++it) {
            int idx = t + it * 256;
            int r = idx >> 5, c4 = idx & 31;
            *(float4*)&sK[r * 132 + c4 * 4] = *(const float4*)&Kt[r * 128 + c4 * 4];
            *(float4*)&sV[r * 132 + c4 * 4] = *(const float4*)&Vt[r * 128 + c4 * 4];
        }
        __syncthreads();

        // ---- S = Q K^T * scale (64x64), strided 4x4 per thread ----
        float acc[4][4];
        #pragma unroll
        for (int v = 0; v < 4; ++v)
            #pragma unroll
            for (int u = 0; u < 4; ++u) acc[v][u] = 0.f;

        #pragma unroll 4
        for (int d4 = 0; d4 < 32; ++d4) {
            float4 a[4], bb[4];
            #pragma unroll
            for (int v = 0; v < 4; ++v)
                a[v] = *(const float4*)&sQ[(ty + 16 * v) * 132 + d4 * 4];
            #pragma unroll
            for (int u = 0; u < 4; ++u)
                bb[u] = *(const float4*)&sK[(tx + 16 * u) * 132 + d4 * 4];
            #pragma unroll
            for (int v = 0; v < 4; ++v)
                #pragma unroll
                for (int u = 0; u < 4; ++u)
                    acc[v][u] += a[v].x * bb[u].x + a[v].y * bb[u].y +
                                 a[v].z * bb[u].z + a[v].w * bb[u].w;
        }
        const bool diag = (kb == qb);
        #pragma unroll
        for (int v = 0; v < 4; ++v)
            #pragma unroll
            for (int u = 0; u < 4; ++u) {
                int i = ty + 16 * v, j = tx + 16 * u;
                float s = acc[v][u] * scale;
                if (diag && j > i) s = -1e30f;
                sS[i * 65 + j] = s;
            }
        __syncthreads();

        // ---- online softmax, 4 threads per row ----
        {
            int i = t >> 2, p = t & 3;
            float sv[16];
            float mloc = -1e30f;
            #pragma unroll
            for (int jj = 0; jj < 16; ++jj) {
                sv[jj] = sS[i * 65 + p * 16 + jj];
                mloc = fmaxf(mloc, sv[jj]);
            }
            mloc = fmaxf(mloc, __shfl_xor_sync(0xffffffffu, mloc, 1));
            mloc = fmaxf(mloc, __shfl_xor_sync(0xffffffffu, mloc, 2));
            float mprev = sM[i];
            float mnew  = fmaxf(mprev, mloc);
            float lsum = 0.f;
            #pragma unroll
            for (int jj = 0; jj < 16; ++jj) {
                float e = __expf(sv[jj] - mnew);
                sS[i * 65 + p * 16 + jj] = e;
                lsum += e;
            }
            lsum += __shfl_xor_sync(0xffffffffu, lsum, 1);
            lsum += __shfl_xor_sync(0xffffffffu, lsum, 2);
            if (p == 0) {
                float alpha = __expf(mprev - mnew);
                sAl[i] = alpha;
                sL[i]  = sL[i] * alpha + lsum;
                sM[i]  = mnew;
            }
        }
        __syncthreads();

        // ---- O = O*alpha + P V : thread owns rows {i0,i0+1}, 16 strided cols ----
        {
            float al0 = sAl[i0], al1 = sAl[i0 + 1];
            #pragma unroll
            for (int k = 0; k < 4; ++k)
                #pragma unroll
                for (int c = 0; c < 4; ++c) {
                    oacc[k * 8 + c]     *= al0;
                    oacc[k * 8 + 4 + c] *= al1;
                }
            #pragma unroll 4
            for (int j = 0; j < 64; ++j) {
                float p0 = sS[i0 * 65 + j];
                float p1 = sS[(i0 + 1) * 65 + j];
                #pragma unroll
                for (int k = 0; k < 4; ++k) {
                    float4 vv = *(const float4*)&sV[j * 132 + cg * 4 + k * 32];
                    oacc[k*8+0] += p0 * vv.x;  oacc[k*8+1] += p0 * vv.y;
                    oacc[k*8+2] += p0 * vv.z;  oacc[k*8+3] += p0 * vv.w;
                    oacc[k*8+4] += p1 * vv.x;  oacc[k*8+5] += p1 * vv.y;
                    oacc[k*8+6] += p1 * vv.z;  oacc[k*8+7] += p1 * vv.w;
                }
            }
        }
        __syncthreads();
    }

    // ---- finalize: divide by l, write to g_att in [B,T,C] layout ----
    float inv0 = 1.f / sL[i0];
    float inv1 = 1.f / sL[i0 + 1];
    int b = bh >> 4, h = bh & 15;
    size_t row0 = ((size_t)b * NT + qb * 64 + i0) * NC + h * ND;
    #pragma unroll
    for (int k = 0; k < 4; ++k) {
        float4 w0, w1;
        w0.x = oacc[k*8+0] * inv0; w0.y = oacc[k*8+1] * inv0;
        w0.z = oacc[k*8+2] * inv0; w0.w = oacc[k*8+3] * inv0;
        w1.x = oacc[k*8+4] * inv1; w1.y = oacc[k*8+5] * inv1;
        w1.z = oacc[k*8+6] * inv1; w1.w = oacc[k*8+7] * inv1;
        *(float4*)&g_att[row0 + cg * 4 + k * 32]      = w0;
        *(float4*)&g_att[row0 + NC + cg * 4 + k * 32] = w1;
    }
}

// ---------------------------------------------------------------------------
// Launch
// ---------------------------------------------------------------------------
extern "C" void kernel_launch(void* const* d_in, const int* in_sizes, int n_in,
                              void* d_out, int out_size)
{
    const float* x    = (const float*)d_in[0];
    const float* Wqkv = (const float*)d_in[1];
    const float* bqkv = (const float*)d_in[2];
    const float* Wo   = (const float*)d_in[3];
    const float* bo   = (const float*)d_in[4];
    float* out = (float*)d_out;

    cudaFuncSetAttribute(attn_kernel,
                         cudaFuncAttributeMaxDynamicSharedMemorySize, ATTN_SMEM);

    // 1) QKV = x @ Wqkv + bqkv, scattered to head-major g_q/g_k/g_v
    sgemm_kernel<0><<<dim3(48, 64), 256>>>(x, Wqkv, bqkv, nullptr, M1, 3 * NC, NC);

    // 2) RoPE on q and k (in place)
    rope_kernel<<<65536, 256>>>();

    // 3) causal flash attention -> g_att [B*T, C]
    attn_kernel<<<dim3(32, 64), 256, ATTN_SMEM>>>();

    // 4) out = g_att @ Wo + bo
    sgemm_kernel<1><<<dim3(16, 64), 256>>>(nullptr, Wo, bo, out, M1, NC, NC);
}

// round 4
// speedup vs baseline: 1.7416x; 1.7416x over previous
#include <cuda_runtime.h>
#include <cuda_bf16.h>
#include <math.h>
#include <stdint.h>

// Problem dims (fixed by reference)
#define NB 4
#define NT 2048
#define NC 2048
#define NH 16
#define ND 128
#define NBH (NB*NH)          // 64
#define M1 (NB*NT)           // 8192
#define KDIM 2048

// ---------------------------------------------------------------------------
// Device scratch (allocation-free rule: __device__ globals)
// ---------------------------------------------------------------------------
__device__ __align__(256) float g_q[16777216];   // [B*H][T][D]
__device__ __align__(256) float g_k[16777216];
__device__ __align__(256) float g_v[16777216];
__device__ __align__(256) float g_att[16777216]; // [B*T][C]

__device__ __align__(256) __nv_bfloat16 g_Ahi[16777216];   // x split   [8192][2048]
__device__ __align__(256) __nv_bfloat16 g_Alo[16777216];
__device__ __align__(256) __nv_bfloat16 g_Whi[12582912];   // Wqkv^T    [6144][2048]
__device__ __align__(256) __nv_bfloat16 g_Wlo[12582912];
__device__ __align__(256) __nv_bfloat16 g_Wohi[4194304];   // Wo^T      [2048][2048]
__device__ __align__(256) __nv_bfloat16 g_Wolo[4194304];
__device__ __align__(256) __nv_bfloat16 g_atthi[16777216]; // att split [8192][2048]
__device__ __align__(256) __nv_bfloat16 g_attlo[16777216];

// ---------------------------------------------------------------------------
// PTX helpers (Ampere-class, valid under compute_103)
// ---------------------------------------------------------------------------
__device__ __forceinline__ uint32_t smem_u32(const void* p) {
    uint32_t a;
    asm("{ .reg .u64 t; cvta.to.shared.u64 t, %1; cvt.u32.u64 %0, t; }"
        : "=r"(a) : "l"(p));
    return a;
}
__device__ __forceinline__ void cp16(uint32_t s, const void* g) {
    asm volatile("cp.async.cg.shared.global [%0], [%1], 16;" :: "r"(s), "l"(g));
}
__device__ __forceinline__ void ldm4(uint32_t* r, uint32_t addr) {
    asm volatile("ldmatrix.sync.aligned.m8n8.x4.shared.b16 {%0,%1,%2,%3}, [%4];"
                 : "=r"(r[0]), "=r"(r[1]), "=r"(r[2]), "=r"(r[3]) : "r"(addr));
}
__device__ __forceinline__ void mma_bf16(float* c, const uint32_t* a, const uint32_t* b) {
    asm volatile(
        "mma.sync.aligned.m16n8k16.row.col.f32.bf16.bf16.f32 "
        "{%0,%1,%2,%3}, {%4,%5,%6,%7}, {%8,%9}, {%0,%1,%2,%3};"
        : "+f"(c[0]), "+f"(c[1]), "+f"(c[2]), "+f"(c[3])
        : "r"(a[0]), "r"(a[1]), "r"(a[2]), "r"(a[3]), "r"(b[0]), "r"(b[1]));
}

// ---------------------------------------------------------------------------
// bf16x3 mma.sync GEMM: C[M,N] = A[M,K] @ B^T  (B stored [N][K] K-major)
// BM=128 BN=128 BK=64, 256 threads (8 warps, 2x4), warp tile 64x32.
// Terms: Ahi*Bhi + Ahi*Blo + Alo*Bhi into fp32 accum.
// EPI==0: bias + scatter to g_q/g_k/g_v head-major.  EPI==1: bias + C row-major.
// smem stage (64KB): Ahi[128][64] | Alo | Bhi[128][64] | Blo, SW128 xor swizzle.
// ---------------------------------------------------------------------------
#define BK 64
#define NKCH (KDIM/BK)       // 32
#define STG_SZ 65536
#define GEMM_SMEM (2*STG_SZ) // 131072

__device__ __forceinline__ void load_stage64(
    uint32_t stg, int t, int koff,
    const __nv_bfloat16* pAh, const __nv_bfloat16* pAl,
    const __nv_bfloat16* pBh, const __nv_bfloat16* pBl)
{
    #pragma unroll
    for (int i = 0; i < 4; ++i) {
        int idx = t + i * 256;
        int r = idx >> 3, ci = idx & 7;
        uint32_t so = stg + r * 128 + ((ci ^ (r & 7)) << 4);
        size_t go = (size_t)r * KDIM + koff + ci * 8;
        cp16(so,          pAh + go);
        cp16(so + 16384,  pAl + go);
        cp16(so + 32768,  pBh + go);
        cp16(so + 49152,  pBl + go);
    }
    asm volatile("cp.async.commit_group;" ::: "memory");
}

__device__ __forceinline__ void compute_stage(
    uint32_t stg, int wm, int wn, int lane, float acc[4][4][4])
{
    const int r = lane & 7, g = lane >> 3;
    const uint32_t rx = (uint32_t)r << 4;
    const uint32_t baseA = stg + (uint32_t)(wm * 64 + (g & 1) * 8 + r) * 128;
    const uint32_t hA4   = (uint32_t)(g >> 1) << 4;
    const uint32_t baseB = stg + 32768 + (uint32_t)(wn * 32 + (g >> 1) * 8 + r) * 128;
    const uint32_t hB4   = (uint32_t)(g & 1) << 4;

    #pragma unroll
    for (int s = 0; s < 4; ++s) {
        const uint32_t offA = (((uint32_t)s << 5) | hA4) ^ rx;
        const uint32_t offB = (((uint32_t)s << 5) | hB4) ^ rx;
        uint32_t ah[4][4], al[4][4], bh[2][4], bl[2][4];
        #pragma unroll
        for (int i = 0; i < 4; ++i) {
            ldm4(ah[i], baseA + i * 2048 + offA);
            ldm4(al[i], baseA + 16384 + i * 2048 + offA);
        }
        #pragma unroll
        for (int j = 0; j < 2; ++j) {
            ldm4(bh[j], baseB + j * 2048 + offB);
            ldm4(bl[j], baseB + 16384 + j * 2048 + offB);
        }
        #pragma unroll
        for (int i = 0; i < 4; ++i)
            #pragma unroll
            for (int q = 0; q < 4; ++q) {
                const int jj = q >> 1, qq = (q & 1) * 2;
                mma_bf16(acc[i][q], ah[i], &bh[jj][qq]);  // hi*hi
                mma_bf16(acc[i][q], ah[i], &bl[jj][qq]);  // hi*lo
                mma_bf16(acc[i][q], al[i], &bh[jj][qq]);  // lo*hi
            }
    }
}

template<int EPI>
__global__ __launch_bounds__(256)
void gemm_bf16x3(const __nv_bfloat16* __restrict__ Ah, const __nv_bfloat16* __restrict__ Al,
                 const __nv_bfloat16* __restrict__ Bh, const __nv_bfloat16* __restrict__ Bl,
                 const float* __restrict__ bias, float* __restrict__ C)
{
    extern __shared__ __align__(1024) char smbuf[];
    uint32_t sb = smem_u32(smbuf);
    const int t    = threadIdx.x;
    const int lane = t & 31, wid = t >> 5;
    const int wm   = wid >> 2, wn = wid & 3;
    const int m0   = blockIdx.y * 128;
    const int n0   = blockIdx.x * 128;

    float acc[4][4][4];
    #pragma unroll
    for (int i = 0; i < 4; ++i)
        #pragma unroll
        for (int q = 0; q < 4; ++q)
            #pragma unroll
            for (int k = 0; k < 4; ++k) acc[i][q][k] = 0.f;

    const __nv_bfloat16* pAh = Ah + (size_t)m0 * KDIM;
    const __nv_bfloat16* pAl = Al + (size_t)m0 * KDIM;
    const __nv_bfloat16* pBh = Bh + (size_t)n0 * KDIM;
    const __nv_bfloat16* pBl = Bl + (size_t)n0 * KDIM;

    load_stage64(sb,          t, 0,  pAh, pAl, pBh, pBl);
    load_stage64(sb + STG_SZ, t, BK, pAh, pAl, pBh, pBl);

    #pragma unroll 1
    for (int kt = 0; kt < NKCH; ++kt) {
        if (kt == NKCH - 1) asm volatile("cp.async.wait_group 0;" ::: "memory");
        else                asm volatile("cp.async.wait_group 1;" ::: "memory");
        __syncthreads();
        compute_stage(sb + (kt & 1) * STG_SZ, wm, wn, lane, acc);
        __syncthreads();
        if (kt + 2 < NKCH)
            load_stage64(sb + (kt & 1) * STG_SZ, t, (kt + 2) * BK, pAh, pAl, pBh, pBl);
    }

    // Epilogue: thread lane holds c0,c1=(m, n..n+1), c2,c3=(m+8, n..n+1)
    const int mr  = (lane >> 2);
    const int nc0 = (lane & 3) * 2;
    if (EPI == 0) {
        const int which = n0 >> 11;
        const int h     = (n0 >> 7) & 15;
        float* dst = (which == 0) ? (float*)g_q
                   : (which == 1) ? (float*)g_k : (float*)g_v;
        const int b = m0 >> 11;
        #pragma unroll
        for (int i = 0; i < 4; ++i) {
            const int m  = m0 + wm * 64 + i * 16 + mr;
            const int tq = m & 2047;
            #pragma unroll
            for (int q = 0; q < 4; ++q) {
                const int dl = wn * 32 + q * 8 + nc0;
                float2 bs = *(const float2*)&bias[n0 + dl];
                size_t off = ((size_t)(b * 16 + h) * NT + tq) * ND + dl;
                float2 v0, v1;
                v0.x = acc[i][q][0] + bs.x;  v0.y = acc[i][q][1] + bs.y;
                v1.x = acc[i][q][2] + bs.x;  v1.y = acc[i][q][3] + bs.y;
                *(float2*)&dst[off]            = v0;
                *(float2*)&dst[off + 8 * ND]   = v1;
            }
        }
    } else {
        #pragma unroll
        for (int i = 0; i < 4; ++i) {
            const int m = m0 + wm * 64 + i * 16 + mr;
            #pragma unroll
            for (int q = 0; q < 4; ++q) {
                const int n = n0 + wn * 32 + q * 8 + nc0;
                float2 bs = *(const float2*)&bias[n];
                float2 v0, v1;
                v0.x = acc[i][q][0] + bs.x;  v0.y = acc[i][q][1] + bs.y;
                v1.x = acc[i][q][2] + bs.x;  v1.y = acc[i][q][3] + bs.y;
                *(float2*)&C[(size_t)m * NC + n]       = v0;
                *(float2*)&C[(size_t)(m + 8) * NC + n] = v1;
            }
        }
    }
}

// ---------------------------------------------------------------------------
// fp32 -> bf16 hi/lo split (same layout)
// ---------------------------------------------------------------------------
__global__ void conv_split_kernel(const float* __restrict__ in,
                                  __nv_bfloat16* __restrict__ hi,
                                  __nv_bfloat16* __restrict__ lo, int n4)
{
    int i = blockIdx.x * blockDim.x + threadIdx.x;
    if (i >= n4) return;
    float4 v = ((const float4*)in)[i];
    float a[4] = {v.x, v.y, v.z, v.w};
    __nv_bfloat16 h[4], l[4];
    #pragma unroll
    for (int j = 0; j < 4; ++j) {
        h[j] = __float2bfloat16(a[j]);
        l[j] = __float2bfloat16(a[j] - __bfloat162float(h[j]));
    }
    __nv_bfloat162* hp = (__nv_bfloat162*)hi;
    __nv_bfloat162* lp = (__nv_bfloat162*)lo;
    hp[2 * i]     = __halves2bfloat162(h[0], h[1]);
    hp[2 * i + 1] = __halves2bfloat162(h[2], h[3]);
    lp[2 * i]     = __halves2bfloat162(l[0], l[1]);
    lp[2 * i + 1] = __halves2bfloat162(l[2], l[3]);
}

// ---------------------------------------------------------------------------
// fp32 [K][N] -> transposed bf16 hi/lo [N][K]
// ---------------------------------------------------------------------------
__global__ void transpose_split_kernel(const float* __restrict__ in,
                                       __nv_bfloat16* __restrict__ hi,
                                       __nv_bfloat16* __restrict__ lo,
                                       int K, int N)
{
    __shared__ float tile[32][33];
    const int n0 = blockIdx.x * 32, k0 = blockIdx.y * 32;
    const int tx = threadIdx.x, ty = threadIdx.y;
    #pragma unroll
    for (int i = 0; i < 32; i += 8)
        tile[ty + i][tx] = in[(size_t)(k0 + ty + i) * N + n0 + tx];
    __syncthreads();
    #pragma unroll
    for (int i = 0; i < 32; i += 8) {
        float v = tile[tx][ty + i];
        __nv_bfloat16 h = __float2bfloat16(v);
        __nv_bfloat16 l = __float2bfloat16(v - __bfloat162float(h));
        size_t o = (size_t)(n0 + ty + i) * K + k0 + tx;
        hi[o] = h;
        lo[o] = l;
    }
}

// ---------------------------------------------------------------------------
// RoPE, in-place on g_q / g_k
// ---------------------------------------------------------------------------
__global__ void rope_kernel()
{
    const int PER = NBH * NT * 64;  // 8388608
    int idx = blockIdx.x * blockDim.x + threadIdx.x;
    float* buf = (idx < PER) ? (float*)g_q : (float*)g_k;
    int r = (idx < PER) ? idx : idx - PER;
    int f    = r & 63;
    int tpos = (r >> 6) & (NT - 1);
    int bh   = r >> 17;
    size_t base = ((size_t)bh * NT + tpos) * ND;
    float theta = powf(10000.0f, -(2.0f * (float)f) * (1.0f / 128.0f));
    float ang = (float)tpos * theta;
    float s, c;
    sincosf(ang, &s, &c);
    float x1 = buf[base + f];
    float x2 = buf[base + f + 64];
    buf[base + f]      = x1 * c - x2 * s;
    buf[base + f + 64] = x1 * s + x2 * c;
}

// ---------------------------------------------------------------------------
// Causal flash attention, fp32 (unchanged, known-good)
// ---------------------------------------------------------------------------
#define ATTN_SMEM ((3 * 64 * 132 + 64 * 65 + 3 * 64) * 4)

__global__ __launch_bounds__(256)
void attn_kernel()
{
    extern __shared__ float sm[];
    float* sQ = sm;
    float* sK = sQ + 64 * 132;
    float* sV = sK + 64 * 132;
    float* sS = sV + 64 * 132;   // [64][65]
    float* sM  = sS + 64 * 65;
    float* sL  = sM + 64;
    float* sAl = sL + 64;

    const int t  = threadIdx.x;
    const int qb = 31 - blockIdx.x;   // heavy q-blocks first
    const int bh = blockIdx.y;
    const float scale = 0.088388347648318447f;  // 1/sqrt(128)

    const float* Qg = g_q + ((size_t)bh * NT + qb * 64) * ND;
    const float* Kg = g_k + (size_t)bh * NT * ND;
    const float* Vg = g_v + (size_t)bh * NT * ND;

    #pragma unroll
    for (int it = 0; it < 8; ++it) {
        int idx = t + it * 256;
        int r = idx >> 5, c4 = idx & 31;
        *(float4*)&sQ[r * 132 + c4 * 4] = *(const float4*)&Qg[r * 128 + c4 * 4];
    }
    if (t < 64) { sM[t] = -1e30f; sL[t] = 0.f; }

    float oacc[32];
    #pragma unroll
    for (int i = 0; i < 32; ++i) oacc[i] = 0.f;

    const int ty = t >> 4, tx = t & 15;
    const int i0 = (t >> 3) * 2;
    const int cg = t & 7;

    __syncthreads();

    for (int kb = 0; kb <= qb; ++kb) {
        const float* Kt = Kg + (size_t)kb * 64 * 128;
        const float* Vt = Vg + (size_t)kb * 64 * 128;
        #pragma unroll
        for (int it = 0; it < 8; ++it) {
            int idx = t + it * 256;
            int r = idx >> 5, c4 = idx & 31;
            *(float4*)&sK[r * 132 + c4 * 4] = *(const float4*)&Kt[r * 128 + c4 * 4];
            *(float4*)&sV[r * 132 + c4 * 4] = *(const float4*)&Vt[r * 128 + c4 * 4];
        }
        __syncthreads();

        float acc[4][4];
        #pragma unroll
        for (int v = 0; v < 4; ++v)
            #pragma unroll
            for (int u = 0; u < 4; ++u) acc[v][u] = 0.f;

        #pragma unroll 4
        for (int d4 = 0; d4 < 32; ++d4) {
            float4 a[4], bb[4];
            #pragma unroll
            for (int v = 0; v < 4; ++v)
                a[v] = *(const float4*)&sQ[(ty + 16 * v) * 132 + d4 * 4];
            #pragma unroll
            for (int u = 0; u < 4; ++u)
                bb[u] = *(const float4*)&sK[(tx + 16 * u) * 132 + d4 * 4];
            #pragma unroll
            for (int v = 0; v < 4; ++v)
                #pragma unroll
                for (int u = 0; u < 4; ++u)
                    acc[v][u] += a[v].x * bb[u].x + a[v].y * bb[u].y +
                                 a[v].z * bb[u].z + a[v].w * bb[u].w;
        }
        const bool diag = (kb == qb);
        #pragma unroll
        for (int v = 0; v < 4; ++v)
            #pragma unroll
            for (int u = 0; u < 4; ++u) {
                int i = ty + 16 * v, j = tx + 16 * u;
                float s = acc[v][u] * scale;
                if (diag && j > i) s = -1e30f;
                sS[i * 65 + j] = s;
            }
        __syncthreads();

        {
            int i = t >> 2, p = t & 3;
            float sv[16];
            float mloc = -1e30f;
            #pragma unroll
            for (int jj = 0; jj < 16; ++jj) {
                sv[jj] = sS[i * 65 + p * 16 + jj];
                mloc = fmaxf(mloc, sv[jj]);
            }
            mloc = fmaxf(mloc, __shfl_xor_sync(0xffffffffu, mloc, 1));
            mloc = fmaxf(mloc, __shfl_xor_sync(0xffffffffu, mloc, 2));
            float mprev = sM[i];
            float mnew  = fmaxf(mprev, mloc);
            float lsum = 0.f;
            #pragma unroll
            for (int jj = 0; jj < 16; ++jj) {
                float e = __expf(sv[jj] - mnew);
                sS[i * 65 + p * 16 + jj] = e;
                lsum += e;
            }
            lsum += __shfl_xor_sync(0xffffffffu, lsum, 1);
            lsum += __shfl_xor_sync(0xffffffffu, lsum, 2);
            if (p == 0) {
                float alpha = __expf(mprev - mnew);
                sAl[i] = alpha;
                sL[i]  = sL[i] * alpha + lsum;
                sM[i]  = mnew;
            }
        }
        __syncthreads();

        {
            float al0 = sAl[i0], al1 = sAl[i0 + 1];
            #pragma unroll
            for (int k = 0; k < 4; ++k)
                #pragma unroll
                for (int c = 0; c < 4; ++c) {
                    oacc[k * 8 + c]     *= al0;
                    oacc[k * 8 + 4 + c] *= al1;
                }
            #pragma unroll 4
            for (int j = 0; j < 64; ++j) {
                float p0 = sS[i0 * 65 + j];
                float p1 = sS[(i0 + 1) * 65 + j];
                #pragma unroll
                for (int k = 0; k < 4; ++k) {
                    float4 vv = *(const float4*)&sV[j * 132 + cg * 4 + k * 32];
                    oacc[k*8+0] += p0 * vv.x;  oacc[k*8+1] += p0 * vv.y;
                    oacc[k*8+2] += p0 * vv.z;  oacc[k*8+3] += p0 * vv.w;
                    oacc[k*8+4] += p1 * vv.x;  oacc[k*8+5] += p1 * vv.y;
                    oacc[k*8+6] += p1 * vv.z;  oacc[k*8+7] += p1 * vv.w;
                }
            }
        }
        __syncthreads();
    }

    float inv0 = 1.f / sL[i0];
    float inv1 = 1.f / sL[i0 + 1];
    int b = bh >> 4, h = bh & 15;
    size_t row0 = ((size_t)b * NT + qb * 64 + i0) * NC + h * ND;
    #pragma unroll
    for (int k = 0; k < 4; ++k) {
        float4 w0, w1;
        w0.x = oacc[k*8+0] * inv0; w0.y = oacc[k*8+1] * inv0;
        w0.z = oacc[k*8+2] * inv0; w0.w = oacc[k*8+3] * inv0;
        w1.x = oacc[k*8+4] * inv1; w1.y = oacc[k*8+5] * inv1;
        w1.z = oacc[k*8+6] * inv1; w1.w = oacc[k*8+7] * inv1;
        *(float4*)&g_att[row0 + cg * 4 + k * 32]      = w0;
        *(float4*)&g_att[row0 + NC + cg * 4 + k * 32] = w1;
    }
}

// ---------------------------------------------------------------------------
// Launch
// ---------------------------------------------------------------------------
extern "C" void kernel_launch(void* const* d_in, const int* in_sizes, int n_in,
                              void* d_out, int out_size)
{
    const float* x    = (const float*)d_in[0];
    const float* Wqkv = (const float*)d_in[1];
    const float* bqkv = (const float*)d_in[2];
    const float* Wo   = (const float*)d_in[3];
    const float* bo   = (const float*)d_in[4];
    float* out = (float*)d_out;

    cudaFuncSetAttribute(attn_kernel,
                         cudaFuncAttributeMaxDynamicSharedMemorySize, ATTN_SMEM);
    cudaFuncSetAttribute(gemm_bf16x3<0>,
                         cudaFuncAttributeMaxDynamicSharedMemorySize, GEMM_SMEM);
    cudaFuncSetAttribute(gemm_bf16x3<1>,
                         cudaFuncAttributeMaxDynamicSharedMemorySize, GEMM_SMEM);

    __nv_bfloat16 *Ahi, *Alo, *Whi, *Wlo, *Wohi, *Wolo, *atthi, *attlo;
    cudaGetSymbolAddress((void**)&Ahi,   g_Ahi);
    cudaGetSymbolAddress((void**)&Alo,   g_Alo);
    cudaGetSymbolAddress((void**)&Whi,   g_Whi);
    cudaGetSymbolAddress((void**)&Wlo,   g_Wlo);
    cudaGetSymbolAddress((void**)&Wohi,  g_Wohi);
    cudaGetSymbolAddress((void**)&Wolo,  g_Wolo);
    cudaGetSymbolAddress((void**)&atthi, g_atthi);
    cudaGetSymbolAddress((void**)&attlo, g_attlo);
    float* att;
    cudaGetSymbolAddress((void**)&att, g_att);

    // 1) splits: x -> Ahi/Alo ; Wqkv^T -> Whi/Wlo ; Wo^T -> Wohi/Wolo
    conv_split_kernel<<<16384, 256>>>(x, Ahi, Alo, 4194304);
    transpose_split_kernel<<<dim3(192, 64), dim3(32, 8)>>>(Wqkv, Whi, Wlo, 2048, 6144);
    transpose_split_kernel<<<dim3(64, 64),  dim3(32, 8)>>>(Wo, Wohi, Wolo, 2048, 2048);

    // 2) QKV = x @ Wqkv + bqkv (mma.sync bf16x3), scattered head-major
    gemm_bf16x3<0><<<dim3(48, 64), 256, GEMM_SMEM>>>(Ahi, Alo, Whi, Wlo, bqkv, nullptr);

    // 3) RoPE on q and k (in place)
    rope_kernel<<<65536, 256>>>();

    // 4) causal flash attention -> g_att [B*T, C]
    attn_kernel<<<dim3(32, 64), 256, ATTN_SMEM>>>();

    // 5) att split + out = att @ Wo + bo (mma.sync bf16x3)
    conv_split_kernel<<<16384, 256>>>(att, atthi, attlo, 4194304);
    gemm_bf16x3<1><<<dim3(16, 64), 256, GEMM_SMEM>>>(atthi, attlo, Wohi, Wolo, bo, out);
}

// round 5
// speedup vs baseline: 3.0319x; 1.7408x over previous
#include <cuda_runtime.h>
#include <cuda_bf16.h>
#include <math.h>
#include <stdint.h>

// Problem dims (fixed by reference)
#define NB 4
#define NT 2048
#define NC 2048
#define NH 16
#define ND 128
#define NBH (NB*NH)          // 64
#define M1 (NB*NT)           // 8192
#define KDIM 2048

// ---------------------------------------------------------------------------
// Device scratch (allocation-free rule: __device__ globals)
// ---------------------------------------------------------------------------
__device__ __align__(256) float g_q[16777216];   // [B*H][T][D] fp32 (pre-rope)
__device__ __align__(256) float g_k[16777216];
__device__ __align__(256) float g_v[16777216];

__device__ __align__(256) __nv_bfloat16 g_Ahi[16777216];   // x split   [8192][2048]
__device__ __align__(256) __nv_bfloat16 g_Alo[16777216];
__device__ __align__(256) __nv_bfloat16 g_Whi[12582912];   // Wqkv^T    [6144][2048]
__device__ __align__(256) __nv_bfloat16 g_Wlo[12582912];
__device__ __align__(256) __nv_bfloat16 g_Wohi[4194304];   // Wo^T      [2048][2048]
__device__ __align__(256) __nv_bfloat16 g_Wolo[4194304];
__device__ __align__(256) __nv_bfloat16 g_atthi[16777216]; // att split [8192][2048]
__device__ __align__(256) __nv_bfloat16 g_attlo[16777216];

__device__ __align__(256) __nv_bfloat16 g_qhi[16777216];   // rope'd q  [bh][t][d]
__device__ __align__(256) __nv_bfloat16 g_qlo[16777216];
__device__ __align__(256) __nv_bfloat16 g_khi[16777216];   // rope'd k  [bh][t][d]
__device__ __align__(256) __nv_bfloat16 g_klo[16777216];
__device__ __align__(256) __nv_bfloat16 g_vhiT[16777216];  // v^T       [bh][d][t]
__device__ __align__(256) __nv_bfloat16 g_vloT[16777216];

// ---------------------------------------------------------------------------
// PTX helpers (Ampere-class, valid under compute_103)
// ---------------------------------------------------------------------------
__device__ __forceinline__ uint32_t smem_u32(const void* p) {
    uint32_t a;
    asm("{ .reg .u64 t; cvta.to.shared.u64 t, %1; cvt.u32.u64 %0, t; }"
        : "=r"(a) : "l"(p));
    return a;
}
__device__ __forceinline__ void cp16(uint32_t s, const void* g) {
    asm volatile("cp.async.cg.shared.global [%0], [%1], 16;" :: "r"(s), "l"(g));
}
__device__ __forceinline__ void ldm4(uint32_t* r, uint32_t addr) {
    asm volatile("ldmatrix.sync.aligned.m8n8.x4.shared.b16 {%0,%1,%2,%3}, [%4];"
                 : "=r"(r[0]), "=r"(r[1]), "=r"(r[2]), "=r"(r[3]) : "r"(addr));
}
__device__ __forceinline__ void mma_bf16(float* c, const uint32_t* a, const uint32_t* b) {
    asm volatile(
        "mma.sync.aligned.m16n8k16.row.col.f32.bf16.bf16.f32 "
        "{%0,%1,%2,%3}, {%4,%5,%6,%7}, {%8,%9}, {%0,%1,%2,%3};"
        : "+f"(c[0]), "+f"(c[1]), "+f"(c[2]), "+f"(c[3])
        : "r"(a[0]), "r"(a[1]), "r"(a[2]), "r"(a[3]), "r"(b[0]), "r"(b[1]));
}
__device__ __forceinline__ float ex2(float x) {
    float y; asm("ex2.approx.f32 %0, %1;" : "=f"(y) : "f"(x)); return y;
}
__device__ __forceinline__ void packhl(float x, float y, uint32_t& hi, uint32_t& lo) {
    __nv_bfloat16 hx = __float2bfloat16(x), hy = __float2bfloat16(y);
    __nv_bfloat162 hp = __halves2bfloat162(hx, hy);
    hi = *(uint32_t*)&hp;
    __nv_bfloat16 lx = __float2bfloat16(x - __bfloat162float(hx));
    __nv_bfloat16 ly = __float2bfloat16(y - __bfloat162float(hy));
    __nv_bfloat162 lp = __halves2bfloat162(lx, ly);
    lo = *(uint32_t*)&lp;
}

// ---------------------------------------------------------------------------
// bf16x3 mma.sync GEMM (unchanged from R4): C[M,N] = A[M,K] @ B^T
// ---------------------------------------------------------------------------
#define BK 64
#define NKCH (KDIM/BK)       // 32
#define STG_SZ 65536
#define GEMM_SMEM (2*STG_SZ) // 131072

__device__ __forceinline__ void load_stage64(
    uint32_t stg, int t, int koff,
    const __nv_bfloat16* pAh, const __nv_bfloat16* pAl,
    const __nv_bfloat16* pBh, const __nv_bfloat16* pBl)
{
    #pragma unroll
    for (int i = 0; i < 4; ++i) {
        int idx = t + i * 256;
        int r = idx >> 3, ci = idx & 7;
        uint32_t so = stg + r * 128 + ((ci ^ (r & 7)) << 4);
        size_t go = (size_t)r * KDIM + koff + ci * 8;
        cp16(so,          pAh + go);
        cp16(so + 16384,  pAl + go);
        cp16(so + 32768,  pBh + go);
        cp16(so + 49152,  pBl + go);
    }
    asm volatile("cp.async.commit_group;" ::: "memory");
}

__device__ __forceinline__ void compute_stage(
    uint32_t stg, int wm, int wn, int lane, float acc[4][4][4])
{
    const int r = lane & 7, g = lane >> 3;
    const uint32_t rx = (uint32_t)r << 4;
    const uint32_t baseA = stg + (uint32_t)(wm * 64 + (g & 1) * 8 + r) * 128;
    const uint32_t hA4   = (uint32_t)(g >> 1) << 4;
    const uint32_t baseB = stg + 32768 + (uint32_t)(wn * 32 + (g >> 1) * 8 + r) * 128;
    const uint32_t hB4   = (uint32_t)(g & 1) << 4;

    #pragma unroll
    for (int s = 0; s < 4; ++s) {
        const uint32_t offA = (((uint32_t)s << 5) | hA4) ^ rx;
        const uint32_t offB = (((uint32_t)s << 5) | hB4) ^ rx;
        uint32_t ah[4][4], al[4][4], bh[2][4], bl[2][4];
        #pragma unroll
        for (int i = 0; i < 4; ++i) {
            ldm4(ah[i], baseA + i * 2048 + offA);
            ldm4(al[i], baseA + 16384 + i * 2048 + offA);
        }
        #pragma unroll
        for (int j = 0; j < 2; ++j) {
            ldm4(bh[j], baseB + j * 2048 + offB);
            ldm4(bl[j], baseB + 16384 + j * 2048 + offB);
        }
        #pragma unroll
        for (int i = 0; i < 4; ++i)
            #pragma unroll
            for (int q = 0; q < 4; ++q) {
                const int jj = q >> 1, qq = (q & 1) * 2;
                mma_bf16(acc[i][q], ah[i], &bh[jj][qq]);
                mma_bf16(acc[i][q], ah[i], &bl[jj][qq]);
                mma_bf16(acc[i][q], al[i], &bh[jj][qq]);
            }
    }
}

template<int EPI>
__global__ __launch_bounds__(256)
void gemm_bf16x3(const __nv_bfloat16* __restrict__ Ah, const __nv_bfloat16* __restrict__ Al,
                 const __nv_bfloat16* __restrict__ Bh, const __nv_bfloat16* __restrict__ Bl,
                 const float* __restrict__ bias, float* __restrict__ C)
{
    extern __shared__ __align__(1024) char smbuf[];
    uint32_t sb = smem_u32(smbuf);
    const int t    = threadIdx.x;
    const int lane = t & 31, wid = t >> 5;
    const int wm   = wid >> 2, wn = wid & 3;
    const int m0   = blockIdx.y * 128;
    const int n0   = blockIdx.x * 128;

    float acc[4][4][4];
    #pragma unroll
    for (int i = 0; i < 4; ++i)
        #pragma unroll
        for (int q = 0; q < 4; ++q)
            #pragma unroll
            for (int k = 0; k < 4; ++k) acc[i][q][k] = 0.f;

    const __nv_bfloat16* pAh = Ah + (size_t)m0 * KDIM;
    const __nv_bfloat16* pAl = Al + (size_t)m0 * KDIM;
    const __nv_bfloat16* pBh = Bh + (size_t)n0 * KDIM;
    const __nv_bfloat16* pBl = Bl + (size_t)n0 * KDIM;

    load_stage64(sb,          t, 0,  pAh, pAl, pBh, pBl);
    load_stage64(sb + STG_SZ, t, BK, pAh, pAl, pBh, pBl);

    #pragma unroll 1
    for (int kt = 0; kt < NKCH; ++kt) {
        if (kt == NKCH - 1) asm volatile("cp.async.wait_group 0;" ::: "memory");
        else                asm volatile("cp.async.wait_group 1;" ::: "memory");
        __syncthreads();
        compute_stage(sb + (kt & 1) * STG_SZ, wm, wn, lane, acc);
        __syncthreads();
        if (kt + 2 < NKCH)
            load_stage64(sb + (kt & 1) * STG_SZ, t, (kt + 2) * BK, pAh, pAl, pBh, pBl);
    }

    const int mr  = (lane >> 2);
    const int nc0 = (lane & 3) * 2;
    if (EPI == 0) {
        const int which = n0 >> 11;
        const int h     = (n0 >> 7) & 15;
        float* dst = (which == 0) ? (float*)g_q
                   : (which == 1) ? (float*)g_k : (float*)g_v;
        const int b = m0 >> 11;
        #pragma unroll
        for (int i = 0; i < 4; ++i) {
            const int m  = m0 + wm * 64 + i * 16 + mr;
            const int tq = m & 2047;
            #pragma unroll
            for (int q = 0; q < 4; ++q) {
                const int dl = wn * 32 + q * 8 + nc0;
                float2 bs = *(const float2*)&bias[n0 + dl];
                size_t off = ((size_t)(b * 16 + h) * NT + tq) * ND + dl;
                float2 v0, v1;
                v0.x = acc[i][q][0] + bs.x;  v0.y = acc[i][q][1] + bs.y;
                v1.x = acc[i][q][2] + bs.x;  v1.y = acc[i][q][3] + bs.y;
                *(float2*)&dst[off]            = v0;
                *(float2*)&dst[off + 8 * ND]   = v1;
            }
        }
    } else {
        #pragma unroll
        for (int i = 0; i < 4; ++i) {
            const int m = m0 + wm * 64 + i * 16 + mr;
            #pragma unroll
            for (int q = 0; q < 4; ++q) {
                const int n = n0 + wn * 32 + q * 8 + nc0;
                float2 bs = *(const float2*)&bias[n];
                float2 v0, v1;
                v0.x = acc[i][q][0] + bs.x;  v0.y = acc[i][q][1] + bs.y;
                v1.x = acc[i][q][2] + bs.x;  v1.y = acc[i][q][3] + bs.y;
                *(float2*)&C[(size_t)m * NC + n]       = v0;
                *(float2*)&C[(size_t)(m + 8) * NC + n] = v1;
            }
        }
    }
}

// ---------------------------------------------------------------------------
// fp32 -> bf16 hi/lo split (x input)
// ---------------------------------------------------------------------------
__global__ void conv_split_kernel(const float* __restrict__ in,
                                  __nv_bfloat16* __restrict__ hi,
                                  __nv_bfloat16* __restrict__ lo, int n4)
{
    int i = blockIdx.x * blockDim.x + threadIdx.x;
    if (i >= n4) return;
    float4 v = ((const float4*)in)[i];
    float a[4] = {v.x, v.y, v.z, v.w};
    __nv_bfloat16 h[4], l[4];
    #pragma unroll
    for (int j = 0; j < 4; ++j) {
        h[j] = __float2bfloat16(a[j]);
        l[j] = __float2bfloat16(a[j] - __bfloat162float(h[j]));
    }
    __nv_bfloat162* hp = (__nv_bfloat162*)hi;
    __nv_bfloat162* lp = (__nv_bfloat162*)lo;
    hp[2 * i]     = __halves2bfloat162(h[0], h[1]);
    hp[2 * i + 1] = __halves2bfloat162(h[2], h[3]);
    lp[2 * i]     = __halves2bfloat162(l[0], l[1]);
    lp[2 * i + 1] = __halves2bfloat162(l[2], l[3]);
}

// ---------------------------------------------------------------------------
// fp32 [K][N] -> transposed bf16 hi/lo [N][K]  (weights)
// ---------------------------------------------------------------------------
__global__ void transpose_split_kernel(const float* __restrict__ in,
                                       __nv_bfloat16* __restrict__ hi,
                                       __nv_bfloat16* __restrict__ lo,
                                       int K, int N)
{
    __shared__ float tile[32][33];
    const int n0 = blockIdx.x * 32, k0 = blockIdx.y * 32;
    const int tx = threadIdx.x, ty = threadIdx.y;
    #pragma unroll
    for (int i = 0; i < 32; i += 8)
        tile[ty + i][tx] = in[(size_t)(k0 + ty + i) * N + n0 + tx];
    __syncthreads();
    #pragma unroll
    for (int i = 0; i < 32; i += 8) {
        float v = tile[tx][ty + i];
        __nv_bfloat16 h = __float2bfloat16(v);
        __nv_bfloat16 l = __float2bfloat16(v - __bfloat162float(h));
        size_t o = (size_t)(n0 + ty + i) * K + k0 + tx;
        hi[o] = h;
        lo[o] = l;
    }
}

// ---------------------------------------------------------------------------
// RoPE (fp32) fused with bf16 hi/lo split: g_q/g_k -> g_qhi/qlo/khi/klo
// Thread handles f pair (2fi, 2fi+1) -> d positions {2fi,2fi+1} & {+64,+65}.
// ---------------------------------------------------------------------------
__global__ void rope_conv_kernel()
{
    const int PER = NBH * NT * 32;  // 4194304
    int idx = blockIdx.x * blockDim.x + threadIdx.x;
    const bool isK = idx >= PER;
    int r = isK ? idx - PER : idx;
    const float* src = isK ? (const float*)g_k : (const float*)g_q;
    __nv_bfloat16* dh = isK ? (__nv_bfloat16*)g_khi : (__nv_bfloat16*)g_qhi;
    __nv_bfloat16* dl = isK ? (__nv_bfloat16*)g_klo : (__nv_bfloat16*)g_qlo;
    int fi   = r & 31;
    int tpos = (r >> 5) & (NT - 1);
    int bh   = r >> 16;
    size_t base = ((size_t)bh * NT + tpos) * ND;
    float2 x1 = *(const float2*)&src[base + 2 * fi];
    float2 x2 = *(const float2*)&src[base + 2 * fi + 64];
    float y1x, y1y, y2x, y2y;
    {
        float f = 2.0f * fi;
        float th = powf(10000.0f, -f * (1.0f / 64.0f));
        float s, c; sincosf((float)tpos * th, &s, &c);
        y1x = x1.x * c - x2.x * s;  y2x = x1.x * s + x2.x * c;
    }
    {
        float f = 2.0f * fi + 1.0f;
        float th = powf(10000.0f, -f * (1.0f / 64.0f));
        float s, c; sincosf((float)tpos * th, &s, &c);
        y1y = x1.y * c - x2.y * s;  y2y = x1.y * s + x2.y * c;
    }
    uint32_t h1, l1, h2, l2;
    packhl(y1x, y1y, h1, l1);
    packhl(y2x, y2y, h2, l2);
    *(uint32_t*)&dh[base + 2 * fi]      = h1;
    *(uint32_t*)&dl[base + 2 * fi]      = l1;
    *(uint32_t*)&dh[base + 2 * fi + 64] = h2;
    *(uint32_t*)&dl[base + 2 * fi + 64] = l2;
}

// ---------------------------------------------------------------------------
// v fp32 [bh][t][d] -> transposed bf16 hi/lo [bh][d][t]
// ---------------------------------------------------------------------------
__global__ void vconv_kernel()
{
    __shared__ float tile[32][33];
    const int bh = blockIdx.z;
    const int t0 = blockIdx.x * 32, d0 = blockIdx.y * 32;
    const int tx = threadIdx.x, ty = threadIdx.y;
    const float* src = (const float*)g_v + (size_t)bh * NT * ND;
    #pragma unroll
    for (int i = 0; i < 32; i += 8)
        tile[ty + i][tx] = src[(size_t)(t0 + ty + i) * ND + d0 + tx];
    __syncthreads();
    __nv_bfloat16* dh = (__nv_bfloat16*)g_vhiT + (size_t)bh * ND * NT;
    __nv_bfloat16* dl = (__nv_bfloat16*)g_vloT + (size_t)bh * ND * NT;
    #pragma unroll
    for (int i = 0; i < 32; i += 8) {
        float v = tile[tx][ty + i];
        __nv_bfloat16 h = __float2bfloat16(v);
        __nv_bfloat16 l = __float2bfloat16(v - __bfloat162float(h));
        size_t o = (size_t)(d0 + ty + i) * NT + t0 + tx;
        dh[o] = h;
        dl[o] = l;
    }
}

// ---------------------------------------------------------------------------
// Flash attention, bf16x3 mma.sync. BQ=128, BK=64, 8 warps (16 q-rows each).
// smem: Qh|Ql (64KB) + 2 stages of (Kh|Kl|VTh|VTl) (64KB each) = 192KB.
// Q/K rows 256B (16 chunks), VT rows 128B (8 chunks); chunk^(<row&7>) swizzle.
// Output written directly as bf16 hi/lo into g_atthi/g_attlo [b*t][h*128+d].
// ---------------------------------------------------------------------------
#define ATTN_SMEM 196608

__device__ __forceinline__ void attn_load_kv(uint32_t sb, int t, int bh, int kb, int buf)
{
    uint32_t stg = sb + 65536 + buf * 65536;
    const size_t koff = ((size_t)bh * NT + kb * 64) * ND;
    #pragma unroll
    for (int i = 0; i < 4; ++i) {
        int idx = t + i * 256;
        int r = idx >> 4, c = idx & 15;
        uint32_t dst = stg + r * 256 + ((c ^ (r & 7)) << 4);
        size_t src = koff + (size_t)r * ND + c * 8;
        cp16(dst,          (const __nv_bfloat16*)g_khi + src);
        cp16(dst + 16384,  (const __nv_bfloat16*)g_klo + src);
    }
    const size_t voff = (size_t)bh * ND * NT + kb * 64;
    #pragma unroll
    for (int i = 0; i < 4; ++i) {
        int idx = t + i * 256;
        int r = idx >> 3, c = idx & 7;
        uint32_t dst = stg + 32768 + r * 128 + ((c ^ (r & 7)) << 4);
        size_t src = voff + (size_t)r * NT + c * 8;
        cp16(dst,          (const __nv_bfloat16*)g_vhiT + src);
        cp16(dst + 16384,  (const __nv_bfloat16*)g_vloT + src);
    }
    asm volatile("cp.async.commit_group;" ::: "memory");
}

__global__ __launch_bounds__(256, 1)
void attn_mma_kernel()
{
    extern __shared__ __align__(1024) char abuf[];
    uint32_t sb = smem_u32(abuf);
    const int t = threadIdx.x, lane = t & 31, w = t >> 5;
    const int lam = lane & 3, ldiv = lane >> 2;
    const int g = lane >> 3, r8 = lane & 7;
    const int qb = 15 - (int)blockIdx.x;   // heavy q-blocks first
    const int bh = blockIdx.y;
    const float C1 = 0.08838834764831845f * 1.4426950408889634f; // scale*log2e

    // Q tile (128 x 128) hi/lo
    const size_t qoff = ((size_t)bh * NT + qb * 128) * ND;
    #pragma unroll
    for (int i = 0; i < 8; ++i) {
        int idx = t + i * 256;
        int r = idx >> 4, c = idx & 15;
        uint32_t dst = sb + r * 256 + ((c ^ (r & 7)) << 4);
        size_t src = qoff + (size_t)r * ND + c * 8;
        cp16(dst,          (const __nv_bfloat16*)g_qhi + src);
        cp16(dst + 32768,  (const __nv_bfloat16*)g_qlo + src);
    }
    const int nkt = 2 * qb + 2;
    attn_load_kv(sb, t, bh, 0, 0);   // commit includes Q
    attn_load_kv(sb, t, bh, 1, 1);

    float oacc[16][4];
    #pragma unroll
    for (int i = 0; i < 16; ++i)
        #pragma unroll
        for (int j = 0; j < 4; ++j) oacc[i][j] = 0.f;
    float m0 = -INFINITY, m1 = -INFINITY, l0 = 0.f, l1 = 0.f;

    const int rowbase = qb * 128 + w * 16;
    const uint32_t aQ = sb + (uint32_t)(w * 16 + (g & 1) * 8 + r8) * 256;

    #pragma unroll 1
    for (int kb = 0; kb < nkt; ++kb) {
        if (kb == nkt - 1) asm volatile("cp.async.wait_group 0;" ::: "memory");
        else               asm volatile("cp.async.wait_group 1;" ::: "memory");
        __syncthreads();
        uint32_t stg = sb + 65536 + (kb & 1) * 65536;

        if (kb * 64 <= rowbase + 15) {  // warp has unmasked work
            // ---- S = Q K^T (bf16x3) ----
            float sacc[8][4];
            #pragma unroll
            for (int i = 0; i < 8; ++i)
                #pragma unroll
                for (int j = 0; j < 4; ++j) sacc[i][j] = 0.f;

            const uint32_t aK = stg + (uint32_t)((g >> 1) * 8 + r8) * 256;
            #pragma unroll
            for (int s = 0; s < 8; ++s) {
                uint32_t ah[4], al[4];
                uint32_t cA = ((uint32_t)(2 * s + (g >> 1)) ^ (uint32_t)r8) << 4;
                ldm4(ah, aQ + cA);
                ldm4(al, aQ + 32768 + cA);
                uint32_t cB = ((uint32_t)(2 * s + (g & 1)) ^ (uint32_t)r8) << 4;
                #pragma unroll
                for (int ng = 0; ng < 4; ++ng) {
                    uint32_t bh4[4], bl4[4];
                    uint32_t aB = aK + (uint32_t)ng * (16 * 256) + cB;
                    ldm4(bh4, aB);
                    ldm4(bl4, aB + 16384);
                    mma_bf16(sacc[ng*2],   ah, &bh4[0]);
                    mma_bf16(sacc[ng*2],   ah, &bl4[0]);
                    mma_bf16(sacc[ng*2],   al, &bh4[0]);
                    mma_bf16(sacc[ng*2+1], ah, &bh4[2]);
                    mma_bf16(sacc[ng*2+1], ah, &bl4[2]);
                    mma_bf16(sacc[ng*2+1], al, &bh4[2]);
                }
            }

            // ---- scale (+ causal mask on diagonal tiles), in log2 domain ----
            if (kb >= 2 * qb) {
                #pragma unroll
                for (int nt = 0; nt < 8; ++nt)
                    #pragma unroll
                    for (int j = 0; j < 4; ++j) {
                        int col = kb * 64 + nt * 8 + lam * 2 + (j & 1);
                        int row = rowbase + ldiv + ((j >> 1) << 3);
                        sacc[nt][j] = (col <= row) ? sacc[nt][j] * C1 : -1e30f;
                    }
            } else {
                #pragma unroll
                for (int nt = 0; nt < 8; ++nt)
                    #pragma unroll
                    for (int j = 0; j < 4; ++j) sacc[nt][j] *= C1;
            }

            // ---- online softmax (rows r and r+8) ----
            float mr0 = -1e30f, mr1 = -1e30f;
            #pragma unroll
            for (int nt = 0; nt < 8; ++nt) {
                mr0 = fmaxf(mr0, fmaxf(sacc[nt][0], sacc[nt][1]));
                mr1 = fmaxf(mr1, fmaxf(sacc[nt][2], sacc[nt][3]));
            }
            mr0 = fmaxf(mr0, __shfl_xor_sync(0xffffffffu, mr0, 1));
            mr0 = fmaxf(mr0, __shfl_xor_sync(0xffffffffu, mr0, 2));
            mr1 = fmaxf(mr1, __shfl_xor_sync(0xffffffffu, mr1, 1));
            mr1 = fmaxf(mr1, __shfl_xor_sync(0xffffffffu, mr1, 2));
            float mn0 = fmaxf(m0, mr0), mn1 = fmaxf(m1, mr1);
            float al0 = ex2(m0 - mn0), al1 = ex2(m1 - mn1);
            m0 = mn0; m1 = mn1;
            float ls0 = 0.f, ls1 = 0.f;
            #pragma unroll
            for (int nt = 0; nt < 8; ++nt) {
                float p0 = ex2(sacc[nt][0] - mn0);
                float p1 = ex2(sacc[nt][1] - mn0);
                float p2 = ex2(sacc[nt][2] - mn1);
                float p3 = ex2(sacc[nt][3] - mn1);
                sacc[nt][0] = p0; sacc[nt][1] = p1;
                sacc[nt][2] = p2; sacc[nt][3] = p3;
                ls0 += p0 + p1;  ls1 += p2 + p3;
            }
            ls0 += __shfl_xor_sync(0xffffffffu, ls0, 1);
            ls0 += __shfl_xor_sync(0xffffffffu, ls0, 2);
            ls1 += __shfl_xor_sync(0xffffffffu, ls1, 1);
            ls1 += __shfl_xor_sync(0xffffffffu, ls1, 2);
            l0 = l0 * al0 + ls0;  l1 = l1 * al1 + ls1;
            #pragma unroll
            for (int i = 0; i < 16; ++i) {
                oacc[i][0] *= al0;  oacc[i][1] *= al0;
                oacc[i][2] *= al1;  oacc[i][3] *= al1;
            }

            // ---- O += P V (bf16x3, P split in registers) ----
            const uint32_t aV = stg + 32768 + (uint32_t)((g >> 1) * 8 + r8) * 128;
            #pragma unroll
            for (int s2 = 0; s2 < 4; ++s2) {
                uint32_t aph[4], apl[4];
                packhl(sacc[2*s2][0],   sacc[2*s2][1],   aph[0], apl[0]);
                packhl(sacc[2*s2][2],   sacc[2*s2][3],   aph[1], apl[1]);
                packhl(sacc[2*s2+1][0], sacc[2*s2+1][1], aph[2], apl[2]);
                packhl(sacc[2*s2+1][2], sacc[2*s2+1][3], aph[3], apl[3]);
                uint32_t cV = ((uint32_t)(2 * s2 + (g & 1)) ^ (uint32_t)r8) << 4;
                #pragma unroll
                for (int ng = 0; ng < 8; ++ng) {
                    uint32_t vh4[4], vl4[4];
                    uint32_t aVb = aV + (uint32_t)ng * (16 * 128) + cV;
                    ldm4(vh4, aVb);
                    ldm4(vl4, aVb + 16384);
                    mma_bf16(oacc[ng*2],   aph, &vh4[0]);
                    mma_bf16(oacc[ng*2],   aph, &vl4[0]);
                    mma_bf16(oacc[ng*2],   apl, &vh4[0]);
                    mma_bf16(oacc[ng*2+1], aph, &vh4[2]);
                    mma_bf16(oacc[ng*2+1], aph, &vl4[2]);
                    mma_bf16(oacc[ng*2+1], apl, &vh4[2]);
                }
            }
        }
        __syncthreads();
        if (kb + 2 < nkt) attn_load_kv(sb, t, bh, kb + 2, kb & 1);
    }

    // ---- finalize: /l, split hi/lo, write to g_atthi/g_attlo ----
    float inv0 = 1.f / l0, inv1 = 1.f / l1;
    const int b = bh >> 4, h = bh & 15;
    const int row0 = qb * 128 + w * 16 + ldiv;
    const size_t obase = ((size_t)b * NT + row0) * NC + h * ND;
    #pragma unroll
    for (int nt = 0; nt < 16; ++nt) {
        const int d = nt * 8 + lam * 2;
        uint32_t h0, lo0, h1, lo1;
        packhl(oacc[nt][0] * inv0, oacc[nt][1] * inv0, h0, lo0);
        packhl(oacc[nt][2] * inv1, oacc[nt][3] * inv1, h1, lo1);
        *(uint32_t*)&g_atthi[obase + d]            = h0;
        *(uint32_t*)&g_attlo[obase + d]            = lo0;
        *(uint32_t*)&g_atthi[obase + 8 * NC + d]   = h1;
        *(uint32_t*)&g_attlo[obase + 8 * NC + d]   = lo1;
    }
}

// ---------------------------------------------------------------------------
// Launch
// ---------------------------------------------------------------------------
extern "C" void kernel_launch(void* const* d_in, const int* in_sizes, int n_in,
                              void* d_out, int out_size)
{
    const float* x    = (const float*)d_in[0];
    const float* Wqkv = (const float*)d_in[1];
    const float* bqkv = (const float*)d_in[2];
    const float* Wo   = (const float*)d_in[3];
    const float* bo   = (const float*)d_in[4];
    float* out = (float*)d_out;

    cudaFuncSetAttribute(gemm_bf16x3<0>,
                         cudaFuncAttributeMaxDynamicSharedMemorySize, GEMM_SMEM);
    cudaFuncSetAttribute(gemm_bf16x3<1>,
                         cudaFuncAttributeMaxDynamicSharedMemorySize, GEMM_SMEM);
    cudaFuncSetAttribute(attn_mma_kernel,
                         cudaFuncAttributeMaxDynamicSharedMemorySize, ATTN_SMEM);

    __nv_bfloat16 *Ahi, *Alo, *Whi, *Wlo, *Wohi, *Wolo, *atthi, *attlo;
    cudaGetSymbolAddress((void**)&Ahi,   g_Ahi);
    cudaGetSymbolAddress((void**)&Alo,   g_Alo);
    cudaGetSymbolAddress((void**)&Whi,   g_Whi);
    cudaGetSymbolAddress((void**)&Wlo,   g_Wlo);
    cudaGetSymbolAddress((void**)&Wohi,  g_Wohi);
    cudaGetSymbolAddress((void**)&Wolo,  g_Wolo);
    cudaGetSymbolAddress((void**)&atthi, g_atthi);
    cudaGetSymbolAddress((void**)&attlo, g_attlo);

    // 1) splits: x -> Ahi/Alo ; Wqkv^T -> Whi/Wlo ; Wo^T -> Wohi/Wolo
    conv_split_kernel<<<16384, 256>>>(x, Ahi, Alo, 4194304);
    transpose_split_kernel<<<dim3(192, 64), dim3(32, 8)>>>(Wqkv, Whi, Wlo, 2048, 6144);
    transpose_split_kernel<<<dim3(64, 64),  dim3(32, 8)>>>(Wo, Wohi, Wolo, 2048, 2048);

    // 2) QKV = x @ Wqkv + bqkv (mma.sync bf16x3) -> g_q/g_k/g_v fp32 head-major
    gemm_bf16x3<0><<<dim3(48, 64), 256, GEMM_SMEM>>>(Ahi, Alo, Whi, Wlo, bqkv, nullptr);

    // 3) RoPE fused with hi/lo split -> g_qhi/qlo/khi/klo
    rope_conv_kernel<<<32768, 256>>>();

    // 4) v transpose + split -> g_vhiT/vloT
    vconv_kernel<<<dim3(64, 4, 64), dim3(32, 8)>>>();

    // 5) flash attention (bf16x3 mma.sync) -> g_atthi/g_attlo
    attn_mma_kernel<<<dim3(16, 64), 256, ATTN_SMEM>>>();

    // 6) out = att @ Wo + bo (mma.sync bf16x3)
    gemm_bf16x3<1><<<dim3(16, 64), 256, GEMM_SMEM>>>(atthi, attlo, Wohi, Wolo, bo, out);
}

// round 6
// speedup vs baseline: 3.0925x; 1.0200x over previous
#include <cuda_runtime.h>
#include <cuda_bf16.h>
#include <math.h>
#include <stdint.h>

// Problem dims (fixed by reference)
#define NB 4
#define NT 2048
#define NC 2048
#define NH 16
#define ND 128
#define NBH (NB*NH)          // 64
#define M1 (NB*NT)           // 8192
#define KDIM 2048

// ---------------------------------------------------------------------------
// Device scratch (allocation-free rule: __device__ globals)
// ---------------------------------------------------------------------------
__device__ __align__(256) float g_q[16777216];   // [B*H][T][D] fp32 (pre-rope)
__device__ __align__(256) float g_k[16777216];
__device__ __align__(256) float g_v[16777216];

__device__ __align__(256) __nv_bfloat16 g_Ahi[16777216];   // x split   [8192][2048]
__device__ __align__(256) __nv_bfloat16 g_Alo[16777216];
__device__ __align__(256) __nv_bfloat16 g_Whi[12582912];   // Wqkv^T    [6144][2048]
__device__ __align__(256) __nv_bfloat16 g_Wlo[12582912];
__device__ __align__(256) __nv_bfloat16 g_Wohi[4194304];   // Wo^T      [2048][2048]
__device__ __align__(256) __nv_bfloat16 g_Wolo[4194304];
__device__ __align__(256) __nv_bfloat16 g_atthi[16777216]; // att split [8192][2048]
__device__ __align__(256) __nv_bfloat16 g_attlo[16777216];

__device__ __align__(256) __nv_bfloat16 g_qhi[16777216];   // rope'd q  [bh][t][d]
__device__ __align__(256) __nv_bfloat16 g_qlo[16777216];
__device__ __align__(256) __nv_bfloat16 g_khi[16777216];   // rope'd k  [bh][t][d]
__device__ __align__(256) __nv_bfloat16 g_klo[16777216];
__device__ __align__(256) __nv_bfloat16 g_vhiT[16777216];  // v^T       [bh][d][t]
__device__ __align__(256) __nv_bfloat16 g_vloT[16777216];

// ---------------------------------------------------------------------------
// PTX helpers (Ampere-class, valid under compute_103)
// ---------------------------------------------------------------------------
__device__ __forceinline__ uint32_t smem_u32(const void* p) {
    uint32_t a;
    asm("{ .reg .u64 t; cvta.to.shared.u64 t, %1; cvt.u32.u64 %0, t; }"
        : "=r"(a) : "l"(p));
    return a;
}
__device__ __forceinline__ void cp16(uint32_t s, const void* g) {
    asm volatile("cp.async.cg.shared.global [%0], [%1], 16;" :: "r"(s), "l"(g));
}
__device__ __forceinline__ void ldm4(uint32_t* r, uint32_t addr) {
    asm volatile("ldmatrix.sync.aligned.m8n8.x4.shared.b16 {%0,%1,%2,%3}, [%4];"
                 : "=r"(r[0]), "=r"(r[1]), "=r"(r[2]), "=r"(r[3]) : "r"(addr));
}
__device__ __forceinline__ void mma_bf16(float* c, const uint32_t* a, const uint32_t* b) {
    asm volatile(
        "mma.sync.aligned.m16n8k16.row.col.f32.bf16.bf16.f32 "
        "{%0,%1,%2,%3}, {%4,%5,%6,%7}, {%8,%9}, {%0,%1,%2,%3};"
        : "+f"(c[0]), "+f"(c[1]), "+f"(c[2]), "+f"(c[3])
        : "r"(a[0]), "r"(a[1]), "r"(a[2]), "r"(a[3]), "r"(b[0]), "r"(b[1]));
}
__device__ __forceinline__ float ex2(float x) {
    float y; asm("ex2.approx.f32 %0, %1;" : "=f"(y) : "f"(x)); return y;
}
__device__ __forceinline__ void packhl(float x, float y, uint32_t& hi, uint32_t& lo) {
    __nv_bfloat16 hx = __float2bfloat16(x), hy = __float2bfloat16(y);
    __nv_bfloat162 hp = __halves2bfloat162(hx, hy);
    hi = *(uint32_t*)&hp;
    __nv_bfloat16 lx = __float2bfloat16(x - __bfloat162float(hx));
    __nv_bfloat16 ly = __float2bfloat16(y - __bfloat162float(hy));
    __nv_bfloat162 lp = __halves2bfloat162(lx, ly);
    lo = *(uint32_t*)&lp;
}

// ---------------------------------------------------------------------------
// bf16x3 mma.sync GEMM: C[M,N] = A[M,K] @ B^T   (3-stage, 1 sync/stage)
// ---------------------------------------------------------------------------
#define BK 64
#define NKCH (KDIM/BK)       // 32
#define STG_SZ 65536
#define GEMM_SMEM (3*STG_SZ) // 196608

__device__ __forceinline__ void load_stage64(
    uint32_t stg, int t, int koff,
    const __nv_bfloat16* pAh, const __nv_bfloat16* pAl,
    const __nv_bfloat16* pBh, const __nv_bfloat16* pBl)
{
    #pragma unroll
    for (int i = 0; i < 4; ++i) {
        int idx = t + i * 256;
        int r = idx >> 3, ci = idx & 7;
        uint32_t so = stg + r * 128 + ((ci ^ (r & 7)) << 4);
        size_t go = (size_t)r * KDIM + koff + ci * 8;
        cp16(so,          pAh + go);
        cp16(so + 16384,  pAl + go);
        cp16(so + 32768,  pBh + go);
        cp16(so + 49152,  pBl + go);
    }
    asm volatile("cp.async.commit_group;" ::: "memory");
}

__device__ __forceinline__ void compute_stage(
    uint32_t stg, int wm, int wn, int lane, float acc[4][4][4])
{
    const int r = lane & 7, g = lane >> 3;
    const uint32_t rx = (uint32_t)r << 4;
    const uint32_t baseA = stg + (uint32_t)(wm * 64 + (g & 1) * 8 + r) * 128;
    const uint32_t hA4   = (uint32_t)(g >> 1) << 4;
    const uint32_t baseB = stg + 32768 + (uint32_t)(wn * 32 + (g >> 1) * 8 + r) * 128;
    const uint32_t hB4   = (uint32_t)(g & 1) << 4;

    #pragma unroll
    for (int s = 0; s < 4; ++s) {
        const uint32_t offA = (((uint32_t)s << 5) | hA4) ^ rx;
        const uint32_t offB = (((uint32_t)s << 5) | hB4) ^ rx;
        uint32_t ah[4][4], al[4][4], bh[2][4], bl[2][4];
        #pragma unroll
        for (int i = 0; i < 4; ++i) {
            ldm4(ah[i], baseA + i * 2048 + offA);
            ldm4(al[i], baseA + 16384 + i * 2048 + offA);
        }
        #pragma unroll
        for (int j = 0; j < 2; ++j) {
            ldm4(bh[j], baseB + j * 2048 + offB);
            ldm4(bl[j], baseB + 16384 + j * 2048 + offB);
        }
        #pragma unroll
        for (int i = 0; i < 4; ++i)
            #pragma unroll
            for (int q = 0; q < 4; ++q) {
                const int jj = q >> 1, qq = (q & 1) * 2;
                mma_bf16(acc[i][q], ah[i], &bh[jj][qq]);
                mma_bf16(acc[i][q], ah[i], &bl[jj][qq]);
                mma_bf16(acc[i][q], al[i], &bh[jj][qq]);
            }
    }
}

template<int EPI>
__global__ __launch_bounds__(256)
void gemm_bf16x3(const __nv_bfloat16* __restrict__ Ah, const __nv_bfloat16* __restrict__ Al,
                 const __nv_bfloat16* __restrict__ Bh, const __nv_bfloat16* __restrict__ Bl,
                 const float* __restrict__ bias, float* __restrict__ C)
{
    extern __shared__ __align__(1024) char smbuf[];
    uint32_t sb = smem_u32(smbuf);
    const int t    = threadIdx.x;
    const int lane = t & 31, wid = t >> 5;
    const int wm   = wid >> 2, wn = wid & 3;
    const int m0   = blockIdx.y * 128;
    const int n0   = blockIdx.x * 128;

    float acc[4][4][4];
    #pragma unroll
    for (int i = 0; i < 4; ++i)
        #pragma unroll
        for (int q = 0; q < 4; ++q)
            #pragma unroll
            for (int k = 0; k < 4; ++k) acc[i][q][k] = 0.f;

    const __nv_bfloat16* pAh = Ah + (size_t)m0 * KDIM;
    const __nv_bfloat16* pAl = Al + (size_t)m0 * KDIM;
    const __nv_bfloat16* pBh = Bh + (size_t)n0 * KDIM;
    const __nv_bfloat16* pBl = Bl + (size_t)n0 * KDIM;

    load_stage64(sb,          t, 0,  pAh, pAl, pBh, pBl);
    load_stage64(sb + STG_SZ, t, BK, pAh, pAl, pBh, pBl);

    int bc = 0, bl2 = 2;   // rotating buffer indices: kt%3, (kt+2)%3
    #pragma unroll 1
    for (int kt = 0; kt < NKCH; ++kt) {
        if (kt == NKCH - 1) asm volatile("cp.async.wait_group 0;" ::: "memory");
        else                asm volatile("cp.async.wait_group 1;" ::: "memory");
        __syncthreads();
        // load into buffer computed at stage kt-1 (safe: covered by the sync above)
        if (kt + 2 < NKCH)
            load_stage64(sb + bl2 * STG_SZ, t, (kt + 2) * BK, pAh, pAl, pBh, pBl);
        compute_stage(sb + bc * STG_SZ, wm, wn, lane, acc);
        bc  = (bc  == 2) ? 0 : bc  + 1;
        bl2 = (bl2 == 2) ? 0 : bl2 + 1;
    }

    const int mr  = (lane >> 2);
    const int nc0 = (lane & 3) * 2;
    if (EPI == 0) {
        const int which = n0 >> 11;
        const int h     = (n0 >> 7) & 15;
        float* dst = (which == 0) ? (float*)g_q
                   : (which == 1) ? (float*)g_k : (float*)g_v;
        const int b = m0 >> 11;
        #pragma unroll
        for (int i = 0; i < 4; ++i) {
            const int m  = m0 + wm * 64 + i * 16 + mr;
            const int tq = m & 2047;
            #pragma unroll
            for (int q = 0; q < 4; ++q) {
                const int dl = wn * 32 + q * 8 + nc0;
                float2 bs = *(const float2*)&bias[n0 + dl];
                size_t off = ((size_t)(b * 16 + h) * NT + tq) * ND + dl;
                float2 v0, v1;
                v0.x = acc[i][q][0] + bs.x;  v0.y = acc[i][q][1] + bs.y;
                v1.x = acc[i][q][2] + bs.x;  v1.y = acc[i][q][3] + bs.y;
                *(float2*)&dst[off]            = v0;
                *(float2*)&dst[off + 8 * ND]   = v1;
            }
        }
    } else {
        #pragma unroll
        for (int i = 0; i < 4; ++i) {
            const int m = m0 + wm * 64 + i * 16 + mr;
            #pragma unroll
            for (int q = 0; q < 4; ++q) {
                const int n = n0 + wn * 32 + q * 8 + nc0;
                float2 bs = *(const float2*)&bias[n];
                float2 v0, v1;
                v0.x = acc[i][q][0] + bs.x;  v0.y = acc[i][q][1] + bs.y;
                v1.x = acc[i][q][2] + bs.x;  v1.y = acc[i][q][3] + bs.y;
                *(float2*)&C[(size_t)m * NC + n]       = v0;
                *(float2*)&C[(size_t)(m + 8) * NC + n] = v1;
            }
        }
    }
}

// ---------------------------------------------------------------------------
// fp32 -> bf16 hi/lo split (x input)
// ---------------------------------------------------------------------------
__global__ void conv_split_kernel(const float* __restrict__ in,
                                  __nv_bfloat16* __restrict__ hi,
                                  __nv_bfloat16* __restrict__ lo, int n4)
{
    int i = blockIdx.x * blockDim.x + threadIdx.x;
    if (i >= n4) return;
    float4 v = ((const float4*)in)[i];
    float a[4] = {v.x, v.y, v.z, v.w};
    __nv_bfloat16 h[4], l[4];
    #pragma unroll
    for (int j = 0; j < 4; ++j) {
        h[j] = __float2bfloat16(a[j]);
        l[j] = __float2bfloat16(a[j] - __bfloat162float(h[j]));
    }
    __nv_bfloat162* hp = (__nv_bfloat162*)hi;
    __nv_bfloat162* lp = (__nv_bfloat162*)lo;
    hp[2 * i]     = __halves2bfloat162(h[0], h[1]);
    hp[2 * i + 1] = __halves2bfloat162(h[2], h[3]);
    lp[2 * i]     = __halves2bfloat162(l[0], l[1]);
    lp[2 * i + 1] = __halves2bfloat162(l[2], l[3]);
}

// ---------------------------------------------------------------------------
// fp32 [K][N] -> transposed bf16 hi/lo [N][K]  (weights)
// ---------------------------------------------------------------------------
__global__ void transpose_split_kernel(const float* __restrict__ in,
                                       __nv_bfloat16* __restrict__ hi,
                                       __nv_bfloat16* __restrict__ lo,
                                       int K, int N)
{
    __shared__ float tile[32][33];
    const int n0 = blockIdx.x * 32, k0 = blockIdx.y * 32;
    const int tx = threadIdx.x, ty = threadIdx.y;
    #pragma unroll
    for (int i = 0; i < 32; i += 8)
        tile[ty + i][tx] = in[(size_t)(k0 + ty + i) * N + n0 + tx];
    __syncthreads();
    #pragma unroll
    for (int i = 0; i < 32; i += 8) {
        float v = tile[tx][ty + i];
        __nv_bfloat16 h = __float2bfloat16(v);
        __nv_bfloat16 l = __float2bfloat16(v - __bfloat162float(h));
        size_t o = (size_t)(n0 + ty + i) * K + k0 + tx;
        hi[o] = h;
        lo[o] = l;
    }
}

// ---------------------------------------------------------------------------
// RoPE (fp32) fused with bf16 hi/lo split: g_q/g_k -> g_qhi/qlo/khi/klo
// ---------------------------------------------------------------------------
__global__ void rope_conv_kernel()
{
    const int PER = NBH * NT * 32;  // 4194304
    int idx = blockIdx.x * blockDim.x + threadIdx.x;
    const bool isK = idx >= PER;
    int r = isK ? idx - PER : idx;
    const float* src = isK ? (const float*)g_k : (const float*)g_q;
    __nv_bfloat16* dh = isK ? (__nv_bfloat16*)g_khi : (__nv_bfloat16*)g_qhi;
    __nv_bfloat16* dl = isK ? (__nv_bfloat16*)g_klo : (__nv_bfloat16*)g_qlo;
    int fi   = r & 31;
    int tpos = (r >> 5) & (NT - 1);
    int bh   = r >> 16;
    size_t base = ((size_t)bh * NT + tpos) * ND;
    float2 x1 = *(const float2*)&src[base + 2 * fi];
    float2 x2 = *(const float2*)&src[base + 2 * fi + 64];
    float y1x, y1y, y2x, y2y;
    {
        float f = 2.0f * fi;
        float th = powf(10000.0f, -f * (1.0f / 64.0f));
        float s, c; sincosf((float)tpos * th, &s, &c);
        y1x = x1.x * c - x2.x * s;  y2x = x1.x * s + x2.x * c;
    }
    {
        float f = 2.0f * fi + 1.0f;
        float th = powf(10000.0f, -f * (1.0f / 64.0f));
        float s, c; sincosf((float)tpos * th, &s, &c);
        y1y = x1.y * c - x2.y * s;  y2y = x1.y * s + x2.y * c;
    }
    uint32_t h1, l1, h2, l2;
    packhl(y1x, y1y, h1, l1);
    packhl(y2x, y2y, h2, l2);
    *(uint32_t*)&dh[base + 2 * fi]      = h1;
    *(uint32_t*)&dl[base + 2 * fi]      = l1;
    *(uint32_t*)&dh[base + 2 * fi + 64] = h2;
    *(uint32_t*)&dl[base + 2 * fi + 64] = l2;
}

// ---------------------------------------------------------------------------
// v fp32 [bh][t][d] -> transposed bf16 hi/lo [bh][d][t]
// ---------------------------------------------------------------------------
__global__ void vconv_kernel()
{
    __shared__ float tile[32][33];
    const int bh = blockIdx.z;
    const int t0 = blockIdx.x * 32, d0 = blockIdx.y * 32;
    const int tx = threadIdx.x, ty = threadIdx.y;
    const float* src = (const float*)g_v + (size_t)bh * NT * ND;
    #pragma unroll
    for (int i = 0; i < 32; i += 8)
        tile[ty + i][tx] = src[(size_t)(t0 + ty + i) * ND + d0 + tx];
    __syncthreads();
    __nv_bfloat16* dh = (__nv_bfloat16*)g_vhiT + (size_t)bh * ND * NT;
    __nv_bfloat16* dl = (__nv_bfloat16*)g_vloT + (size_t)bh * ND * NT;
    #pragma unroll
    for (int i = 0; i < 32; i += 8) {
        float v = tile[tx][ty + i];
        __nv_bfloat16 h = __float2bfloat16(v);
        __nv_bfloat16 l = __float2bfloat16(v - __bfloat162float(h));
        size_t o = (size_t)(d0 + ty + i) * NT + t0 + tx;
        dh[o] = h;
        dl[o] = l;
    }
}

// ---------------------------------------------------------------------------
// Flash attention, bf16x3 mma.sync. BQ=128, BK=64, 8 warps (16 q-rows each).
// 3-stage K/V pipeline (1 sync/stage); Q fragments hoisted into registers and
// Q's smem region recycled as stage buffer 2.
// smem: 3 x 64KB stages. Stage: Khi 16K | Klo 16K | VThi 16K | VTlo 16K.
// ---------------------------------------------------------------------------
#define ATTN_SMEM 196608

__device__ __forceinline__ void attn_load_kv(uint32_t stg, int t, int bh, int kb)
{
    const size_t koff = ((size_t)bh * NT + kb * 64) * ND;
    #pragma unroll
    for (int i = 0; i < 4; ++i) {
        int idx = t + i * 256;
        int r = idx >> 4, c = idx & 15;
        uint32_t dst = stg + r * 256 + ((c ^ (r & 7)) << 4);
        size_t src = koff + (size_t)r * ND + c * 8;
        cp16(dst,          (const __nv_bfloat16*)g_khi + src);
        cp16(dst + 16384,  (const __nv_bfloat16*)g_klo + src);
    }
    const size_t voff = (size_t)bh * ND * NT + kb * 64;
    #pragma unroll
    for (int i = 0; i < 4; ++i) {
        int idx = t + i * 256;
        int r = idx >> 3, c = idx & 7;
        uint32_t dst = stg + 32768 + r * 128 + ((c ^ (r & 7)) << 4);
        size_t src = voff + (size_t)r * NT + c * 8;
        cp16(dst,          (const __nv_bfloat16*)g_vhiT + src);
        cp16(dst + 16384,  (const __nv_bfloat16*)g_vloT + src);
    }
    asm volatile("cp.async.commit_group;" ::: "memory");
}

__global__ __launch_bounds__(256, 1)
void attn_mma_kernel()
{
    extern __shared__ __align__(1024) char abuf[];
    uint32_t sb = smem_u32(abuf);
    const int t = threadIdx.x, lane = t & 31, w = t >> 5;
    const int lam = lane & 3, ldiv = lane >> 2;
    const int g = lane >> 3, r8 = lane & 7;
    const int qb = 15 - (int)blockIdx.x;   // heavy q-blocks first
    const int bh = blockIdx.y;
    const float C1 = 0.08838834764831845f * 1.4426950408889634f; // scale*log2e

    // Q tile (128 x 128) hi/lo into stage-2 region (recycled after hoist)
    const uint32_t qreg = sb + 2 * 65536;
    const size_t qoff = ((size_t)bh * NT + qb * 128) * ND;
    #pragma unroll
    for (int i = 0; i < 8; ++i) {
        int idx = t + i * 256;
        int r = idx >> 4, c = idx & 15;
        uint32_t dst = qreg + r * 256 + ((c ^ (r & 7)) << 4);
        size_t src = qoff + (size_t)r * ND + c * 8;
        cp16(dst,          (const __nv_bfloat16*)g_qhi + src);
        cp16(dst + 32768,  (const __nv_bfloat16*)g_qlo + src);
    }
    asm volatile("cp.async.commit_group;" ::: "memory");   // group 0 = Q
    const int nkt = 2 * qb + 2;
    attn_load_kv(sb,         t, bh, 0);                    // group 1
    attn_load_kv(sb + 65536, t, bh, 1);                    // group 2

    // Hoist Q fragments to registers (Q done after wait_group 2)
    asm volatile("cp.async.wait_group 2;" ::: "memory");
    __syncthreads();
    uint32_t qh[8][4], ql[8][4];
    {
        const uint32_t aQ = qreg + (uint32_t)(w * 16 + (g & 1) * 8 + r8) * 256;
        #pragma unroll
        for (int s = 0; s < 8; ++s) {
            uint32_t cA = ((uint32_t)(2 * s + (g >> 1)) ^ (uint32_t)r8) << 4;
            ldm4(qh[s], aQ + cA);
            ldm4(ql[s], aQ + 32768 + cA);
        }
    }

    float oacc[16][4];
    #pragma unroll
    for (int i = 0; i < 16; ++i)
        #pragma unroll
        for (int j = 0; j < 4; ++j) oacc[i][j] = 0.f;
    float m0 = -INFINITY, m1 = -INFINITY, l0 = 0.f, l1 = 0.f;

    const int rowbase = qb * 128 + w * 16;

    int bc = 0, bl2 = 2;   // kb%3, (kb+2)%3
    #pragma unroll 1
    for (int kb = 0; kb < nkt; ++kb) {
        if (kb == nkt - 1) asm volatile("cp.async.wait_group 0;" ::: "memory");
        else               asm volatile("cp.async.wait_group 1;" ::: "memory");
        __syncthreads();
        if (kb + 2 < nkt) attn_load_kv(sb + bl2 * 65536, t, bh, kb + 2);
        uint32_t stg = sb + bc * 65536;
        bc  = (bc  == 2) ? 0 : bc  + 1;
        bl2 = (bl2 == 2) ? 0 : bl2 + 1;

        if (kb * 64 <= rowbase + 15) {  // warp has unmasked work
            // ---- S = Q K^T (bf16x3) ----
            float sacc[8][4];
            #pragma unroll
            for (int i = 0; i < 8; ++i)
                #pragma unroll
                for (int j = 0; j < 4; ++j) sacc[i][j] = 0.f;

            const uint32_t aK = stg + (uint32_t)((g >> 1) * 8 + r8) * 256;
            #pragma unroll
            for (int s = 0; s < 8; ++s) {
                uint32_t cB = ((uint32_t)(2 * s + (g & 1)) ^ (uint32_t)r8) << 4;
                #pragma unroll
                for (int ng = 0; ng < 4; ++ng) {
                    uint32_t bh4[4], bl4[4];
                    uint32_t aB = aK + (uint32_t)ng * (16 * 256) + cB;
                    ldm4(bh4, aB);
                    ldm4(bl4, aB + 16384);
                    mma_bf16(sacc[ng*2],   qh[s], &bh4[0]);
                    mma_bf16(sacc[ng*2],   qh[s], &bl4[0]);
                    mma_bf16(sacc[ng*2],   ql[s], &bh4[0]);
                    mma_bf16(sacc[ng*2+1], qh[s], &bh4[2]);
                    mma_bf16(sacc[ng*2+1], qh[s], &bl4[2]);
                    mma_bf16(sacc[ng*2+1], ql[s], &bh4[2]);
                }
            }

            // ---- scale (+ causal mask on diagonal tiles), log2 domain ----
            if (kb >= 2 * qb) {
                #pragma unroll
                for (int nt = 0; nt < 8; ++nt)
                    #pragma unroll
                    for (int j = 0; j < 4; ++j) {
                        int col = kb * 64 + nt * 8 + lam * 2 + (j & 1);
                        int row = rowbase + ldiv + ((j >> 1) << 3);
                        sacc[nt][j] = (col <= row) ? sacc[nt][j] * C1 : -1e30f;
                    }
            } else {
                #pragma unroll
                for (int nt = 0; nt < 8; ++nt)
                    #pragma unroll
                    for (int j = 0; j < 4; ++j) sacc[nt][j] *= C1;
            }

            // ---- online softmax (rows r and r+8) ----
            float mr0 = -1e30f, mr1 = -1e30f;
            #pragma unroll
            for (int nt = 0; nt < 8; ++nt) {
                mr0 = fmaxf(mr0, fmaxf(sacc[nt][0], sacc[nt][1]));
                mr1 = fmaxf(mr1, fmaxf(sacc[nt][2], sacc[nt][3]));
            }
            mr0 = fmaxf(mr0, __shfl_xor_sync(0xffffffffu, mr0, 1));
            mr0 = fmaxf(mr0, __shfl_xor_sync(0xffffffffu, mr0, 2));
            mr1 = fmaxf(mr1, __shfl_xor_sync(0xffffffffu, mr1, 1));
            mr1 = fmaxf(mr1, __shfl_xor_sync(0xffffffffu, mr1, 2));
            float mn0 = fmaxf(m0, mr0), mn1 = fmaxf(m1, mr1);
            float al0 = ex2(m0 - mn0), al1 = ex2(m1 - mn1);
            m0 = mn0; m1 = mn1;
            float ls0 = 0.f, ls1 = 0.f;
            #pragma unroll
            for (int nt = 0; nt < 8; ++nt) {
                float p0 = ex2(sacc[nt][0] - mn0);
                float p1 = ex2(sacc[nt][1] - mn0);
                float p2 = ex2(sacc[nt][2] - mn1);
                float p3 = ex2(sacc[nt][3] - mn1);
                sacc[nt][0] = p0; sacc[nt][1] = p1;
                sacc[nt][2] = p2; sacc[nt][3] = p3;
                ls0 += p0 + p1;  ls1 += p2 + p3;
            }
            ls0 += __shfl_xor_sync(0xffffffffu, ls0, 1);
            ls0 += __shfl_xor_sync(0xffffffffu, ls0, 2);
            ls1 += __shfl_xor_sync(0xffffffffu, ls1, 1);
            ls1 += __shfl_xor_sync(0xffffffffu, ls1, 2);
            l0 = l0 * al0 + ls0;  l1 = l1 * al1 + ls1;
            #pragma unroll
            for (int i = 0; i < 16; ++i) {
                oacc[i][0] *= al0;  oacc[i][1] *= al0;
                oacc[i][2] *= al1;  oacc[i][3] *= al1;
            }

            // ---- O += P V (bf16x3, P split in registers) ----
            const uint32_t aV = stg + 32768 + (uint32_t)((g >> 1) * 8 + r8) * 128;
            #pragma unroll
            for (int s2 = 0; s2 < 4; ++s2) {
                uint32_t aph[4], apl[4];
                packhl(sacc[2*s2][0],   sacc[2*s2][1],   aph[0], apl[0]);
                packhl(sacc[2*s2][2],   sacc[2*s2][3],   aph[1], apl[1]);
                packhl(sacc[2*s2+1][0], sacc[2*s2+1][1], aph[2], apl[2]);
                packhl(sacc[2*s2+1][2], sacc[2*s2+1][3], aph[3], apl[3]);
                uint32_t cV = ((uint32_t)(2 * s2 + (g & 1)) ^ (uint32_t)r8) << 4;
                #pragma unroll
                for (int ng = 0; ng < 8; ++ng) {
                    uint32_t vh4[4], vl4[4];
                    uint32_t aVb = aV + (uint32_t)ng * (16 * 128) + cV;
                    ldm4(vh4, aVb);
                    ldm4(vl4, aVb + 16384);
                    mma_bf16(oacc[ng*2],   aph, &vh4[0]);
                    mma_bf16(oacc[ng*2],   aph, &vl4[0]);
                    mma_bf16(oacc[ng*2],   apl, &vh4[0]);
                    mma_bf16(oacc[ng*2+1], aph, &vh4[2]);
                    mma_bf16(oacc[ng*2+1], aph, &vl4[2]);
                    mma_bf16(oacc[ng*2+1], apl, &vh4[2]);
                }
            }
        }
    }

    // ---- finalize: /l, split hi/lo, write to g_atthi/g_attlo ----
    float inv0 = 1.f / l0, inv1 = 1.f / l1;
    const int b = bh >> 4, h = bh & 15;
    const int row0 = qb * 128 + w * 16 + ldiv;
    const size_t obase = ((size_t)b * NT + row0) * NC + h * ND;
    #pragma unroll
    for (int nt = 0; nt < 16; ++nt) {
        const int d = nt * 8 + lam * 2;
        uint32_t h0, lo0, h1, lo1;
        packhl(oacc[nt][0] * inv0, oacc[nt][1] * inv0, h0, lo0);
        packhl(oacc[nt][2] * inv1, oacc[nt][3] * inv1, h1, lo1);
        *(uint32_t*)&g_atthi[obase + d]            = h0;
        *(uint32_t*)&g_attlo[obase + d]            = lo0;
        *(uint32_t*)&g_atthi[obase + 8 * NC + d]   = h1;
        *(uint32_t*)&g_attlo[obase + 8 * NC + d]   = lo1;
    }
}

// ---------------------------------------------------------------------------
// Launch
// ---------------------------------------------------------------------------
extern "C" void kernel_launch(void* const* d_in, const int* in_sizes, int n_in,
                              void* d_out, int out_size)
{
    const float* x    = (const float*)d_in[0];
    const float* Wqkv = (const float*)d_in[1];
    const float* bqkv = (const float*)d_in[2];
    const float* Wo   = (const float*)d_in[3];
    const float* bo   = (const float*)d_in[4];
    float* out = (float*)d_out;

    cudaFuncSetAttribute(gemm_bf16x3<0>,
                         cudaFuncAttributeMaxDynamicSharedMemorySize, GEMM_SMEM);
    cudaFuncSetAttribute(gemm_bf16x3<1>,
                         cudaFuncAttributeMaxDynamicSharedMemorySize, GEMM_SMEM);
    cudaFuncSetAttribute(attn_mma_kernel,
                         cudaFuncAttributeMaxDynamicSharedMemorySize, ATTN_SMEM);

    __nv_bfloat16 *Ahi, *Alo, *Whi, *Wlo, *Wohi, *Wolo, *atthi, *attlo;
    cudaGetSymbolAddress((void**)&Ahi,   g_Ahi);
    cudaGetSymbolAddress((void**)&Alo,   g_Alo);
    cudaGetSymbolAddress((void**)&Whi,   g_Whi);
    cudaGetSymbolAddress((void**)&Wlo,   g_Wlo);
    cudaGetSymbolAddress((void**)&Wohi,  g_Wohi);
    cudaGetSymbolAddress((void**)&Wolo,  g_Wolo);
    cudaGetSymbolAddress((void**)&atthi, g_atthi);
    cudaGetSymbolAddress((void**)&attlo, g_attlo);

    // 1) splits: x -> Ahi/Alo ; Wqkv^T -> Whi/Wlo ; Wo^T -> Wohi/Wolo
    conv_split_kernel<<<16384, 256>>>(x, Ahi, Alo, 4194304);
    transpose_split_kernel<<<dim3(192, 64), dim3(32, 8)>>>(Wqkv, Whi, Wlo, 2048, 6144);
    transpose_split_kernel<<<dim3(64, 64),  dim3(32, 8)>>>(Wo, Wohi, Wolo, 2048, 2048);

    // 2) QKV = x @ Wqkv + bqkv (mma.sync bf16x3) -> g_q/g_k/g_v fp32 head-major
    gemm_bf16x3<0><<<dim3(48, 64), 256, GEMM_SMEM>>>(Ahi, Alo, Whi, Wlo, bqkv, nullptr);

    // 3) RoPE fused with hi/lo split -> g_qhi/qlo/khi/klo
    rope_conv_kernel<<<32768, 256>>>();

    // 4) v transpose + split -> g_vhiT/vloT
    vconv_kernel<<<dim3(64, 4, 64), dim3(32, 8)>>>();

    // 5) flash attention (bf16x3 mma.sync) -> g_atthi/g_attlo
    attn_mma_kernel<<<dim3(16, 64), 256, ATTN_SMEM>>>();

    // 6) out = att @ Wo + bo (mma.sync bf16x3)
    gemm_bf16x3<1><<<dim3(16, 64), 256, GEMM_SMEM>>>(atthi, attlo, Wohi, Wolo, bo, out);
}

// round 7
// speedup vs baseline: 4.3013x; 1.3909x over previous
#include <cuda_runtime.h>
#include <cuda_fp16.h>
#include <math.h>
#include <stdint.h>

// Problem dims (fixed by reference)
#define NB 4
#define NT 2048
#define NC 2048
#define NH 16
#define ND 128
#define NBH (NB*NH)          // 64
#define M1 (NB*NT)           // 8192
#define KDIM 2048

// ---------------------------------------------------------------------------
// Device scratch (allocation-free rule: __device__ globals)
// ---------------------------------------------------------------------------
__device__ __align__(256) float g_q[16777216];   // [B*H][T][D] fp32 (pre-rope)
__device__ __align__(256) float g_k[16777216];
__device__ __align__(256) float g_v[16777216];

__device__ __align__(256) __half g_xh[16777216];    // x fp16       [8192][2048]
__device__ __align__(256) __half g_Whi[12582912];   // Wqkv^T hi/lo [6144][2048]
__device__ __align__(256) __half g_Wlo[12582912];
__device__ __align__(256) __half g_Wohi[4194304];   // Wo^T hi/lo   [2048][2048]
__device__ __align__(256) __half g_Wolo[4194304];
__device__ __align__(256) __half g_attf[16777216];  // att fp16     [8192][2048]

__device__ __align__(256) __half g_qhi[16777216];   // rope'd q hi/lo [bh][t][d]
__device__ __align__(256) __half g_qlo[16777216];
__device__ __align__(256) __half g_kh[16777216];    // rope'd k fp16  [bh][t][d]
__device__ __align__(256) __half g_vT[16777216];    // v^T fp16       [bh][d][t]

// ---------------------------------------------------------------------------
// PTX helpers (Ampere-class, valid under compute_103)
// ---------------------------------------------------------------------------
__device__ __forceinline__ uint32_t smem_u32(const void* p) {
    uint32_t a;
    asm("{ .reg .u64 t; cvta.to.shared.u64 t, %1; cvt.u32.u64 %0, t; }"
        : "=r"(a) : "l"(p));
    return a;
}
__device__ __forceinline__ void cp16(uint32_t s, const void* g) {
    asm volatile("cp.async.cg.shared.global [%0], [%1], 16;" :: "r"(s), "l"(g));
}
__device__ __forceinline__ void ldm4(uint32_t* r, uint32_t addr) {
    asm volatile("ldmatrix.sync.aligned.m8n8.x4.shared.b16 {%0,%1,%2,%3}, [%4];"
                 : "=r"(r[0]), "=r"(r[1]), "=r"(r[2]), "=r"(r[3]) : "r"(addr));
}
__device__ __forceinline__ void mma_f16(float* c, const uint32_t* a, const uint32_t* b) {
    asm volatile(
        "mma.sync.aligned.m16n8k16.row.col.f32.f16.f16.f32 "
        "{%0,%1,%2,%3}, {%4,%5,%6,%7}, {%8,%9}, {%0,%1,%2,%3};"
        : "+f"(c[0]), "+f"(c[1]), "+f"(c[2]), "+f"(c[3])
        : "r"(a[0]), "r"(a[1]), "r"(a[2]), "r"(a[3]), "r"(b[0]), "r"(b[1]));
}
__device__ __forceinline__ float ex2(float x) {
    float y; asm("ex2.approx.f32 %0, %1;" : "=f"(y) : "f"(x)); return y;
}
__device__ __forceinline__ uint32_t packh(float x, float y) {
    __half2 h = __floats2half2_rn(x, y);
    return *(uint32_t*)&h;
}
__device__ __forceinline__ void packhl(float x, float y, uint32_t& hi, uint32_t& lo) {
    __half hx = __float2half_rn(x), hy = __float2half_rn(y);
    __half2 hp = __halves2half2(hx, hy);
    hi = *(uint32_t*)&hp;
    __half lx = __float2half_rn(x - __half2float(hx));
    __half ly = __float2half_rn(y - __half2float(hy));
    __half2 lp = __halves2half2(lx, ly);
    lo = *(uint32_t*)&lp;
}

// ---------------------------------------------------------------------------
// fp16x2 mma.sync GEMM: C[M,N] = A[M,K] @ B^T   (A plain, B split hi/lo)
// BM=128 BN=128 BK=64, 8 warps (2x4), 3-stage, 1 sync/stage.
// Stage (48KB): A[128][64] | Bhi[128][64] | Blo[128][64], xor swizzle.
// ---------------------------------------------------------------------------
#define BK 64
#define NKCH (KDIM/BK)       // 32
#define STG_SZ 49152
#define GEMM_SMEM (3*STG_SZ) // 147456

__device__ __forceinline__ void load_stage48(
    uint32_t stg, int t, int koff,
    const __half* pA, const __half* pBh, const __half* pBl)
{
    #pragma unroll
    for (int i = 0; i < 4; ++i) {
        int idx = t + i * 256;
        int r = idx >> 3, ci = idx & 7;
        uint32_t so = stg + r * 128 + ((ci ^ (r & 7)) << 4);
        size_t go = (size_t)r * KDIM + koff + ci * 8;
        cp16(so,          pA  + go);
        cp16(so + 16384,  pBh + go);
        cp16(so + 32768,  pBl + go);
    }
    asm volatile("cp.async.commit_group;" ::: "memory");
}

__device__ __forceinline__ void compute_stage(
    uint32_t stg, int wm, int wn, int lane, float acc[4][4][4])
{
    const int r = lane & 7, g = lane >> 3;
    const uint32_t rx = (uint32_t)r << 4;
    const uint32_t baseA = stg + (uint32_t)(wm * 64 + (g & 1) * 8 + r) * 128;
    const uint32_t hA4   = (uint32_t)(g >> 1) << 4;
    const uint32_t baseB = stg + 16384 + (uint32_t)(wn * 32 + (g >> 1) * 8 + r) * 128;
    const uint32_t hB4   = (uint32_t)(g & 1) << 4;

    #pragma unroll
    for (int s = 0; s < 4; ++s) {
        const uint32_t offA = (((uint32_t)s << 5) | hA4) ^ rx;
        const uint32_t offB = (((uint32_t)s << 5) | hB4) ^ rx;
        uint32_t ah[4][4], bh[2][4], bl[2][4];
        #pragma unroll
        for (int i = 0; i < 4; ++i)
            ldm4(ah[i], baseA + i * 2048 + offA);
        #pragma unroll
        for (int j = 0; j < 2; ++j) {
            ldm4(bh[j], baseB + j * 2048 + offB);
            ldm4(bl[j], baseB + 16384 + j * 2048 + offB);
        }
        #pragma unroll
        for (int i = 0; i < 4; ++i)
            #pragma unroll
            for (int q = 0; q < 4; ++q) {
                const int jj = q >> 1, qq = (q & 1) * 2;
                mma_f16(acc[i][q], ah[i], &bh[jj][qq]);
                mma_f16(acc[i][q], ah[i], &bl[jj][qq]);
            }
    }
}

template<int EPI>
__global__ __launch_bounds__(256)
void gemm_fp16x2(const __half* __restrict__ A,
                 const __half* __restrict__ Bh, const __half* __restrict__ Bl,
                 const float* __restrict__ bias, float* __restrict__ C)
{
    extern __shared__ __align__(1024) char smbuf[];
    uint32_t sb = smem_u32(smbuf);
    const int t    = threadIdx.x;
    const int lane = t & 31, wid = t >> 5;
    const int wm   = wid >> 2, wn = wid & 3;
    const int m0   = blockIdx.y * 128;
    const int n0   = blockIdx.x * 128;

    float acc[4][4][4];
    #pragma unroll
    for (int i = 0; i < 4; ++i)
        #pragma unroll
        for (int q = 0; q < 4; ++q)
            #pragma unroll
            for (int k = 0; k < 4; ++k) acc[i][q][k] = 0.f;

    const __half* pA  = A  + (size_t)m0 * KDIM;
    const __half* pBh = Bh + (size_t)n0 * KDIM;
    const __half* pBl = Bl + (size_t)n0 * KDIM;

    load_stage48(sb,          t, 0,  pA, pBh, pBl);
    load_stage48(sb + STG_SZ, t, BK, pA, pBh, pBl);

    int bc = 0, bl2 = 2;
    #pragma unroll 1
    for (int kt = 0; kt < NKCH; ++kt) {
        if (kt == NKCH - 1) asm volatile("cp.async.wait_group 0;" ::: "memory");
        else                asm volatile("cp.async.wait_group 1;" ::: "memory");
        __syncthreads();
        if (kt + 2 < NKCH)
            load_stage48(sb + bl2 * STG_SZ, t, (kt + 2) * BK, pA, pBh, pBl);
        compute_stage(sb + bc * STG_SZ, wm, wn, lane, acc);
        bc  = (bc  == 2) ? 0 : bc  + 1;
        bl2 = (bl2 == 2) ? 0 : bl2 + 1;
    }

    const int mr  = (lane >> 2);
    const int nc0 = (lane & 3) * 2;
    if (EPI == 0) {
        const int which = n0 >> 11;
        const int h     = (n0 >> 7) & 15;
        float* dst = (which == 0) ? (float*)g_q
                   : (which == 1) ? (float*)g_k : (float*)g_v;
        const int b = m0 >> 11;
        #pragma unroll
        for (int i = 0; i < 4; ++i) {
            const int m  = m0 + wm * 64 + i * 16 + mr;
            const int tq = m & 2047;
            #pragma unroll
            for (int q = 0; q < 4; ++q) {
                const int dl = wn * 32 + q * 8 + nc0;
                float2 bs = *(const float2*)&bias[n0 + dl];
                size_t off = ((size_t)(b * 16 + h) * NT + tq) * ND + dl;
                float2 v0, v1;
                v0.x = acc[i][q][0] + bs.x;  v0.y = acc[i][q][1] + bs.y;
                v1.x = acc[i][q][2] + bs.x;  v1.y = acc[i][q][3] + bs.y;
                *(float2*)&dst[off]            = v0;
                *(float2*)&dst[off + 8 * ND]   = v1;
            }
        }
    } else {
        #pragma unroll
        for (int i = 0; i < 4; ++i) {
            const int m = m0 + wm * 64 + i * 16 + mr;
            #pragma unroll
            for (int q = 0; q < 4; ++q) {
                const int n = n0 + wn * 32 + q * 8 + nc0;
                float2 bs = *(const float2*)&bias[n];
                float2 v0, v1;
                v0.x = acc[i][q][0] + bs.x;  v0.y = acc[i][q][1] + bs.y;
                v1.x = acc[i][q][2] + bs.x;  v1.y = acc[i][q][3] + bs.y;
                *(float2*)&C[(size_t)m * NC + n]       = v0;
                *(float2*)&C[(size_t)(m + 8) * NC + n] = v1;
            }
        }
    }
}

// ---------------------------------------------------------------------------
// fp32 -> fp16 convert (x input)
// ---------------------------------------------------------------------------
__global__ void conv_f16_kernel(const float* __restrict__ in,
                                __half* __restrict__ out, int n4)
{
    int i = blockIdx.x * blockDim.x + threadIdx.x;
    if (i >= n4) return;
    float4 v = ((const float4*)in)[i];
    uint32_t* op = (uint32_t*)out;
    op[2 * i]     = packh(v.x, v.y);
    op[2 * i + 1] = packh(v.z, v.w);
}

// ---------------------------------------------------------------------------
// fp32 [K][N] -> transposed fp16 hi/lo [N][K]  (weights)
// ---------------------------------------------------------------------------
__global__ void transpose_split_kernel(const float* __restrict__ in,
                                       __half* __restrict__ hi,
                                       __half* __restrict__ lo,
                                       int K, int N)
{
    __shared__ float tile[32][33];
    const int n0 = blockIdx.x * 32, k0 = blockIdx.y * 32;
    const int tx = threadIdx.x, ty = threadIdx.y;
    #pragma unroll
    for (int i = 0; i < 32; i += 8)
        tile[ty + i][tx] = in[(size_t)(k0 + ty + i) * N + n0 + tx];
    __syncthreads();
    #pragma unroll
    for (int i = 0; i < 32; i += 8) {
        float v = tile[tx][ty + i];
        __half h = __float2half_rn(v);
        __half l = __float2half_rn(v - __half2float(h));
        size_t o = (size_t)(n0 + ty + i) * K + k0 + tx;
        hi[o] = h;
        lo[o] = l;
    }
}

// ---------------------------------------------------------------------------
// RoPE fused with fp16 conversion: q -> hi/lo split, k -> plain fp16
// ---------------------------------------------------------------------------
__global__ void rope_conv_kernel()
{
    const int PER = NBH * NT * 32;  // 4194304
    int idx = blockIdx.x * blockDim.x + threadIdx.x;
    const bool isK = idx >= PER;
    int r = isK ? idx - PER : idx;
    const float* src = isK ? (const float*)g_k : (const float*)g_q;
    int fi   = r & 31;
    int tpos = (r >> 5) & (NT - 1);
    int bh   = r >> 16;
    size_t base = ((size_t)bh * NT + tpos) * ND;
    float2 x1 = *(const float2*)&src[base + 2 * fi];
    float2 x2 = *(const float2*)&src[base + 2 * fi + 64];
    float y1x, y1y, y2x, y2y;
    {
        float f = 2.0f * fi;
        float th = powf(10000.0f, -f * (1.0f / 64.0f));
        float s, c; sincosf((float)tpos * th, &s, &c);
        y1x = x1.x * c - x2.x * s;  y2x = x1.x * s + x2.x * c;
    }
    {
        float f = 2.0f * fi + 1.0f;
        float th = powf(10000.0f, -f * (1.0f / 64.0f));
        float s, c; sincosf((float)tpos * th, &s, &c);
        y1y = x1.y * c - x2.y * s;  y2y = x1.y * s + x2.y * c;
    }
    if (isK) {
        uint32_t* kh = (uint32_t*)g_kh;
        kh[(base + 2 * fi) >> 1]      = packh(y1x, y1y);
        kh[(base + 2 * fi + 64) >> 1] = packh(y2x, y2y);
    } else {
        uint32_t h1, l1, h2, l2;
        packhl(y1x, y1y, h1, l1);
        packhl(y2x, y2y, h2, l2);
        *(uint32_t*)&g_qhi[base + 2 * fi]      = h1;
        *(uint32_t*)&g_qlo[base + 2 * fi]      = l1;
        *(uint32_t*)&g_qhi[base + 2 * fi + 64] = h2;
        *(uint32_t*)&g_qlo[base + 2 * fi + 64] = l2;
    }
}

// ---------------------------------------------------------------------------
// v fp32 [bh][t][d] -> transposed fp16 [bh][d][t]
// ---------------------------------------------------------------------------
__global__ void vconv_kernel()
{
    __shared__ float tile[32][33];
    const int bh = blockIdx.z;
    const int t0 = blockIdx.x * 32, d0 = blockIdx.y * 32;
    const int tx = threadIdx.x, ty = threadIdx.y;
    const float* src = (const float*)g_v + (size_t)bh * NT * ND;
    #pragma unroll
    for (int i = 0; i < 32; i += 8)
        tile[ty + i][tx] = src[(size_t)(t0 + ty + i) * ND + d0 + tx];
    __syncthreads();
    __half* dh = (__half*)g_vT + (size_t)bh * ND * NT;
    #pragma unroll
    for (int i = 0; i < 32; i += 8) {
        size_t o = (size_t)(d0 + ty + i) * NT + t0 + tx;
        dh[o] = __float2half_rn(tile[tx][ty + i]);
    }
}

// ---------------------------------------------------------------------------
// Flash attention, fp16x2 mma.sync. BQ=128, BK=64, 8 warps (16 q-rows each).
// Q split hi/lo (register-hoisted); K, V plain fp16. 3-stage pipeline.
// smem: 3 x 32KB stages (K 16K | VT 16K) + Q 64KB (hi 32K | lo 32K) = 160KB.
// ---------------------------------------------------------------------------
#define ASTG 32768
#define ATTN_SMEM (3*ASTG + 65536)   // 163840

__device__ __forceinline__ void attn_load_kv(uint32_t stg, int t, int bh, int kb)
{
    const size_t koff = ((size_t)bh * NT + kb * 64) * ND;
    #pragma unroll
    for (int i = 0; i < 4; ++i) {
        int idx = t + i * 256;
        int r = idx >> 4, c = idx & 15;
        uint32_t dst = stg + r * 256 + ((c ^ (r & 7)) << 4);
        cp16(dst, (const __half*)g_kh + koff + (size_t)r * ND + c * 8);
    }
    const size_t voff = (size_t)bh * ND * NT + kb * 64;
    #pragma unroll
    for (int i = 0; i < 4; ++i) {
        int idx = t + i * 256;
        int r = idx >> 3, c = idx & 7;
        uint32_t dst = stg + 16384 + r * 128 + ((c ^ (r & 7)) << 4);
        cp16(dst, (const __half*)g_vT + voff + (size_t)r * NT + c * 8);
    }
    asm volatile("cp.async.commit_group;" ::: "memory");
}

__global__ __launch_bounds__(256, 1)
void attn_mma_kernel()
{
    extern __shared__ __align__(1024) char abuf[];
    uint32_t sb = smem_u32(abuf);
    const int t = threadIdx.x, lane = t & 31, w = t >> 5;
    const int lam = lane & 3, ldiv = lane >> 2;
    const int g = lane >> 3, r8 = lane & 7;
    const int qb = 15 - (int)blockIdx.x;   // heavy q-blocks first
    const int bh = blockIdx.y;
    const float C1 = 0.08838834764831845f * 1.4426950408889634f; // scale*log2e

    // Q tile (128 x 128) hi/lo
    const uint32_t qreg = sb + 3 * ASTG;
    const size_t qoff = ((size_t)bh * NT + qb * 128) * ND;
    #pragma unroll
    for (int i = 0; i < 8; ++i) {
        int idx = t + i * 256;
        int r = idx >> 4, c = idx & 15;
        uint32_t dst = qreg + r * 256 + ((c ^ (r & 7)) << 4);
        size_t src = qoff + (size_t)r * ND + c * 8;
        cp16(dst,          (const __half*)g_qhi + src);
        cp16(dst + 32768,  (const __half*)g_qlo + src);
    }
    asm volatile("cp.async.commit_group;" ::: "memory");   // group: Q
    const int nkt = 2 * qb + 2;
    attn_load_kv(sb,        t, bh, 0);
    attn_load_kv(sb + ASTG, t, bh, 1);

    // Hoist Q fragments to registers
    asm volatile("cp.async.wait_group 2;" ::: "memory");
    __syncthreads();
    uint32_t qh[8][4], ql[8][4];
    {
        const uint32_t aQ = qreg + (uint32_t)(w * 16 + (g & 1) * 8 + r8) * 256;
        #pragma unroll
        for (int s = 0; s < 8; ++s) {
            uint32_t cA = ((uint32_t)(2 * s + (g >> 1)) ^ (uint32_t)r8) << 4;
            ldm4(qh[s], aQ + cA);
            ldm4(ql[s], aQ + 32768 + cA);
        }
    }

    float oacc[16][4];
    #pragma unroll
    for (int i = 0; i < 16; ++i)
        #pragma unroll
        for (int j = 0; j < 4; ++j) oacc[i][j] = 0.f;
    float m0 = -INFINITY, m1 = -INFINITY, l0 = 0.f, l1 = 0.f;

    const int rowbase = qb * 128 + w * 16;

    int bc = 0, bl2 = 2;
    #pragma unroll 1
    for (int kb = 0; kb < nkt; ++kb) {
        if (kb == nkt - 1) asm volatile("cp.async.wait_group 0;" ::: "memory");
        else               asm volatile("cp.async.wait_group 1;" ::: "memory");
        __syncthreads();
        if (kb + 2 < nkt) attn_load_kv(sb + bl2 * ASTG, t, bh, kb + 2);
        uint32_t stg = sb + bc * ASTG;
        bc  = (bc  == 2) ? 0 : bc  + 1;
        bl2 = (bl2 == 2) ? 0 : bl2 + 1;

        if (kb * 64 <= rowbase + 15) {
            // ---- S = Q K^T (fp16x2: Qhi*K + Qlo*K) ----
            float sacc[8][4];
            #pragma unroll
            for (int i = 0; i < 8; ++i)
                #pragma unroll
                for (int j = 0; j < 4; ++j) sacc[i][j] = 0.f;

            const uint32_t aK = stg + (uint32_t)((g >> 1) * 8 + r8) * 256;
            #pragma unroll
            for (int s = 0; s < 8; ++s) {
                uint32_t cB = ((uint32_t)(2 * s + (g & 1)) ^ (uint32_t)r8) << 4;
                #pragma unroll
                for (int ng = 0; ng < 4; ++ng) {
                    uint32_t k4[4];
                    ldm4(k4, aK + (uint32_t)ng * (16 * 256) + cB);
                    mma_f16(sacc[ng*2],   qh[s], &k4[0]);
                    mma_f16(sacc[ng*2],   ql[s], &k4[0]);
                    mma_f16(sacc[ng*2+1], qh[s], &k4[2]);
                    mma_f16(sacc[ng*2+1], ql[s], &k4[2]);
                }
            }

            // ---- scale (+ causal mask on diagonal tiles), log2 domain ----
            if (kb >= 2 * qb) {
                #pragma unroll
                for (int nt = 0; nt < 8; ++nt)
                    #pragma unroll
                    for (int j = 0; j < 4; ++j) {
                        int col = kb * 64 + nt * 8 + lam * 2 + (j & 1);
                        int row = rowbase + ldiv + ((j >> 1) << 3);
                        sacc[nt][j] = (col <= row) ? sacc[nt][j] * C1 : -1e30f;
                    }
            } else {
                #pragma unroll
                for (int nt = 0; nt < 8; ++nt)
                    #pragma unroll
                    for (int j = 0; j < 4; ++j) sacc[nt][j] *= C1;
            }

            // ---- online softmax (rows r and r+8) ----
            float mr0 = -1e30f, mr1 = -1e30f;
            #pragma unroll
            for (int nt = 0; nt < 8; ++nt) {
                mr0 = fmaxf(mr0, fmaxf(sacc[nt][0], sacc[nt][1]));
                mr1 = fmaxf(mr1, fmaxf(sacc[nt][2], sacc[nt][3]));
            }
            mr0 = fmaxf(mr0, __shfl_xor_sync(0xffffffffu, mr0, 1));
            mr0 = fmaxf(mr0, __shfl_xor_sync(0xffffffffu, mr0, 2));
            mr1 = fmaxf(mr1, __shfl_xor_sync(0xffffffffu, mr1, 1));
            mr1 = fmaxf(mr1, __shfl_xor_sync(0xffffffffu, mr1, 2));
            float mn0 = fmaxf(m0, mr0), mn1 = fmaxf(m1, mr1);
            float al0 = ex2(m0 - mn0), al1 = ex2(m1 - mn1);
            m0 = mn0; m1 = mn1;
            float ls0 = 0.f, ls1 = 0.f;
            #pragma unroll
            for (int nt = 0; nt < 8; ++nt) {
                float p0 = ex2(sacc[nt][0] - mn0);
                float p1 = ex2(sacc[nt][1] - mn0);
                float p2 = ex2(sacc[nt][2] - mn1);
                float p3 = ex2(sacc[nt][3] - mn1);
                sacc[nt][0] = p0; sacc[nt][1] = p1;
                sacc[nt][2] = p2; sacc[nt][3] = p3;
                ls0 += p0 + p1;  ls1 += p2 + p3;
            }
            ls0 += __shfl_xor_sync(0xffffffffu, ls0, 1);
            ls0 += __shfl_xor_sync(0xffffffffu, ls0, 2);
            ls1 += __shfl_xor_sync(0xffffffffu, ls1, 1);
            ls1 += __shfl_xor_sync(0xffffffffu, ls1, 2);
            l0 = l0 * al0 + ls0;  l1 = l1 * al1 + ls1;
            #pragma unroll
            for (int i = 0; i < 16; ++i) {
                oacc[i][0] *= al0;  oacc[i][1] *= al0;
                oacc[i][2] *= al1;  oacc[i][3] *= al1;
            }

            // ---- O += P V (fp16x2: Phi*V + Plo*V) ----
            const uint32_t aV = stg + 16384 + (uint32_t)((g >> 1) * 8 + r8) * 128;
            #pragma unroll
            for (int s2 = 0; s2 < 4; ++s2) {
                uint32_t ph[4], pl[4];
                packhl(sacc[2*s2][0],   sacc[2*s2][1],   ph[0], pl[0]);
                packhl(sacc[2*s2][2],   sacc[2*s2][3],   ph[1], pl[1]);
                packhl(sacc[2*s2+1][0], sacc[2*s2+1][1], ph[2], pl[2]);
                packhl(sacc[2*s2+1][2], sacc[2*s2+1][3], ph[3], pl[3]);
                uint32_t cV = ((uint32_t)(2 * s2 + (g & 1)) ^ (uint32_t)r8) << 4;
                #pragma unroll
                for (int ng = 0; ng < 8; ++ng) {
                    uint32_t v4[4];
                    ldm4(v4, aV + (uint32_t)ng * (16 * 128) + cV);
                    mma_f16(oacc[ng*2],   ph, &v4[0]);
                    mma_f16(oacc[ng*2],   pl, &v4[0]);
                    mma_f16(oacc[ng*2+1], ph, &v4[2]);
                    mma_f16(oacc[ng*2+1], pl, &v4[2]);
                }
            }
        }
    }

    // ---- finalize: /l, write fp16 att [b,t,h*128+d] ----
    float inv0 = 1.f / l0, inv1 = 1.f / l1;
    const int b = bh >> 4, h = bh & 15;
    const int row0 = qb * 128 + w * 16 + ldiv;
    const size_t obase = ((size_t)b * NT + row0) * NC + h * ND;
    #pragma unroll
    for (int nt = 0; nt < 16; ++nt) {
        const int d = nt * 8 + lam * 2;
        *(uint32_t*)&g_attf[obase + d]          = packh(oacc[nt][0] * inv0, oacc[nt][1] * inv0);
        *(uint32_t*)&g_attf[obase + 8 * NC + d] = packh(oacc[nt][2] * inv1, oacc[nt][3] * inv1);
    }
}

// ---------------------------------------------------------------------------
// Launch
// ---------------------------------------------------------------------------
extern "C" void kernel_launch(void* const* d_in, const int* in_sizes, int n_in,
                              void* d_out, int out_size)
{
    const float* x    = (const float*)d_in[0];
    const float* Wqkv = (const float*)d_in[1];
    const float* bqkv = (const float*)d_in[2];
    const float* Wo   = (const float*)d_in[3];
    const float* bo   = (const float*)d_in[4];
    float* out = (float*)d_out;

    cudaFuncSetAttribute(gemm_fp16x2<0>,
                         cudaFuncAttributeMaxDynamicSharedMemorySize, GEMM_SMEM);
    cudaFuncSetAttribute(gemm_fp16x2<1>,
                         cudaFuncAttributeMaxDynamicSharedMemorySize, GEMM_SMEM);
    cudaFuncSetAttribute(attn_mma_kernel,
                         cudaFuncAttributeMaxDynamicSharedMemorySize, ATTN_SMEM);

    __half *xh, *Whi, *Wlo, *Wohi, *Wolo, *attf;
    cudaGetSymbolAddress((void**)&xh,   g_xh);
    cudaGetSymbolAddress((void**)&Whi,  g_Whi);
    cudaGetSymbolAddress((void**)&Wlo,  g_Wlo);
    cudaGetSymbolAddress((void**)&Wohi, g_Wohi);
    cudaGetSymbolAddress((void**)&Wolo, g_Wolo);
    cudaGetSymbolAddress((void**)&attf, g_attf);

    // 1) conversions: x -> fp16 ; Wqkv^T, Wo^T -> fp16 hi/lo
    conv_f16_kernel<<<16384, 256>>>(x, xh, 4194304);
    transpose_split_kernel<<<dim3(192, 64), dim3(32, 8)>>>(Wqkv, Whi, Wlo, 2048, 6144);
    transpose_split_kernel<<<dim3(64, 64),  dim3(32, 8)>>>(Wo, Wohi, Wolo, 2048, 2048);

    // 2) QKV = x @ Wqkv + bqkv (fp16x2) -> g_q/g_k/g_v fp32 head-major
    gemm_fp16x2<0><<<dim3(48, 64), 256, GEMM_SMEM>>>(xh, Whi, Wlo, bqkv, nullptr);

    // 3) RoPE + fp16 conversion: q -> hi/lo, k -> plain
    rope_conv_kernel<<<32768, 256>>>();

    // 4) v transpose -> fp16 [bh][d][t]
    vconv_kernel<<<dim3(64, 4, 64), dim3(32, 8)>>>();

    // 5) flash attention (fp16x2 mma.sync) -> g_attf
    attn_mma_kernel<<<dim3(16, 64), 256, ATTN_SMEM>>>();

    // 6) out = att @ Wo + bo (fp16x2)
    gemm_fp16x2<1><<<dim3(16, 64), 256, GEMM_SMEM>>>(attf, Wohi, Wolo, bo, out);
}

// round 8
// speedup vs baseline: 4.5573x; 1.0595x over previous
#include <cuda_runtime.h>
#include <cuda_fp16.h>
#include <math.h>
#include <stdint.h>

// Problem dims (fixed by reference)
#define NB 4
#define NT 2048
#define NC 2048
#define NH 16
#define ND 128
#define NBH (NB*NH)          // 64
#define M1 (NB*NT)           // 8192
#define KDIM 2048

// ---------------------------------------------------------------------------
// Device scratch (allocation-free rule: __device__ globals)
// ---------------------------------------------------------------------------
__device__ __align__(256) float g_q[16777216];   // [B*H][T][D] fp32 (pre-rope)
__device__ __align__(256) float g_k[16777216];
__device__ __align__(256) float g_v[16777216];

__device__ __align__(256) __half g_xh[16777216];    // x fp16       [8192][2048]
__device__ __align__(256) __half g_Whi[12582912];   // Wqkv^T hi/lo [6144][2048]
__device__ __align__(256) __half g_Wlo[12582912];
__device__ __align__(256) __half g_Wohi[4194304];   // Wo^T hi/lo   [2048][2048]
__device__ __align__(256) __half g_Wolo[4194304];
__device__ __align__(256) __half g_attf[16777216];  // att fp16     [8192][2048]

__device__ __align__(256) __half g_qhi[16777216];   // rope'd q hi/lo [bh][t][d]
__device__ __align__(256) __half g_qlo[16777216];
__device__ __align__(256) __half g_kh[16777216];    // rope'd k fp16  [bh][t][d]
__device__ __align__(256) __half g_vT[16777216];    // v^T fp16       [bh][d][t]

// ---------------------------------------------------------------------------
// PTX helpers (Ampere-class, valid under compute_103)
// ---------------------------------------------------------------------------
__device__ __forceinline__ uint32_t smem_u32(const void* p) {
    uint32_t a;
    asm("{ .reg .u64 t; cvta.to.shared.u64 t, %1; cvt.u32.u64 %0, t; }"
        : "=r"(a) : "l"(p));
    return a;
}
__device__ __forceinline__ void cp16(uint32_t s, const void* g) {
    asm volatile("cp.async.cg.shared.global [%0], [%1], 16;" :: "r"(s), "l"(g));
}
__device__ __forceinline__ void ldm4(uint32_t* r, uint32_t addr) {
    asm volatile("ldmatrix.sync.aligned.m8n8.x4.shared.b16 {%0,%1,%2,%3}, [%4];"
                 : "=r"(r[0]), "=r"(r[1]), "=r"(r[2]), "=r"(r[3]) : "r"(addr));
}
__device__ __forceinline__ void mma_f16(float* c, const uint32_t* a, const uint32_t* b) {
    asm volatile(
        "mma.sync.aligned.m16n8k16.row.col.f32.f16.f16.f32 "
        "{%0,%1,%2,%3}, {%4,%5,%6,%7}, {%8,%9}, {%0,%1,%2,%3};"
        : "+f"(c[0]), "+f"(c[1]), "+f"(c[2]), "+f"(c[3])
        : "r"(a[0]), "r"(a[1]), "r"(a[2]), "r"(a[3]), "r"(b[0]), "r"(b[1]));
}
__device__ __forceinline__ float ex2(float x) {
    float y; asm("ex2.approx.f32 %0, %1;" : "=f"(y) : "f"(x)); return y;
}
__device__ __forceinline__ uint32_t packh(float x, float y) {
    __half2 h = __floats2half2_rn(x, y);
    return *(uint32_t*)&h;
}
__device__ __forceinline__ void packhl(float x, float y, uint32_t& hi, uint32_t& lo) {
    __half hx = __float2half_rn(x), hy = __float2half_rn(y);
    __half2 hp = __halves2half2(hx, hy);
    hi = *(uint32_t*)&hp;
    __half lx = __float2half_rn(x - __half2float(hx));
    __half ly = __float2half_rn(y - __half2float(hy));
    __half2 lp = __halves2half2(lx, ly);
    lo = *(uint32_t*)&lp;
}

// ---------------------------------------------------------------------------
// fp16x2 mma.sync GEMM: C[M,N] = A[M,K] @ B^T   (A plain, B split hi/lo)
// BM=128 BN=128 BK=64, 8 warps (2x4). 2-stage pipeline, 96KB smem total
// -> 2 CTAs per SM (cross-CTA latency hiding).
// ---------------------------------------------------------------------------
#define BK 64
#define NKCH (KDIM/BK)       // 32
#define STG_SZ 49152
#define GEMM_SMEM (2*STG_SZ) // 98304

__device__ __forceinline__ void load_stage48(
    uint32_t stg, int t, int koff,
    const __half* pA, const __half* pBh, const __half* pBl)
{
    #pragma unroll
    for (int i = 0; i < 4; ++i) {
        int idx = t + i * 256;
        int r = idx >> 3, ci = idx & 7;
        uint32_t so = stg + r * 128 + ((ci ^ (r & 7)) << 4);
        size_t go = (size_t)r * KDIM + koff + ci * 8;
        cp16(so,          pA  + go);
        cp16(so + 16384,  pBh + go);
        cp16(so + 32768,  pBl + go);
    }
    asm volatile("cp.async.commit_group;" ::: "memory");
}

__device__ __forceinline__ void compute_stage(
    uint32_t stg, int wm, int wn, int lane, float acc[4][4][4])
{
    const int r = lane & 7, g = lane >> 3;
    const uint32_t rx = (uint32_t)r << 4;
    const uint32_t baseA = stg + (uint32_t)(wm * 64 + (g & 1) * 8 + r) * 128;
    const uint32_t hA4   = (uint32_t)(g >> 1) << 4;
    const uint32_t baseB = stg + 16384 + (uint32_t)(wn * 32 + (g >> 1) * 8 + r) * 128;
    const uint32_t hB4   = (uint32_t)(g & 1) << 4;

    #pragma unroll
    for (int s = 0; s < 4; ++s) {
        const uint32_t offA = (((uint32_t)s << 5) | hA4) ^ rx;
        const uint32_t offB = (((uint32_t)s << 5) | hB4) ^ rx;
        uint32_t ah[4][4], bh[2][4], bl[2][4];
        #pragma unroll
        for (int i = 0; i < 4; ++i)
            ldm4(ah[i], baseA + i * 2048 + offA);
        #pragma unroll
        for (int j = 0; j < 2; ++j) {
            ldm4(bh[j], baseB + j * 2048 + offB);
            ldm4(bl[j], baseB + 16384 + j * 2048 + offB);
        }
        #pragma unroll
        for (int i = 0; i < 4; ++i)
            #pragma unroll
            for (int q = 0; q < 4; ++q) {
                const int jj = q >> 1, qq = (q & 1) * 2;
                mma_f16(acc[i][q], ah[i], &bh[jj][qq]);
                mma_f16(acc[i][q], ah[i], &bl[jj][qq]);
            }
    }
}

template<int EPI>
__global__ __launch_bounds__(256, 2)
void gemm_fp16x2(const __half* __restrict__ A,
                 const __half* __restrict__ Bh, const __half* __restrict__ Bl,
                 const float* __restrict__ bias, float* __restrict__ C)
{
    extern __shared__ __align__(1024) char smbuf[];
    uint32_t sb = smem_u32(smbuf);
    const int t    = threadIdx.x;
    const int lane = t & 31, wid = t >> 5;
    const int wm   = wid >> 2, wn = wid & 3;
    const int m0   = blockIdx.y * 128;
    const int n0   = blockIdx.x * 128;

    float acc[4][4][4];
    #pragma unroll
    for (int i = 0; i < 4; ++i)
        #pragma unroll
        for (int q = 0; q < 4; ++q)
            #pragma unroll
            for (int k = 0; k < 4; ++k) acc[i][q][k] = 0.f;

    const __half* pA  = A  + (size_t)m0 * KDIM;
    const __half* pBh = Bh + (size_t)n0 * KDIM;
    const __half* pBl = Bl + (size_t)n0 * KDIM;

    load_stage48(sb,          t, 0,  pA, pBh, pBl);
    load_stage48(sb + STG_SZ, t, BK, pA, pBh, pBl);

    #pragma unroll 1
    for (int kt = 0; kt < NKCH; ++kt) {
        if (kt == NKCH - 1) asm volatile("cp.async.wait_group 0;" ::: "memory");
        else                asm volatile("cp.async.wait_group 1;" ::: "memory");
        __syncthreads();
        compute_stage(sb + (kt & 1) * STG_SZ, wm, wn, lane, acc);
        __syncthreads();
        if (kt + 2 < NKCH)
            load_stage48(sb + (kt & 1) * STG_SZ, t, (kt + 2) * BK, pA, pBh, pBl);
    }

    const int mr  = (lane >> 2);
    const int nc0 = (lane & 3) * 2;
    if (EPI == 0) {
        const int which = n0 >> 11;
        const int h     = (n0 >> 7) & 15;
        float* dst = (which == 0) ? (float*)g_q
                   : (which == 1) ? (float*)g_k : (float*)g_v;
        const int b = m0 >> 11;
        #pragma unroll
        for (int i = 0; i < 4; ++i) {
            const int m  = m0 + wm * 64 + i * 16 + mr;
            const int tq = m & 2047;
            #pragma unroll
            for (int q = 0; q < 4; ++q) {
                const int dl = wn * 32 + q * 8 + nc0;
                float2 bs = *(const float2*)&bias[n0 + dl];
                size_t off = ((size_t)(b * 16 + h) * NT + tq) * ND + dl;
                float2 v0, v1;
                v0.x = acc[i][q][0] + bs.x;  v0.y = acc[i][q][1] + bs.y;
                v1.x = acc[i][q][2] + bs.x;  v1.y = acc[i][q][3] + bs.y;
                *(float2*)&dst[off]            = v0;
                *(float2*)&dst[off + 8 * ND]   = v1;
            }
        }
    } else {
        #pragma unroll
        for (int i = 0; i < 4; ++i) {
            const int m = m0 + wm * 64 + i * 16 + mr;
            #pragma unroll
            for (int q = 0; q < 4; ++q) {
                const int n = n0 + wn * 32 + q * 8 + nc0;
                float2 bs = *(const float2*)&bias[n];
                float2 v0, v1;
                v0.x = acc[i][q][0] + bs.x;  v0.y = acc[i][q][1] + bs.y;
                v1.x = acc[i][q][2] + bs.x;  v1.y = acc[i][q][3] + bs.y;
                *(float2*)&C[(size_t)m * NC + n]       = v0;
                *(float2*)&C[(size_t)(m + 8) * NC + n] = v1;
            }
        }
    }
}

// ---------------------------------------------------------------------------
// fp32 -> fp16 convert (x input)
// ---------------------------------------------------------------------------
__global__ void conv_f16_kernel(const float* __restrict__ in,
                                __half* __restrict__ out, int n4)
{
    int i = blockIdx.x * blockDim.x + threadIdx.x;
    if (i >= n4) return;
    float4 v = ((const float4*)in)[i];
    uint32_t* op = (uint32_t*)out;
    op[2 * i]     = packh(v.x, v.y);
    op[2 * i + 1] = packh(v.z, v.w);
}

// ---------------------------------------------------------------------------
// fp32 [K][N] -> transposed fp16 hi/lo [N][K]  (weights)
// ---------------------------------------------------------------------------
__global__ void transpose_split_kernel(const float* __restrict__ in,
                                       __half* __restrict__ hi,
                                       __half* __restrict__ lo,
                                       int K, int N)
{
    __shared__ float tile[32][33];
    const int n0 = blockIdx.x * 32, k0 = blockIdx.y * 32;
    const int tx = threadIdx.x, ty = threadIdx.y;
    #pragma unroll
    for (int i = 0; i < 32; i += 8)
        tile[ty + i][tx] = in[(size_t)(k0 + ty + i) * N + n0 + tx];
    __syncthreads();
    #pragma unroll
    for (int i = 0; i < 32; i += 8) {
        float v = tile[tx][ty + i];
        __half h = __float2half_rn(v);
        __half l = __float2half_rn(v - __half2float(h));
        size_t o = (size_t)(n0 + ty + i) * K + k0 + tx;
        hi[o] = h;
        lo[o] = l;
    }
}

// ---------------------------------------------------------------------------
// RoPE fused with fp16 conversion: q -> hi/lo split, k -> plain fp16
// ---------------------------------------------------------------------------
__global__ void rope_conv_kernel()
{
    const int PER = NBH * NT * 32;  // 4194304
    int idx = blockIdx.x * blockDim.x + threadIdx.x;
    const bool isK = idx >= PER;
    int r = isK ? idx - PER : idx;
    const float* src = isK ? (const float*)g_k : (const float*)g_q;
    int fi   = r & 31;
    int tpos = (r >> 5) & (NT - 1);
    int bh   = r >> 16;
    size_t base = ((size_t)bh * NT + tpos) * ND;
    float2 x1 = *(const float2*)&src[base + 2 * fi];
    float2 x2 = *(const float2*)&src[base + 2 * fi + 64];
    float y1x, y1y, y2x, y2y;
    {
        float f = 2.0f * fi;
        float th = powf(10000.0f, -f * (1.0f / 64.0f));
        float s, c; sincosf((float)tpos * th, &s, &c);
        y1x = x1.x * c - x2.x * s;  y2x = x1.x * s + x2.x * c;
    }
    {
        float f = 2.0f * fi + 1.0f;
        float th = powf(10000.0f, -f * (1.0f / 64.0f));
        float s, c; sincosf((float)tpos * th, &s, &c);
        y1y = x1.y * c - x2.y * s;  y2y = x1.y * s + x2.y * c;
    }
    if (isK) {
        uint32_t* kh = (uint32_t*)g_kh;
        kh[(base + 2 * fi) >> 1]      = packh(y1x, y1y);
        kh[(base + 2 * fi + 64) >> 1] = packh(y2x, y2y);
    } else {
        uint32_t h1, l1, h2, l2;
        packhl(y1x, y1y, h1, l1);
        packhl(y2x, y2y, h2, l2);
        *(uint32_t*)&g_qhi[base + 2 * fi]      = h1;
        *(uint32_t*)&g_qlo[base + 2 * fi]      = l1;
        *(uint32_t*)&g_qhi[base + 2 * fi + 64] = h2;
        *(uint32_t*)&g_qlo[base + 2 * fi + 64] = l2;
    }
}

// ---------------------------------------------------------------------------
// v fp32 [bh][t][d] -> transposed fp16 [bh][d][t]
// ---------------------------------------------------------------------------
__global__ void vconv_kernel()
{
    __shared__ float tile[32][33];
    const int bh = blockIdx.z;
    const int t0 = blockIdx.x * 32, d0 = blockIdx.y * 32;
    const int tx = threadIdx.x, ty = threadIdx.y;
    const float* src = (const float*)g_v + (size_t)bh * NT * ND;
    #pragma unroll
    for (int i = 0; i < 32; i += 8)
        tile[ty + i][tx] = src[(size_t)(t0 + ty + i) * ND + d0 + tx];
    __syncthreads();
    __half* dh = (__half*)g_vT + (size_t)bh * ND * NT;
    #pragma unroll
    for (int i = 0; i < 32; i += 8) {
        size_t o = (size_t)(d0 + ty + i) * NT + t0 + tx;
        dh[o] = __float2half_rn(tile[tx][ty + i]);
    }
}

// ---------------------------------------------------------------------------
// Flash attention, fp16x2 mma.sync (unchanged from R7).
// ---------------------------------------------------------------------------
#define ASTG 32768
#define ATTN_SMEM (3*ASTG + 65536)   // 163840

__device__ __forceinline__ void attn_load_kv(uint32_t stg, int t, int bh, int kb)
{
    const size_t koff = ((size_t)bh * NT + kb * 64) * ND;
    #pragma unroll
    for (int i = 0; i < 4; ++i) {
        int idx = t + i * 256;
        int r = idx >> 4, c = idx & 15;
        uint32_t dst = stg + r * 256 + ((c ^ (r & 7)) << 4);
        cp16(dst, (const __half*)g_kh + koff + (size_t)r * ND + c * 8);
    }
    const size_t voff = (size_t)bh * ND * NT + kb * 64;
    #pragma unroll
    for (int i = 0; i < 4; ++i) {
        int idx = t + i * 256;
        int r = idx >> 3, c = idx & 7;
        uint32_t dst = stg + 16384 + r * 128 + ((c ^ (r & 7)) << 4);
        cp16(dst, (const __half*)g_vT + voff + (size_t)r * NT + c * 8);
    }
    asm volatile("cp.async.commit_group;" ::: "memory");
}

__global__ __launch_bounds__(256, 1)
void attn_mma_kernel()
{
    extern __shared__ __align__(1024) char abuf[];
    uint32_t sb = smem_u32(abuf);
    const int t = threadIdx.x, lane = t & 31, w = t >> 5;
    const int lam = lane & 3, ldiv = lane >> 2;
    const int g = lane >> 3, r8 = lane & 7;
    const int qb = 15 - (int)blockIdx.x;   // heavy q-blocks first
    const int bh = blockIdx.y;
    const float C1 = 0.08838834764831845f * 1.4426950408889634f; // scale*log2e

    // Q tile (128 x 128) hi/lo
    const uint32_t qreg = sb + 3 * ASTG;
    const size_t qoff = ((size_t)bh * NT + qb * 128) * ND;
    #pragma unroll
    for (int i = 0; i < 8; ++i) {
        int idx = t + i * 256;
        int r = idx >> 4, c = idx & 15;
        uint32_t dst = qreg + r * 256 + ((c ^ (r & 7)) << 4);
        size_t src = qoff + (size_t)r * ND + c * 8;
        cp16(dst,          (const __half*)g_qhi + src);
        cp16(dst + 32768,  (const __half*)g_qlo + src);
    }
    asm volatile("cp.async.commit_group;" ::: "memory");   // group: Q
    const int nkt = 2 * qb + 2;
    attn_load_kv(sb,        t, bh, 0);
    attn_load_kv(sb + ASTG, t, bh, 1);

    // Hoist Q fragments to registers
    asm volatile("cp.async.wait_group 2;" ::: "memory");
    __syncthreads();
    uint32_t qh[8][4], ql[8][4];
    {
        const uint32_t aQ = qreg + (uint32_t)(w * 16 + (g & 1) * 8 + r8) * 256;
        #pragma unroll
        for (int s = 0; s < 8; ++s) {
            uint32_t cA = ((uint32_t)(2 * s + (g >> 1)) ^ (uint32_t)r8) << 4;
            ldm4(qh[s], aQ + cA);
            ldm4(ql[s], aQ + 32768 + cA);
        }
    }

    float oacc[16][4];
    #pragma unroll
    for (int i = 0; i < 16; ++i)
        #pragma unroll
        for (int j = 0; j < 4; ++j) oacc[i][j] = 0.f;
    float m0 = -INFINITY, m1 = -INFINITY, l0 = 0.f, l1 = 0.f;

    const int rowbase = qb * 128 + w * 16;

    int bc = 0, bl2 = 2;
    #pragma unroll 1
    for (int kb = 0; kb < nkt; ++kb) {
        if (kb == nkt - 1) asm volatile("cp.async.wait_group 0;" ::: "memory");
        else               asm volatile("cp.async.wait_group 1;" ::: "memory");
        __syncthreads();
        if (kb + 2 < nkt) attn_load_kv(sb + bl2 * ASTG, t, bh, kb + 2);
        uint32_t stg = sb + bc * ASTG;
        bc  = (bc  == 2) ? 0 : bc  + 1;
        bl2 = (bl2 == 2) ? 0 : bl2 + 1;

        if (kb * 64 <= rowbase + 15) {
            // ---- S = Q K^T (fp16x2: Qhi*K + Qlo*K) ----
            float sacc[8][4];
            #pragma unroll
            for (int i = 0; i < 8; ++i)
                #pragma unroll
                for (int j = 0; j < 4; ++j) sacc[i][j] = 0.f;

            const uint32_t aK = stg + (uint32_t)((g >> 1) * 8 + r8) * 256;
            #pragma unroll
            for (int s = 0; s < 8; ++s) {
                uint32_t cB = ((uint32_t)(2 * s + (g & 1)) ^ (uint32_t)r8) << 4;
                #pragma unroll
                for (int ng = 0; ng < 4; ++ng) {
                    uint32_t k4[4];
                    ldm4(k4, aK + (uint32_t)ng * (16 * 256) + cB);
                    mma_f16(sacc[ng*2],   qh[s], &k4[0]);
                    mma_f16(sacc[ng*2],   ql[s], &k4[0]);
                    mma_f16(sacc[ng*2+1], qh[s], &k4[2]);
                    mma_f16(sacc[ng*2+1], ql[s], &k4[2]);
                }
            }

            // ---- scale (+ causal mask on diagonal tiles), log2 domain ----
            if (kb >= 2 * qb) {
                #pragma unroll
                for (int nt = 0; nt < 8; ++nt)
                    #pragma unroll
                    for (int j = 0; j < 4; ++j) {
                        int col = kb * 64 + nt * 8 + lam * 2 + (j & 1);
                        int row = rowbase + ldiv + ((j >> 1) << 3);
                        sacc[nt][j] = (col <= row) ? sacc[nt][j] * C1 : -1e30f;
                    }
            } else {
                #pragma unroll
                for (int nt = 0; nt < 8; ++nt)
                    #pragma unroll
                    for (int j = 0; j < 4; ++j) sacc[nt][j] *= C1;
            }

            // ---- online softmax (rows r and r+8) ----
            float mr0 = -1e30f, mr1 = -1e30f;
            #pragma unroll
            for (int nt = 0; nt < 8; ++nt) {
                mr0 = fmaxf(mr0, fmaxf(sacc[nt][0], sacc[nt][1]));
                mr1 = fmaxf(mr1, fmaxf(sacc[nt][2], sacc[nt][3]));
            }
            mr0 = fmaxf(mr0, __shfl_xor_sync(0xffffffffu, mr0, 1));
            mr0 = fmaxf(mr0, __shfl_xor_sync(0xffffffffu, mr0, 2));
            mr1 = fmaxf(mr1, __shfl_xor_sync(0xffffffffu, mr1, 1));
            mr1 = fmaxf(mr1, __shfl_xor_sync(0xffffffffu, mr1, 2));
            float mn0 = fmaxf(m0, mr0), mn1 = fmaxf(m1, mr1);
            float al0 = ex2(m0 - mn0), al1 = ex2(m1 - mn1);
            m0 = mn0; m1 = mn1;
            float ls0 = 0.f, ls1 = 0.f;
            #pragma unroll
            for (int nt = 0; nt < 8; ++nt) {
                float p0 = ex2(sacc[nt][0] - mn0);
                float p1 = ex2(sacc[nt][1] - mn0);
                float p2 = ex2(sacc[nt][2] - mn1);
                float p3 = ex2(sacc[nt][3] - mn1);
                sacc[nt][0] = p0; sacc[nt][1] = p1;
                sacc[nt][2] = p2; sacc[nt][3] = p3;
                ls0 += p0 + p1;  ls1 += p2 + p3;
            }
            ls0 += __shfl_xor_sync(0xffffffffu, ls0, 1);
            ls0 += __shfl_xor_sync(0xffffffffu, ls0, 2);
            ls1 += __shfl_xor_sync(0xffffffffu, ls1, 1);
            ls1 += __shfl_xor_sync(0xffffffffu, ls1, 2);
            l0 = l0 * al0 + ls0;  l1 = l1 * al1 + ls1;
            #pragma unroll
            for (int i = 0; i < 16; ++i) {
                oacc[i][0] *= al0;  oacc[i][1] *= al0;
                oacc[i][2] *= al1;  oacc[i][3] *= al1;
            }

            // ---- O += P V (fp16x2: Phi*V + Plo*V) ----
            const uint32_t aV = stg + 16384 + (uint32_t)((g >> 1) * 8 + r8) * 128;
            #pragma unroll
            for (int s2 = 0; s2 < 4; ++s2) {
                uint32_t ph[4], pl[4];
                packhl(sacc[2*s2][0],   sacc[2*s2][1],   ph[0], pl[0]);
                packhl(sacc[2*s2][2],   sacc[2*s2][3],   ph[1], pl[1]);
                packhl(sacc[2*s2+1][0], sacc[2*s2+1][1], ph[2], pl[2]);
                packhl(sacc[2*s2+1][2], sacc[2*s2+1][3], ph[3], pl[3]);
                uint32_t cV = ((uint32_t)(2 * s2 + (g & 1)) ^ (uint32_t)r8) << 4;
                #pragma unroll
                for (int ng = 0; ng < 8; ++ng) {
                    uint32_t v4[4];
                    ldm4(v4, aV + (uint32_t)ng * (16 * 128) + cV);
                    mma_f16(oacc[ng*2],   ph, &v4[0]);
                    mma_f16(oacc[ng*2],   pl, &v4[0]);
                    mma_f16(oacc[ng*2+1], ph, &v4[2]);
                    mma_f16(oacc[ng*2+1], pl, &v4[2]);
                }
            }
        }
    }

    // ---- finalize: /l, write fp16 att [b,t,h*128+d] ----
    float inv0 = 1.f / l0, inv1 = 1.f / l1;
    const int b = bh >> 4, h = bh & 15;
    const int row0 = qb * 128 + w * 16 + ldiv;
    const size_t obase = ((size_t)b * NT + row0) * NC + h * ND;
    #pragma unroll
    for (int nt = 0; nt < 16; ++nt) {
        const int d = nt * 8 + lam * 2;
        *(uint32_t*)&g_attf[obase + d]          = packh(oacc[nt][0] * inv0, oacc[nt][1] * inv0);
        *(uint32_t*)&g_attf[obase + 8 * NC + d] = packh(oacc[nt][2] * inv1, oacc[nt][3] * inv1);
    }
}

// ---------------------------------------------------------------------------
// Launch
// ---------------------------------------------------------------------------
extern "C" void kernel_launch(void* const* d_in, const int* in_sizes, int n_in,
                              void* d_out, int out_size)
{
    const float* x    = (const float*)d_in[0];
    const float* Wqkv = (const float*)d_in[1];
    const float* bqkv = (const float*)d_in[2];
    const float* Wo   = (const float*)d_in[3];
    const float* bo   = (const float*)d_in[4];
    float* out = (float*)d_out;

    cudaFuncSetAttribute(gemm_fp16x2<0>,
                         cudaFuncAttributeMaxDynamicSharedMemorySize, GEMM_SMEM);
    cudaFuncSetAttribute(gemm_fp16x2<1>,
                         cudaFuncAttributeMaxDynamicSharedMemorySize, GEMM_SMEM);
    cudaFuncSetAttribute(attn_mma_kernel,
                         cudaFuncAttributeMaxDynamicSharedMemorySize, ATTN_SMEM);

    __half *xh, *Whi, *Wlo, *Wohi, *Wolo, *attf;
    cudaGetSymbolAddress((void**)&xh,   g_xh);
    cudaGetSymbolAddress((void**)&Whi,  g_Whi);
    cudaGetSymbolAddress((void**)&Wlo,  g_Wlo);
    cudaGetSymbolAddress((void**)&Wohi, g_Wohi);
    cudaGetSymbolAddress((void**)&Wolo, g_Wolo);
    cudaGetSymbolAddress((void**)&attf, g_attf);

    // 1) conversions: x -> fp16 ; Wqkv^T, Wo^T -> fp16 hi/lo
    conv_f16_kernel<<<16384, 256>>>(x, xh, 4194304);
    transpose_split_kernel<<<dim3(192, 64), dim3(32, 8)>>>(Wqkv, Whi, Wlo, 2048, 6144);
    transpose_split_kernel<<<dim3(64, 64),  dim3(32, 8)>>>(Wo, Wohi, Wolo, 2048, 2048);

    // 2) QKV = x @ Wqkv + bqkv (fp16x2) -> g_q/g_k/g_v fp32 head-major
    gemm_fp16x2<0><<<dim3(48, 64), 256, GEMM_SMEM>>>(xh, Whi, Wlo, bqkv, nullptr);

    // 3) RoPE + fp16 conversion: q -> hi/lo, k -> plain
    rope_conv_kernel<<<32768, 256>>>();

    // 4) v transpose -> fp16 [bh][d][t]
    vconv_kernel<<<dim3(64, 4, 64), dim3(32, 8)>>>();

    // 5) flash attention (fp16x2 mma.sync) -> g_attf
    attn_mma_kernel<<<dim3(16, 64), 256, ATTN_SMEM>>>();

    // 6) out = att @ Wo + bo (fp16x2)
    gemm_fp16x2<1><<<dim3(16, 64), 256, GEMM_SMEM>>>(attf, Wohi, Wolo, bo, out);
}

// round 9
// speedup vs baseline: 6.8303x; 1.4988x over previous
#include <cuda_runtime.h>
#include <cuda_fp16.h>
#include <math.h>
#include <stdint.h>

// Problem dims (fixed by reference)
#define NB 4
#define NT 2048
#define NC 2048
#define NH 16
#define ND 128
#define NBH (NB*NH)          // 64
#define M1 (NB*NT)           // 8192
#define KDIM 2048

// ---------------------------------------------------------------------------
// Device scratch (allocation-free rule: __device__ globals)
// ---------------------------------------------------------------------------
__device__ __align__(256) float g_q[16777216];   // [B*H][T][D] fp32 (pre-rope)
__device__ __align__(256) float g_k[16777216];
__device__ __align__(256) float g_v[16777216];

__device__ __align__(256) __half g_xh[16777216];    // x fp16     [8192][2048]
__device__ __align__(256) __half g_Wh[12582912];    // Wqkv^T     [6144][2048]
__device__ __align__(256) __half g_Woh[4194304];    // Wo^T       [2048][2048]
__device__ __align__(256) __half g_attf[16777216];  // att fp16   [8192][2048]

__device__ __align__(256) __half g_qhi[16777216];   // rope'd q hi/lo [bh][t][d]
__device__ __align__(256) __half g_qlo[16777216];
__device__ __align__(256) __half g_kh[16777216];    // rope'd k fp16  [bh][t][d]
__device__ __align__(256) __half g_vT[16777216];    // v^T fp16       [bh][d][t]

// ---------------------------------------------------------------------------
// PTX helpers (Ampere-class, valid under compute_103)
// ---------------------------------------------------------------------------
__device__ __forceinline__ uint32_t smem_u32(const void* p) {
    uint32_t a;
    asm("{ .reg .u64 t; cvta.to.shared.u64 t, %1; cvt.u32.u64 %0, t; }"
        : "=r"(a) : "l"(p));
    return a;
}
__device__ __forceinline__ void cp16(uint32_t s, const void* g) {
    asm volatile("cp.async.cg.shared.global [%0], [%1], 16;" :: "r"(s), "l"(g));
}
__device__ __forceinline__ void ldm4(uint32_t* r, uint32_t addr) {
    asm volatile("ldmatrix.sync.aligned.m8n8.x4.shared.b16 {%0,%1,%2,%3}, [%4];"
                 : "=r"(r[0]), "=r"(r[1]), "=r"(r[2]), "=r"(r[3]) : "r"(addr));
}
__device__ __forceinline__ void mma_f16(float* c, const uint32_t* a, const uint32_t* b) {
    asm volatile(
        "mma.sync.aligned.m16n8k16.row.col.f32.f16.f16.f32 "
        "{%0,%1,%2,%3}, {%4,%5,%6,%7}, {%8,%9}, {%0,%1,%2,%3};"
        : "+f"(c[0]), "+f"(c[1]), "+f"(c[2]), "+f"(c[3])
        : "r"(a[0]), "r"(a[1]), "r"(a[2]), "r"(a[3]), "r"(b[0]), "r"(b[1]));
}
__device__ __forceinline__ float ex2(float x) {
    float y; asm("ex2.approx.f32 %0, %1;" : "=f"(y) : "f"(x)); return y;
}
__device__ __forceinline__ uint32_t packh(float x, float y) {
    __half2 h = __floats2half2_rn(x, y);
    return *(uint32_t*)&h;
}
__device__ __forceinline__ void packhl(float x, float y, uint32_t& hi, uint32_t& lo) {
    __half hx = __float2half_rn(x), hy = __float2half_rn(y);
    __half2 hp = __halves2half2(hx, hy);
    hi = *(uint32_t*)&hp;
    __half lx = __float2half_rn(x - __half2float(hx));
    __half ly = __float2half_rn(y - __half2float(hy));
    __half2 lp = __halves2half2(lx, ly);
    lo = *(uint32_t*)&lp;
}

// ---------------------------------------------------------------------------
// Plain fp16 mma.sync GEMM: C[M,N] = A[M,K] @ B^T
// BM=128 BN=128 BK=64, 8 warps (2x4). 2-stage pipeline, 64KB smem total
// -> 2 CTAs per SM.
// ---------------------------------------------------------------------------
#define BK 64
#define NKCH (KDIM/BK)       // 32
#define STG_SZ 32768
#define GEMM_SMEM (2*STG_SZ) // 65536

__device__ __forceinline__ void load_stage32(
    uint32_t stg, int t, int koff,
    const __half* pA, const __half* pB)
{
    #pragma unroll
    for (int i = 0; i < 4; ++i) {
        int idx = t + i * 256;
        int r = idx >> 3, ci = idx & 7;
        uint32_t so = stg + r * 128 + ((ci ^ (r & 7)) << 4);
        size_t go = (size_t)r * KDIM + koff + ci * 8;
        cp16(so,          pA + go);
        cp16(so + 16384,  pB + go);
    }
    asm volatile("cp.async.commit_group;" ::: "memory");
}

__device__ __forceinline__ void compute_stage(
    uint32_t stg, int wm, int wn, int lane, float acc[4][4][4])
{
    const int r = lane & 7, g = lane >> 3;
    const uint32_t rx = (uint32_t)r << 4;
    const uint32_t baseA = stg + (uint32_t)(wm * 64 + (g & 1) * 8 + r) * 128;
    const uint32_t hA4   = (uint32_t)(g >> 1) << 4;
    const uint32_t baseB = stg + 16384 + (uint32_t)(wn * 32 + (g >> 1) * 8 + r) * 128;
    const uint32_t hB4   = (uint32_t)(g & 1) << 4;

    #pragma unroll
    for (int s = 0; s < 4; ++s) {
        const uint32_t offA = (((uint32_t)s << 5) | hA4) ^ rx;
        const uint32_t offB = (((uint32_t)s << 5) | hB4) ^ rx;
        uint32_t ah[4][4], bh[2][4];
        #pragma unroll
        for (int i = 0; i < 4; ++i)
            ldm4(ah[i], baseA + i * 2048 + offA);
        #pragma unroll
        for (int j = 0; j < 2; ++j)
            ldm4(bh[j], baseB + j * 2048 + offB);
        #pragma unroll
        for (int i = 0; i < 4; ++i)
            #pragma unroll
            for (int q = 0; q < 4; ++q)
                mma_f16(acc[i][q], ah[i], &bh[q >> 1][(q & 1) * 2]);
    }
}

template<int EPI>
__global__ __launch_bounds__(256, 2)
void gemm_fp16(const __half* __restrict__ A, const __half* __restrict__ B,
               const float* __restrict__ bias, float* __restrict__ C)
{
    extern __shared__ __align__(1024) char smbuf[];
    uint32_t sb = smem_u32(smbuf);
    const int t    = threadIdx.x;
    const int lane = t & 31, wid = t >> 5;
    const int wm   = wid >> 2, wn = wid & 3;
    const int m0   = blockIdx.y * 128;
    const int n0   = blockIdx.x * 128;

    float acc[4][4][4];
    #pragma unroll
    for (int i = 0; i < 4; ++i)
        #pragma unroll
        for (int q = 0; q < 4; ++q)
            #pragma unroll
            for (int k = 0; k < 4; ++k) acc[i][q][k] = 0.f;

    const __half* pA = A + (size_t)m0 * KDIM;
    const __half* pB = B + (size_t)n0 * KDIM;

    load_stage32(sb,          t, 0,  pA, pB);
    load_stage32(sb + STG_SZ, t, BK, pA, pB);

    #pragma unroll 1
    for (int kt = 0; kt < NKCH; ++kt) {
        if (kt == NKCH - 1) asm volatile("cp.async.wait_group 0;" ::: "memory");
        else                asm volatile("cp.async.wait_group 1;" ::: "memory");
        __syncthreads();
        compute_stage(sb + (kt & 1) * STG_SZ, wm, wn, lane, acc);
        __syncthreads();
        if (kt + 2 < NKCH)
            load_stage32(sb + (kt & 1) * STG_SZ, t, (kt + 2) * BK, pA, pB);
    }

    const int mr  = (lane >> 2);
    const int nc0 = (lane & 3) * 2;
    if (EPI == 0) {
        const int which = n0 >> 11;
        const int h     = (n0 >> 7) & 15;
        float* dst = (which == 0) ? (float*)g_q
                   : (which == 1) ? (float*)g_k : (float*)g_v;
        const int b = m0 >> 11;
        #pragma unroll
        for (int i = 0; i < 4; ++i) {
            const int m  = m0 + wm * 64 + i * 16 + mr;
            const int tq = m & 2047;
            #pragma unroll
            for (int q = 0; q < 4; ++q) {
                const int dl = wn * 32 + q * 8 + nc0;
                float2 bs = *(const float2*)&bias[n0 + dl];
                size_t off = ((size_t)(b * 16 + h) * NT + tq) * ND + dl;
                float2 v0, v1;
                v0.x = acc[i][q][0] + bs.x;  v0.y = acc[i][q][1] + bs.y;
                v1.x = acc[i][q][2] + bs.x;  v1.y = acc[i][q][3] + bs.y;
                *(float2*)&dst[off]            = v0;
                *(float2*)&dst[off + 8 * ND]   = v1;
            }
        }
    } else {
        #pragma unroll
        for (int i = 0; i < 4; ++i) {
            const int m = m0 + wm * 64 + i * 16 + mr;
            #pragma unroll
            for (int q = 0; q < 4; ++q) {
                const int n = n0 + wn * 32 + q * 8 + nc0;
                float2 bs = *(const float2*)&bias[n];
                float2 v0, v1;
                v0.x = acc[i][q][0] + bs.x;  v0.y = acc[i][q][1] + bs.y;
                v1.x = acc[i][q][2] + bs.x;  v1.y = acc[i][q][3] + bs.y;
                *(float2*)&C[(size_t)m * NC + n]       = v0;
                *(float2*)&C[(size_t)(m + 8) * NC + n] = v1;
            }
        }
    }
}

// ---------------------------------------------------------------------------
// fp32 -> fp16 convert (x input)
// ---------------------------------------------------------------------------
__global__ void conv_f16_kernel(const float* __restrict__ in,
                                __half* __restrict__ out, int n4)
{
    int i = blockIdx.x * blockDim.x + threadIdx.x;
    if (i >= n4) return;
    float4 v = ((const float4*)in)[i];
    uint32_t* op = (uint32_t*)out;
    op[2 * i]     = packh(v.x, v.y);
    op[2 * i + 1] = packh(v.z, v.w);
}

// ---------------------------------------------------------------------------
// fp32 [K][N] -> transposed fp16 [N][K]  (weights)
// ---------------------------------------------------------------------------
__global__ void transpose_conv_kernel(const float* __restrict__ in,
                                      __half* __restrict__ out,
                                      int K, int N)
{
    __shared__ float tile[32][33];
    const int n0 = blockIdx.x * 32, k0 = blockIdx.y * 32;
    const int tx = threadIdx.x, ty = threadIdx.y;
    #pragma unroll
    for (int i = 0; i < 32; i += 8)
        tile[ty + i][tx] = in[(size_t)(k0 + ty + i) * N + n0 + tx];
    __syncthreads();
    #pragma unroll
    for (int i = 0; i < 32; i += 8) {
        size_t o = (size_t)(n0 + ty + i) * K + k0 + tx;
        out[o] = __float2half_rn(tile[tx][ty + i]);
    }
}

// ---------------------------------------------------------------------------
// RoPE fused with fp16 conversion: q -> hi/lo split, k -> plain fp16
// ---------------------------------------------------------------------------
__global__ void rope_conv_kernel()
{
    const int PER = NBH * NT * 32;  // 4194304
    int idx = blockIdx.x * blockDim.x + threadIdx.x;
    const bool isK = idx >= PER;
    int r = isK ? idx - PER : idx;
    const float* src = isK ? (const float*)g_k : (const float*)g_q;
    int fi   = r & 31;
    int tpos = (r >> 5) & (NT - 1);
    int bh   = r >> 16;
    size_t base = ((size_t)bh * NT + tpos) * ND;
    float2 x1 = *(const float2*)&src[base + 2 * fi];
    float2 x2 = *(const float2*)&src[base + 2 * fi + 64];
    float y1x, y1y, y2x, y2y;
    {
        float f = 2.0f * fi;
        float th = powf(10000.0f, -f * (1.0f / 64.0f));
        float s, c; sincosf((float)tpos * th, &s, &c);
        y1x = x1.x * c - x2.x * s;  y2x = x1.x * s + x2.x * c;
    }
    {
        float f = 2.0f * fi + 1.0f;
        float th = powf(10000.0f, -f * (1.0f / 64.0f));
        float s, c; sincosf((float)tpos * th, &s, &c);
        y1y = x1.y * c - x2.y * s;  y2y = x1.y * s + x2.y * c;
    }
    if (isK) {
        uint32_t* kh = (uint32_t*)g_kh;
        kh[(base + 2 * fi) >> 1]      = packh(y1x, y1y);
        kh[(base + 2 * fi + 64) >> 1] = packh(y2x, y2y);
    } else {
        uint32_t h1, l1, h2, l2;
        packhl(y1x, y1y, h1, l1);
        packhl(y2x, y2y, h2, l2);
        *(uint32_t*)&g_qhi[base + 2 * fi]      = h1;
        *(uint32_t*)&g_qlo[base + 2 * fi]      = l1;
        *(uint32_t*)&g_qhi[base + 2 * fi + 64] = h2;
        *(uint32_t*)&g_qlo[base + 2 * fi + 64] = l2;
    }
}

// ---------------------------------------------------------------------------
// v fp32 [bh][t][d] -> transposed fp16 [bh][d][t]
// ---------------------------------------------------------------------------
__global__ void vconv_kernel()
{
    __shared__ float tile[32][33];
    const int bh = blockIdx.z;
    const int t0 = blockIdx.x * 32, d0 = blockIdx.y * 32;
    const int tx = threadIdx.x, ty = threadIdx.y;
    const float* src = (const float*)g_v + (size_t)bh * NT * ND;
    #pragma unroll
    for (int i = 0; i < 32; i += 8)
        tile[ty + i][tx] = src[(size_t)(t0 + ty + i) * ND + d0 + tx];
    __syncthreads();
    __half* dh = (__half*)g_vT + (size_t)bh * ND * NT;
    #pragma unroll
    for (int i = 0; i < 32; i += 8) {
        size_t o = (size_t)(d0 + ty + i) * NT + t0 + tx;
        dh[o] = __float2half_rn(tile[tx][ty + i]);
    }
}

// ---------------------------------------------------------------------------
// Flash attention, fp16x2 mma.sync (unchanged from R7/R8).
// ---------------------------------------------------------------------------
#define ASTG 32768
#define ATTN_SMEM (3*ASTG + 65536)   // 163840

__device__ __forceinline__ void attn_load_kv(uint32_t stg, int t, int bh, int kb)
{
    const size_t koff = ((size_t)bh * NT + kb * 64) * ND;
    #pragma unroll
    for (int i = 0; i < 4; ++i) {
        int idx = t + i * 256;
        int r = idx >> 4, c = idx & 15;
        uint32_t dst = stg + r * 256 + ((c ^ (r & 7)) << 4);
        cp16(dst, (const __half*)g_kh + koff + (size_t)r * ND + c * 8);
    }
    const size_t voff = (size_t)bh * ND * NT + kb * 64;
    #pragma unroll
    for (int i = 0; i < 4; ++i) {
        int idx = t + i * 256;
        int r = idx >> 3, c = idx & 7;
        uint32_t dst = stg + 16384 + r * 128 + ((c ^ (r & 7)) << 4);
        cp16(dst, (const __half*)g_vT + voff + (size_t)r * NT + c * 8);
    }
    asm volatile("cp.async.commit_group;" ::: "memory");
}

__global__ __launch_bounds__(256, 1)
void attn_mma_kernel()
{
    extern __shared__ __align__(1024) char abuf[];
    uint32_t sb = smem_u32(abuf);
    const int t = threadIdx.x, lane = t & 31, w = t >> 5;
    const int lam = lane & 3, ldiv = lane >> 2;
    const int g = lane >> 3, r8 = lane & 7;
    const int qb = 15 - (int)blockIdx.x;   // heavy q-blocks first
    const int bh = blockIdx.y;
    const float C1 = 0.08838834764831845f * 1.4426950408889634f; // scale*log2e

    // Q tile (128 x 128) hi/lo
    const uint32_t qreg = sb + 3 * ASTG;
    const size_t qoff = ((size_t)bh * NT + qb * 128) * ND;
    #pragma unroll
    for (int i = 0; i < 8; ++i) {
        int idx = t + i * 256;
        int r = idx >> 4, c = idx & 15;
        uint32_t dst = qreg + r * 256 + ((c ^ (r & 7)) << 4);
        size_t src = qoff + (size_t)r * ND + c * 8;
        cp16(dst,          (const __half*)g_qhi + src);
        cp16(dst + 32768,  (const __half*)g_qlo + src);
    }
    asm volatile("cp.async.commit_group;" ::: "memory");   // group: Q
    const int nkt = 2 * qb + 2;
    attn_load_kv(sb,        t, bh, 0);
    attn_load_kv(sb + ASTG, t, bh, 1);

    // Hoist Q fragments to registers
    asm volatile("cp.async.wait_group 2;" ::: "memory");
    __syncthreads();
    uint32_t qh[8][4], ql[8][4];
    {
        const uint32_t aQ = qreg + (uint32_t)(w * 16 + (g & 1) * 8 + r8) * 256;
        #pragma unroll
        for (int s = 0; s < 8; ++s) {
            uint32_t cA = ((uint32_t)(2 * s + (g >> 1)) ^ (uint32_t)r8) << 4;
            ldm4(qh[s], aQ + cA);
            ldm4(ql[s], aQ + 32768 + cA);
        }
    }

    float oacc[16][4];
    #pragma unroll
    for (int i = 0; i < 16; ++i)
        #pragma unroll
        for (int j = 0; j < 4; ++j) oacc[i][j] = 0.f;
    float m0 = -INFINITY, m1 = -INFINITY, l0 = 0.f, l1 = 0.f;

    const int rowbase = qb * 128 + w * 16;

    int bc = 0, bl2 = 2;
    #pragma unroll 1
    for (int kb = 0; kb < nkt; ++kb) {
        if (kb == nkt - 1) asm volatile("cp.async.wait_group 0;" ::: "memory");
        else               asm volatile("cp.async.wait_group 1;" ::: "memory");
        __syncthreads();
        if (kb + 2 < nkt) attn_load_kv(sb + bl2 * ASTG, t, bh, kb + 2);
        uint32_t stg = sb + bc * ASTG;
        bc  = (bc  == 2) ? 0 : bc  + 1;
        bl2 = (bl2 == 2) ? 0 : bl2 + 1;

        if (kb * 64 <= rowbase + 15) {
            // ---- S = Q K^T (fp16x2: Qhi*K + Qlo*K) ----
            float sacc[8][4];
            #pragma unroll
            for (int i = 0; i < 8; ++i)
                #pragma unroll
                for (int j = 0; j < 4; ++j) sacc[i][j] = 0.f;

            const uint32_t aK = stg + (uint32_t)((g >> 1) * 8 + r8) * 256;
            #pragma unroll
            for (int s = 0; s < 8; ++s) {
                uint32_t cB = ((uint32_t)(2 * s + (g & 1)) ^ (uint32_t)r8) << 4;
                #pragma unroll
                for (int ng = 0; ng < 4; ++ng) {
                    uint32_t k4[4];
                    ldm4(k4, aK + (uint32_t)ng * (16 * 256) + cB);
                    mma_f16(sacc[ng*2],   qh[s], &k4[0]);
                    mma_f16(sacc[ng*2],   ql[s], &k4[0]);
                    mma_f16(sacc[ng*2+1], qh[s], &k4[2]);
                    mma_f16(sacc[ng*2+1], ql[s], &k4[2]);
                }
            }

            // ---- scale (+ causal mask on diagonal tiles), log2 domain ----
            if (kb >= 2 * qb) {
                #pragma unroll
                for (int nt = 0; nt < 8; ++nt)
                    #pragma unroll
                    for (int j = 0; j < 4; ++j) {
                        int col = kb * 64 + nt * 8 + lam * 2 + (j & 1);
                        int row = rowbase + ldiv + ((j >> 1) << 3);
                        sacc[nt][j] = (col <= row) ? sacc[nt][j] * C1 : -1e30f;
                    }
            } else {
                #pragma unroll
                for (int nt = 0; nt < 8; ++nt)
                    #pragma unroll
                    for (int j = 0; j < 4; ++j) sacc[nt][j] *= C1;
            }

            // ---- online softmax (rows r and r+8) ----
            float mr0 = -1e30f, mr1 = -1e30f;
            #pragma unroll
            for (int nt = 0; nt < 8; ++nt) {
                mr0 = fmaxf(mr0, fmaxf(sacc[nt][0], sacc[nt][1]));
                mr1 = fmaxf(mr1, fmaxf(sacc[nt][2], sacc[nt][3]));
            }
            mr0 = fmaxf(mr0, __shfl_xor_sync(0xffffffffu, mr0, 1));
            mr0 = fmaxf(mr0, __shfl_xor_sync(0xffffffffu, mr0, 2));
            mr1 = fmaxf(mr1, __shfl_xor_sync(0xffffffffu, mr1, 1));
            mr1 = fmaxf(mr1, __shfl_xor_sync(0xffffffffu, mr1, 2));
            float mn0 = fmaxf(m0, mr0), mn1 = fmaxf(m1, mr1);
            float al0 = ex2(m0 - mn0), al1 = ex2(m1 - mn1);
            m0 = mn0; m1 = mn1;
            float ls0 = 0.f, ls1 = 0.f;
            #pragma unroll
            for (int nt = 0; nt < 8; ++nt) {
                float p0 = ex2(sacc[nt][0] - mn0);
                float p1 = ex2(sacc[nt][1] - mn0);
                float p2 = ex2(sacc[nt][2] - mn1);
                float p3 = ex2(sacc[nt][3] - mn1);
                sacc[nt][0] = p0; sacc[nt][1] = p1;
                sacc[nt][2] = p2; sacc[nt][3] = p3;
                ls0 += p0 + p1;  ls1 += p2 + p3;
            }
            ls0 += __shfl_xor_sync(0xffffffffu, ls0, 1);
            ls0 += __shfl_xor_sync(0xffffffffu, ls0, 2);
            ls1 += __shfl_xor_sync(0xffffffffu, ls1, 1);
            ls1 += __shfl_xor_sync(0xffffffffu, ls1, 2);
            l0 = l0 * al0 + ls0;  l1 = l1 * al1 + ls1;
            #pragma unroll
            for (int i = 0; i < 16; ++i) {
                oacc[i][0] *= al0;  oacc[i][1] *= al0;
                oacc[i][2] *= al1;  oacc[i][3] *= al1;
            }

            // ---- O += P V (fp16x2: Phi*V + Plo*V) ----
            const uint32_t aV = stg + 16384 + (uint32_t)((g >> 1) * 8 + r8) * 128;
            #pragma unroll
            for (int s2 = 0; s2 < 4; ++s2) {
                uint32_t ph[4], pl[4];
                packhl(sacc[2*s2][0],   sacc[2*s2][1],   ph[0], pl[0]);
                packhl(sacc[2*s2][2],   sacc[2*s2][3],   ph[1], pl[1]);
                packhl(sacc[2*s2+1][0], sacc[2*s2+1][1], ph[2], pl[2]);
                packhl(sacc[2*s2+1][2], sacc[2*s2+1][3], ph[3], pl[3]);
                uint32_t cV = ((uint32_t)(2 * s2 + (g & 1)) ^ (uint32_t)r8) << 4;
                #pragma unroll
                for (int ng = 0; ng < 8; ++ng) {
                    uint32_t v4[4];
                    ldm4(v4, aV + (uint32_t)ng * (16 * 128) + cV);
                    mma_f16(oacc[ng*2],   ph, &v4[0]);
                    mma_f16(oacc[ng*2],   pl, &v4[0]);
                    mma_f16(oacc[ng*2+1], ph, &v4[2]);
                    mma_f16(oacc[ng*2+1], pl, &v4[2]);
                }
            }
        }
    }

    // ---- finalize: /l, write fp16 att [b,t,h*128+d] ----
    float inv0 = 1.f / l0, inv1 = 1.f / l1;
    const int b = bh >> 4, h = bh & 15;
    const int row0 = qb * 128 + w * 16 + ldiv;
    const size_t obase = ((size_t)b * NT + row0) * NC + h * ND;
    #pragma unroll
    for (int nt = 0; nt < 16; ++nt) {
        const int d = nt * 8 + lam * 2;
        *(uint32_t*)&g_attf[obase + d]          = packh(oacc[nt][0] * inv0, oacc[nt][1] * inv0);
        *(uint32_t*)&g_attf[obase + 8 * NC + d] = packh(oacc[nt][2] * inv1, oacc[nt][3] * inv1);
    }
}

// ---------------------------------------------------------------------------
// Launch
// ---------------------------------------------------------------------------
extern "C" void kernel_launch(void* const* d_in, const int* in_sizes, int n_in,
                              void* d_out, int out_size)
{
    const float* x    = (const float*)d_in[0];
    const float* Wqkv = (const float*)d_in[1];
    const float* bqkv = (const float*)d_in[2];
    const float* Wo   = (const float*)d_in[3];
    const float* bo   = (const float*)d_in[4];
    float* out = (float*)d_out;

    cudaFuncSetAttribute(gemm_fp16<0>,
                         cudaFuncAttributeMaxDynamicSharedMemorySize, GEMM_SMEM);
    cudaFuncSetAttribute(gemm_fp16<1>,
                         cudaFuncAttributeMaxDynamicSharedMemorySize, GEMM_SMEM);
    cudaFuncSetAttribute(attn_mma_kernel,
                         cudaFuncAttributeMaxDynamicSharedMemorySize, ATTN_SMEM);

    __half *xh, *Wh, *Woh, *attf;
    cudaGetSymbolAddress((void**)&xh,   g_xh);
    cudaGetSymbolAddress((void**)&Wh,   g_Wh);
    cudaGetSymbolAddress((void**)&Woh,  g_Woh);
    cudaGetSymbolAddress((void**)&attf, g_attf);

    // 1) conversions: x -> fp16 ; Wqkv^T, Wo^T -> fp16
    conv_f16_kernel<<<16384, 256>>>(x, xh, 4194304);
    transpose_conv_kernel<<<dim3(192, 64), dim3(32, 8)>>>(Wqkv, Wh, 2048, 6144);
    transpose_conv_kernel<<<dim3(64, 64),  dim3(32, 8)>>>(Wo, Woh, 2048, 2048);

    // 2) QKV = x @ Wqkv + bqkv (fp16 mma) -> g_q/g_k/g_v fp32 head-major
    gemm_fp16<0><<<dim3(48, 64), 256, GEMM_SMEM>>>(xh, Wh, bqkv, nullptr);

    // 3) RoPE + fp16 conversion: q -> hi/lo, k -> plain
    rope_conv_kernel<<<32768, 256>>>();

    // 4) v transpose -> fp16 [bh][d][t]
    vconv_kernel<<<dim3(64, 4, 64), dim3(32, 8)>>>();

    // 5) flash attention (fp16x2 mma.sync) -> g_attf
    attn_mma_kernel<<<dim3(16, 64), 256, ATTN_SMEM>>>();

    // 6) out = att @ Wo + bo (fp16 mma)
    gemm_fp16<1><<<dim3(16, 64), 256, GEMM_SMEM>>>(attf, Woh, bo, out);
}

// round 11
// speedup vs baseline: 7.9506x; 1.1640x over previous
#include <cuda_runtime.h>
#include <cuda_fp16.h>
#include <math.h>
#include <stdint.h>

// Problem dims (fixed by reference)
#define NB 4
#define NT 2048
#define NC 2048
#define NH 16
#define ND 128
#define NBH (NB*NH)          // 64
#define M1 (NB*NT)           // 8192
#define KDIM 2048

// ---------------------------------------------------------------------------
// Device scratch (allocation-free rule: __device__ globals)
// ---------------------------------------------------------------------------
__device__ __align__(256) float g_q[16777216];   // [B*H][T][D] fp32 (pre-rope)
__device__ __align__(256) float g_k[16777216];
__device__ __align__(256) float g_v[16777216];

__device__ __align__(256) __half g_xh[16777216];    // x fp16     [8192][2048]
__device__ __align__(256) __half g_Wh[12582912];    // Wqkv^T     [6144][2048]
__device__ __align__(256) __half g_Woh[4194304];    // Wo^T       [2048][2048]
__device__ __align__(256) __half g_attf[16777216];  // att fp16   [8192][2048]

__device__ __align__(256) __half g_qh[16777216];    // rope'd q fp16 [bh][t][d]
__device__ __align__(256) __half g_kh[16777216];    // rope'd k fp16 [bh][t][d]
__device__ __align__(256) __half g_vT[16777216];    // v^T fp16      [bh][d][t]

// ---------------------------------------------------------------------------
// PTX helpers (Ampere-class, valid under compute_103)
// ---------------------------------------------------------------------------
__device__ __forceinline__ uint32_t smem_u32(const void* p) {
    uint32_t a;
    asm("{ .reg .u64 t; cvta.to.shared.u64 t, %1; cvt.u32.u64 %0, t; }"
        : "=r"(a) : "l"(p));
    return a;
}
__device__ __forceinline__ void cp16(uint32_t s, const void* g) {
    asm volatile("cp.async.cg.shared.global [%0], [%1], 16;" :: "r"(s), "l"(g));
}
__device__ __forceinline__ void ldm4(uint32_t* r, uint32_t addr) {
    asm volatile("ldmatrix.sync.aligned.m8n8.x4.shared.b16 {%0,%1,%2,%3}, [%4];"
                 : "=r"(r[0]), "=r"(r[1]), "=r"(r[2]), "=r"(r[3]) : "r"(addr));
}
__device__ __forceinline__ void mma_f16(float* c, const uint32_t* a, const uint32_t* b) {
    asm volatile(
        "mma.sync.aligned.m16n8k16.row.col.f32.f16.f16.f32 "
        "{%0,%1,%2,%3}, {%4,%5,%6,%7}, {%8,%9}, {%0,%1,%2,%3};"
        : "+f"(c[0]), "+f"(c[1]), "+f"(c[2]), "+f"(c[3])
        : "r"(a[0]), "r"(a[1]), "r"(a[2]), "r"(a[3]), "r"(b[0]), "r"(b[1]));
}
__device__ __forceinline__ float ex2(float x) {
    float y; asm("ex2.approx.f32 %0, %1;" : "=f"(y) : "f"(x)); return y;
}
__device__ __forceinline__ uint32_t packh(float x, float y) {
    __half2 h = __floats2half2_rn(x, y);
    return *(uint32_t*)&h;
}

// ---------------------------------------------------------------------------
// Plain fp16 mma.sync GEMM (unchanged from R9): C[M,N] = A[M,K] @ B^T
// BM=128 BN=128 BK=64, 8 warps (2x4). 2-stage, 64KB smem -> 2 CTAs/SM.
// ---------------------------------------------------------------------------
#define BK 64
#define NKCH (KDIM/BK)       // 32
#define STG_SZ 32768
#define GEMM_SMEM (2*STG_SZ) // 65536

__device__ __forceinline__ void load_stage32(
    uint32_t stg, int t, int koff,
    const __half* pA, const __half* pB)
{
    #pragma unroll
    for (int i = 0; i < 4; ++i) {
        int idx = t + i * 256;
        int r = idx >> 3, ci = idx & 7;
        uint32_t so = stg + r * 128 + ((ci ^ (r & 7)) << 4);
        size_t go = (size_t)r * KDIM + koff + ci * 8;
        cp16(so,          pA + go);
        cp16(so + 16384,  pB + go);
    }
    asm volatile("cp.async.commit_group;" ::: "memory");
}

__device__ __forceinline__ void compute_stage(
    uint32_t stg, int wm, int wn, int lane, float acc[4][4][4])
{
    const int r = lane & 7, g = lane >> 3;
    const uint32_t rx = (uint32_t)r << 4;
    const uint32_t baseA = stg + (uint32_t)(wm * 64 + (g & 1) * 8 + r) * 128;
    const uint32_t hA4   = (uint32_t)(g >> 1) << 4;
    const uint32_t baseB = stg + 16384 + (uint32_t)(wn * 32 + (g >> 1) * 8 + r) * 128;
    const uint32_t hB4   = (uint32_t)(g & 1) << 4;

    #pragma unroll
    for (int s = 0; s < 4; ++s) {
        const uint32_t offA = (((uint32_t)s << 5) | hA4) ^ rx;
        const uint32_t offB = (((uint32_t)s << 5) | hB4) ^ rx;
        uint32_t ah[4][4], bh[2][4];
        #pragma unroll
        for (int i = 0; i < 4; ++i)
            ldm4(ah[i], baseA + i * 2048 + offA);
        #pragma unroll
        for (int j = 0; j < 2; ++j)
            ldm4(bh[j], baseB + j * 2048 + offB);
        #pragma unroll
        for (int i = 0; i < 4; ++i)
            #pragma unroll
            for (int q = 0; q < 4; ++q)
                mma_f16(acc[i][q], ah[i], &bh[q >> 1][(q & 1) * 2]);
    }
}

template<int EPI>
__global__ __launch_bounds__(256, 2)
void gemm_fp16(const __half* __restrict__ A, const __half* __restrict__ B,
               const float* __restrict__ bias, float* __restrict__ C)
{
    extern __shared__ __align__(1024) char smbuf[];
    uint32_t sb = smem_u32(smbuf);
    const int t    = threadIdx.x;
    const int lane = t & 31, wid = t >> 5;
    const int wm   = wid >> 2, wn = wid & 3;
    const int m0   = blockIdx.y * 128;
    const int n0   = blockIdx.x * 128;

    float acc[4][4][4];
    #pragma unroll
    for (int i = 0; i < 4; ++i)
        #pragma unroll
        for (int q = 0; q < 4; ++q)
            #pragma unroll
            for (int k = 0; k < 4; ++k) acc[i][q][k] = 0.f;

    const __half* pA = A + (size_t)m0 * KDIM;
    const __half* pB = B + (size_t)n0 * KDIM;

    load_stage32(sb,          t, 0,  pA, pB);
    load_stage32(sb + STG_SZ, t, BK, pA, pB);

    #pragma unroll 1
    for (int kt = 0; kt < NKCH; ++kt) {
        if (kt == NKCH - 1) asm volatile("cp.async.wait_group 0;" ::: "memory");
        else                asm volatile("cp.async.wait_group 1;" ::: "memory");
        __syncthreads();
        compute_stage(sb + (kt & 1) * STG_SZ, wm, wn, lane, acc);
        __syncthreads();
        if (kt + 2 < NKCH)
            load_stage32(sb + (kt & 1) * STG_SZ, t, (kt + 2) * BK, pA, pB);
    }

    const int mr  = (lane >> 2);
    const int nc0 = (lane & 3) * 2;
    if (EPI == 0) {
        const int which = n0 >> 11;
        const int h     = (n0 >> 7) & 15;
        float* dst = (which == 0) ? (float*)g_q
                   : (which == 1) ? (float*)g_k : (float*)g_v;
        const int b = m0 >> 11;
        #pragma unroll
        for (int i = 0; i < 4; ++i) {
            const int m  = m0 + wm * 64 + i * 16 + mr;
            const int tq = m & 2047;
            #pragma unroll
            for (int q = 0; q < 4; ++q) {
                const int dl = wn * 32 + q * 8 + nc0;
                float2 bs = *(const float2*)&bias[n0 + dl];
                size_t off = ((size_t)(b * 16 + h) * NT + tq) * ND + dl;
                float2 v0, v1;
                v0.x = acc[i][q][0] + bs.x;  v0.y = acc[i][q][1] + bs.y;
                v1.x = acc[i][q][2] + bs.x;  v1.y = acc[i][q][3] + bs.y;
                *(float2*)&dst[off]            = v0;
                *(float2*)&dst[off + 8 * ND]   = v1;
            }
        }
    } else {
        #pragma unroll
        for (int i = 0; i < 4; ++i) {
            const int m = m0 + wm * 64 + i * 16 + mr;
            #pragma unroll
            for (int q = 0; q < 4; ++q) {
                const int n = n0 + wn * 32 + q * 8 + nc0;
                float2 bs = *(const float2*)&bias[n];
                float2 v0, v1;
                v0.x = acc[i][q][0] + bs.x;  v0.y = acc[i][q][1] + bs.y;
                v1.x = acc[i][q][2] + bs.x;  v1.y = acc[i][q][3] + bs.y;
                *(float2*)&C[(size_t)m * NC + n]       = v0;
                *(float2*)&C[(size_t)(m + 8) * NC + n] = v1;
            }
        }
    }
}

// ---------------------------------------------------------------------------
// fp32 -> fp16 convert (x input)
// ---------------------------------------------------------------------------
__global__ void conv_f16_kernel(const float* __restrict__ in,
                                __half* __restrict__ out, int n4)
{
    int i = blockIdx.x * blockDim.x + threadIdx.x;
    if (i >= n4) return;
    float4 v = ((const float4*)in)[i];
    uint32_t* op = (uint32_t*)out;
    op[2 * i]     = packh(v.x, v.y);
    op[2 * i + 1] = packh(v.z, v.w);
}

// ---------------------------------------------------------------------------
// fp32 [K][N] -> transposed fp16 [N][K]  (weights)
// ---------------------------------------------------------------------------
__global__ void transpose_conv_kernel(const float* __restrict__ in,
                                      __half* __restrict__ out,
                                      int K, int N)
{
    __shared__ float tile[32][33];
    const int n0 = blockIdx.x * 32, k0 = blockIdx.y * 32;
    const int tx = threadIdx.x, ty = threadIdx.y;
    #pragma unroll
    for (int i = 0; i < 32; i += 8)
        tile[ty + i][tx] = in[(size_t)(k0 + ty + i) * N + n0 + tx];
    __syncthreads();
    #pragma unroll
    for (int i = 0; i < 32; i += 8) {
        size_t o = (size_t)(n0 + ty + i) * K + k0 + tx;
        out[o] = __float2half_rn(tile[tx][ty + i]);
    }
}

// ---------------------------------------------------------------------------
// RoPE fused with fp16 conversion: q and k -> plain fp16 (same path)
// ---------------------------------------------------------------------------
__global__ void rope_conv_kernel()
{
    const int PER = NBH * NT * 32;  // 4194304
    int idx = blockIdx.x * blockDim.x + threadIdx.x;
    const bool isK = idx >= PER;
    int r = isK ? idx - PER : idx;
    const float* src = isK ? (const float*)g_k : (const float*)g_q;
    __half* dst = isK ? (__half*)g_kh : (__half*)g_qh;
    int fi   = r & 31;
    int tpos = (r >> 5) & (NT - 1);
    int bh   = r >> 16;
    size_t base = ((size_t)bh * NT + tpos) * ND;
    float2 x1 = *(const float2*)&src[base + 2 * fi];
    float2 x2 = *(const float2*)&src[base + 2 * fi + 64];
    float y1x, y1y, y2x, y2y;
    {
        float f = 2.0f * fi;
        float th = powf(10000.0f, -f * (1.0f / 64.0f));
        float s, c; sincosf((float)tpos * th, &s, &c);
        y1x = x1.x * c - x2.x * s;  y2x = x1.x * s + x2.x * c;
    }
    {
        float f = 2.0f * fi + 1.0f;
        float th = powf(10000.0f, -f * (1.0f / 64.0f));
        float s, c; sincosf((float)tpos * th, &s, &c);
        y1y = x1.y * c - x2.y * s;  y2y = x1.y * s + x2.y * c;
    }
    *(uint32_t*)&dst[base + 2 * fi]      = packh(y1x, y1y);
    *(uint32_t*)&dst[base + 2 * fi + 64] = packh(y2x, y2y);
}

// ---------------------------------------------------------------------------
// v fp32 [bh][t][d] -> transposed fp16 [bh][d][t]
// ---------------------------------------------------------------------------
__global__ void vconv_kernel()
{
    __shared__ float tile[32][33];
    const int bh = blockIdx.z;
    const int t0 = blockIdx.x * 32, d0 = blockIdx.y * 32;
    const int tx = threadIdx.x, ty = threadIdx.y;
    const float* src = (const float*)g_v + (size_t)bh * NT * ND;
    #pragma unroll
    for (int i = 0; i < 32; i += 8)
        tile[ty + i][tx] = src[(size_t)(t0 + ty + i) * ND + d0 + tx];
    __syncthreads();
    __half* dh = (__half*)g_vT + (size_t)bh * ND * NT;
    #pragma unroll
    for (int i = 0; i < 32; i += 8) {
        size_t o = (size_t)(d0 + ty + i) * NT + t0 + tx;
        dh[o] = __float2half_rn(tile[tx][ty + i]);
    }
}

// ---------------------------------------------------------------------------
// Flash attention, plain fp16 mma.sync. BQ=128, BK=64, 8 warps (16 q-rows).
// Q plain fp16 (register-hoisted); K, V plain fp16; P plain fp16.
// smem: 3 x 32KB K/V stages + Q 32KB = 128KB.
// ---------------------------------------------------------------------------
#define ASTG 32768
#define ATTN_SMEM (3*ASTG + 32768)   // 131072

__device__ __forceinline__ void attn_load_kv(uint32_t stg, int t, int bh, int kb)
{
    const size_t koff = ((size_t)bh * NT + kb * 64) * ND;
    #pragma unroll
    for (int i = 0; i < 4; ++i) {
        int idx = t + i * 256;
        int r = idx >> 4, c = idx & 15;
        uint32_t dst = stg + r * 256 + ((c ^ (r & 7)) << 4);
        cp16(dst, (const __half*)g_kh + koff + (size_t)r * ND + c * 8);
    }
    const size_t voff = (size_t)bh * ND * NT + kb * 64;
    #pragma unroll
    for (int i = 0; i < 4; ++i) {
        int idx = t + i * 256;
        int r = idx >> 3, c = idx & 7;
        uint32_t dst = stg + 16384 + r * 128 + ((c ^ (r & 7)) << 4);
        cp16(dst, (const __half*)g_vT + voff + (size_t)r * NT + c * 8);
    }
    asm volatile("cp.async.commit_group;" ::: "memory");
}

__global__ __launch_bounds__(256, 1)
void attn_mma_kernel()
{
    extern __shared__ __align__(1024) char abuf[];
    uint32_t sb = smem_u32(abuf);
    const int t = threadIdx.x, lane = t & 31, w = t >> 5;
    const int lam = lane & 3, ldiv = lane >> 2;
    const int g = lane >> 3, r8 = lane & 7;
    const int qb = 15 - (int)blockIdx.x;   // heavy q-blocks first
    const int bh = blockIdx.y;
    const float C1 = 0.08838834764831845f * 1.4426950408889634f; // scale*log2e

    // Q tile (128 x 128) plain fp16: 128 rows x 16 chunks = 2048 chunks
    const uint32_t qreg = sb + 3 * ASTG;
    const size_t qoff = ((size_t)bh * NT + qb * 128) * ND;
    #pragma unroll
    for (int i = 0; i < 8; ++i) {                 // FIX: full tile (was i < 4)
        int idx = t + i * 256;
        int r = idx >> 4, c = idx & 15;
        uint32_t dst = qreg + r * 256 + ((c ^ (r & 7)) << 4);
        cp16(dst, (const __half*)g_qh + qoff + (size_t)r * ND + c * 8);
    }
    asm volatile("cp.async.commit_group;" ::: "memory");   // group: Q
    const int nkt = 2 * qb + 2;
    attn_load_kv(sb,        t, bh, 0);
    attn_load_kv(sb + ASTG, t, bh, 1);

    // Hoist Q fragments to registers
    asm volatile("cp.async.wait_group 2;" ::: "memory");
    __syncthreads();
    uint32_t qh[8][4];
    {
        const uint32_t aQ = qreg + (uint32_t)(w * 16 + (g & 1) * 8 + r8) * 256;
        #pragma unroll
        for (int s = 0; s < 8; ++s) {
            uint32_t cA = ((uint32_t)(2 * s + (g >> 1)) ^ (uint32_t)r8) << 4;
            ldm4(qh[s], aQ + cA);
        }
    }

    float oacc[16][4];
    #pragma unroll
    for (int i = 0; i < 16; ++i)
        #pragma unroll
        for (int j = 0; j < 4; ++j) oacc[i][j] = 0.f;
    float m0 = -INFINITY, m1 = -INFINITY, l0 = 0.f, l1 = 0.f;

    const int rowbase = qb * 128 + w * 16;

    int bc = 0, bl2 = 2;
    #pragma unroll 1
    for (int kb = 0; kb < nkt; ++kb) {
        if (kb == nkt - 1) asm volatile("cp.async.wait_group 0;" ::: "memory");
        else               asm volatile("cp.async.wait_group 1;" ::: "memory");
        __syncthreads();
        if (kb + 2 < nkt) attn_load_kv(sb + bl2 * ASTG, t, bh, kb + 2);
        uint32_t stg = sb + bc * ASTG;
        bc  = (bc  == 2) ? 0 : bc  + 1;
        bl2 = (bl2 == 2) ? 0 : bl2 + 1;

        if (kb * 64 <= rowbase + 15) {
            // ---- S = Q K^T (plain fp16) ----
            float sacc[8][4];
            #pragma unroll
            for (int i = 0; i < 8; ++i)
                #pragma unroll
                for (int j = 0; j < 4; ++j) sacc[i][j] = 0.f;

            const uint32_t aK = stg + (uint32_t)((g >> 1) * 8 + r8) * 256;
            #pragma unroll
            for (int s = 0; s < 8; ++s) {
                uint32_t cB = ((uint32_t)(2 * s + (g & 1)) ^ (uint32_t)r8) << 4;
                #pragma unroll
                for (int ng = 0; ng < 4; ++ng) {
                    uint32_t k4[4];
                    ldm4(k4, aK + (uint32_t)ng * (16 * 256) + cB);
                    mma_f16(sacc[ng*2],   qh[s], &k4[0]);
                    mma_f16(sacc[ng*2+1], qh[s], &k4[2]);
                }
            }

            // ---- scale (+ causal mask on diagonal tiles), log2 domain ----
            if (kb >= 2 * qb) {
                #pragma unroll
                for (int nt = 0; nt < 8; ++nt)
                    #pragma unroll
                    for (int j = 0; j < 4; ++j) {
                        int col = kb * 64 + nt * 8 + lam * 2 + (j & 1);
                        int row = rowbase + ldiv + ((j >> 1) << 3);
                        sacc[nt][j] = (col <= row) ? sacc[nt][j] * C1 : -1e30f;
                    }
            } else {
                #pragma unroll
                for (int nt = 0; nt < 8; ++nt)
                    #pragma unroll
                    for (int j = 0; j < 4; ++j) sacc[nt][j] *= C1;
            }

            // ---- online softmax (rows r and r+8) ----
            float mr0 = -1e30f, mr1 = -1e30f;
            #pragma unroll
            for (int nt = 0; nt < 8; ++nt) {
                mr0 = fmaxf(mr0, fmaxf(sacc[nt][0], sacc[nt][1]));
                mr1 = fmaxf(mr1, fmaxf(sacc[nt][2], sacc[nt][3]));
            }
            mr0 = fmaxf(mr0, __shfl_xor_sync(0xffffffffu, mr0, 1));
            mr0 = fmaxf(mr0, __shfl_xor_sync(0xffffffffu, mr0, 2));
            mr1 = fmaxf(mr1, __shfl_xor_sync(0xffffffffu, mr1, 1));
            mr1 = fmaxf(mr1, __shfl_xor_sync(0xffffffffu, mr1, 2));
            float mn0 = fmaxf(m0, mr0), mn1 = fmaxf(m1, mr1);
            float al0 = ex2(m0 - mn0), al1 = ex2(m1 - mn1);
            m0 = mn0; m1 = mn1;
            float ls0 = 0.f, ls1 = 0.f;
            #pragma unroll
            for (int nt = 0; nt < 8; ++nt) {
                float p0 = ex2(sacc[nt][0] - mn0);
                float p1 = ex2(sacc[nt][1] - mn0);
                float p2 = ex2(sacc[nt][2] - mn1);
                float p3 = ex2(sacc[nt][3] - mn1);
                sacc[nt][0] = p0; sacc[nt][1] = p1;
                sacc[nt][2] = p2; sacc[nt][3] = p3;
                ls0 += p0 + p1;  ls1 += p2 + p3;
            }
            ls0 += __shfl_xor_sync(0xffffffffu, ls0, 1);
            ls0 += __shfl_xor_sync(0xffffffffu, ls0, 2);
            ls1 += __shfl_xor_sync(0xffffffffu, ls1, 1);
            ls1 += __shfl_xor_sync(0xffffffffu, ls1, 2);
            l0 = l0 * al0 + ls0;  l1 = l1 * al1 + ls1;
            #pragma unroll
            for (int i = 0; i < 16; ++i) {
                oacc[i][0] *= al0;  oacc[i][1] *= al0;
                oacc[i][2] *= al1;  oacc[i][3] *= al1;
            }

            // ---- O += P V (plain fp16 P) ----
            const uint32_t aV = stg + 16384 + (uint32_t)((g >> 1) * 8 + r8) * 128;
            #pragma unroll
            for (int s2 = 0; s2 < 4; ++s2) {
                uint32_t ph[4];
                ph[0] = packh(sacc[2*s2][0],   sacc[2*s2][1]);
                ph[1] = packh(sacc[2*s2][2],   sacc[2*s2][3]);
                ph[2] = packh(sacc[2*s2+1][0], sacc[2*s2+1][1]);
                ph[3] = packh(sacc[2*s2+1][2], sacc[2*s2+1][3]);
                uint32_t cV = ((uint32_t)(2 * s2 + (g & 1)) ^ (uint32_t)r8) << 4;
                #pragma unroll
                for (int ng = 0; ng < 8; ++ng) {
                    uint32_t v4[4];
                    ldm4(v4, aV + (uint32_t)ng * (16 * 128) + cV);
                    mma_f16(oacc[ng*2],   ph, &v4[0]);
                    mma_f16(oacc[ng*2+1], ph, &v4[2]);
                }
            }
        }
    }

    // ---- finalize: /l, write fp16 att [b,t,h*128+d] ----
    float inv0 = 1.f / l0, inv1 = 1.f / l1;
    const int b = bh >> 4, h = bh & 15;
    const int row0 = qb * 128 + w * 16 + ldiv;
    const size_t obase = ((size_t)b * NT + row0) * NC + h * ND;
    #pragma unroll
    for (int nt = 0; nt < 16; ++nt) {
        const int d = nt * 8 + lam * 2;
        *(uint32_t*)&g_attf[obase + d]          = packh(oacc[nt][0] * inv0, oacc[nt][1] * inv0);
        *(uint32_t*)&g_attf[obase + 8 * NC + d] = packh(oacc[nt][2] * inv1, oacc[nt][3] * inv1);
    }
}

// ---------------------------------------------------------------------------
// Launch
// ---------------------------------------------------------------------------
extern "C" void kernel_launch(void* const* d_in, const int* in_sizes, int n_in,
                              void* d_out, int out_size)
{
    const float* x    = (const float*)d_in[0];
    const float* Wqkv = (const float*)d_in[1];
    const float* bqkv = (const float*)d_in[2];
    const float* Wo   = (const float*)d_in[3];
    const float* bo   = (const float*)d_in[4];
    float* out = (float*)d_out;

    cudaFuncSetAttribute(gemm_fp16<0>,
                         cudaFuncAttributeMaxDynamicSharedMemorySize, GEMM_SMEM);
    cudaFuncSetAttribute(gemm_fp16<1>,
                         cudaFuncAttributeMaxDynamicSharedMemorySize, GEMM_SMEM);
    cudaFuncSetAttribute(attn_mma_kernel,
                         cudaFuncAttributeMaxDynamicSharedMemorySize, ATTN_SMEM);

    __half *xh, *Wh, *Woh, *attf;
    cudaGetSymbolAddress((void**)&xh,   g_xh);
    cudaGetSymbolAddress((void**)&Wh,   g_Wh);
    cudaGetSymbolAddress((void**)&Woh,  g_Woh);
    cudaGetSymbolAddress((void**)&attf, g_attf);

    // 1) conversions: x -> fp16 ; Wqkv^T, Wo^T -> fp16
    conv_f16_kernel<<<16384, 256>>>(x, xh, 4194304);
    transpose_conv_kernel<<<dim3(192, 64), dim3(32, 8)>>>(Wqkv, Wh, 2048, 6144);
    transpose_conv_kernel<<<dim3(64, 64),  dim3(32, 8)>>>(Wo, Woh, 2048, 2048);

    // 2) QKV = x @ Wqkv + bqkv (fp16 mma) -> g_q/g_k/g_v fp32 head-major
    gemm_fp16<0><<<dim3(48, 64), 256, GEMM_SMEM>>>(xh, Wh, bqkv, nullptr);

    // 3) RoPE + fp16 conversion (q and k plain)
    rope_conv_kernel<<<32768, 256>>>();

    // 4) v transpose -> fp16 [bh][d][t]
    vconv_kernel<<<dim3(64, 4, 64), dim3(32, 8)>>>();

    // 5) flash attention (plain fp16 mma.sync) -> g_attf
    attn_mma_kernel<<<dim3(16, 64), 256, ATTN_SMEM>>>();

    // 6) out = att @ Wo + bo (fp16 mma)
    gemm_fp16<1><<<dim3(16, 64), 256, GEMM_SMEM>>>(attf, Woh, bo, out);
}

// round 12
// speedup vs baseline: 7.9532x; 1.0003x over previous
#include <cuda_runtime.h>
#include <cuda_fp16.h>
#include <math.h>
#include <stdint.h>

// Problem dims (fixed by reference)
#define NB 4
#define NT 2048
#define NC 2048
#define NH 16
#define ND 128
#define NBH (NB*NH)          // 64
#define M1 (NB*NT)           // 8192
#define KDIM 2048

// ---------------------------------------------------------------------------
// Device scratch (allocation-free rule: __device__ globals)
// ---------------------------------------------------------------------------
__device__ __align__(256) float g_q[16777216];   // [B*H][T][D] fp32 (pre-rope)
__device__ __align__(256) float g_k[16777216];
__device__ __align__(256) float g_v[16777216];

__device__ __align__(256) __half g_xh[16777216];    // x fp16     [8192][2048]
__device__ __align__(256) __half g_Wh[12582912];    // Wqkv^T     [6144][2048]
__device__ __align__(256) __half g_Woh[4194304];    // Wo^T       [2048][2048]
__device__ __align__(256) __half g_attf[16777216];  // att fp16   [8192][2048]

__device__ __align__(256) __half g_qh[16777216];    // rope'd q fp16 [bh][t][d]
__device__ __align__(256) __half g_kh[16777216];    // rope'd k fp16 [bh][t][d]
__device__ __align__(256) __half g_vT[16777216];    // v^T fp16      [bh][d][t]

// ---------------------------------------------------------------------------
// PTX helpers (Ampere-class, valid under compute_103)
// ---------------------------------------------------------------------------
__device__ __forceinline__ uint32_t smem_u32(const void* p) {
    uint32_t a;
    asm("{ .reg .u64 t; cvta.to.shared.u64 t, %1; cvt.u32.u64 %0, t; }"
        : "=r"(a) : "l"(p));
    return a;
}
__device__ __forceinline__ void cp16(uint32_t s, const void* g) {
    asm volatile("cp.async.cg.shared.global [%0], [%1], 16;" :: "r"(s), "l"(g));
}
__device__ __forceinline__ void ldm4(uint32_t* r, uint32_t addr) {
    asm volatile("ldmatrix.sync.aligned.m8n8.x4.shared.b16 {%0,%1,%2,%3}, [%4];"
                 : "=r"(r[0]), "=r"(r[1]), "=r"(r[2]), "=r"(r[3]) : "r"(addr));
}
__device__ __forceinline__ void mma_f16(float* c, const uint32_t* a, const uint32_t* b) {
    asm volatile(
        "mma.sync.aligned.m16n8k16.row.col.f32.f16.f16.f32 "
        "{%0,%1,%2,%3}, {%4,%5,%6,%7}, {%8,%9}, {%0,%1,%2,%3};"
        : "+f"(c[0]), "+f"(c[1]), "+f"(c[2]), "+f"(c[3])
        : "r"(a[0]), "r"(a[1]), "r"(a[2]), "r"(a[3]), "r"(b[0]), "r"(b[1]));
}
__device__ __forceinline__ float ex2(float x) {
    float y; asm("ex2.approx.f32 %0, %1;" : "=f"(y) : "f"(x)); return y;
}
__device__ __forceinline__ uint32_t packh(float x, float y) {
    __half2 h = __floats2half2_rn(x, y);
    return *(uint32_t*)&h;
}

// ---------------------------------------------------------------------------
// Plain fp16 mma.sync GEMM: C[M,N] = A[M,K] @ B^T
// BM=128 BN=128 BK=64, 8 warps (2x4).
// 3-stage pipeline, ONE sync per stage, 96KB smem -> still 2 CTAs/SM.
// ---------------------------------------------------------------------------
#define BK 64
#define NKCH (KDIM/BK)       // 32
#define STG_SZ 32768
#define GEMM_SMEM (3*STG_SZ) // 98304

__device__ __forceinline__ void load_stage32(
    uint32_t stg, int t, int koff,
    const __half* pA, const __half* pB)
{
    #pragma unroll
    for (int i = 0; i < 4; ++i) {
        int idx = t + i * 256;
        int r = idx >> 3, ci = idx & 7;
        uint32_t so = stg + r * 128 + ((ci ^ (r & 7)) << 4);
        size_t go = (size_t)r * KDIM + koff + ci * 8;
        cp16(so,          pA + go);
        cp16(so + 16384,  pB + go);
    }
    asm volatile("cp.async.commit_group;" ::: "memory");
}

__device__ __forceinline__ void compute_stage(
    uint32_t stg, int wm, int wn, int lane, float acc[4][4][4])
{
    const int r = lane & 7, g = lane >> 3;
    const uint32_t rx = (uint32_t)r << 4;
    const uint32_t baseA = stg + (uint32_t)(wm * 64 + (g & 1) * 8 + r) * 128;
    const uint32_t hA4   = (uint32_t)(g >> 1) << 4;
    const uint32_t baseB = stg + 16384 + (uint32_t)(wn * 32 + (g >> 1) * 8 + r) * 128;
    const uint32_t hB4   = (uint32_t)(g & 1) << 4;

    #pragma unroll
    for (int s = 0; s < 4; ++s) {
        const uint32_t offA = (((uint32_t)s << 5) | hA4) ^ rx;
        const uint32_t offB = (((uint32_t)s << 5) | hB4) ^ rx;
        uint32_t ah[4][4], bh[2][4];
        #pragma unroll
        for (int i = 0; i < 4; ++i)
            ldm4(ah[i], baseA + i * 2048 + offA);
        #pragma unroll
        for (int j = 0; j < 2; ++j)
            ldm4(bh[j], baseB + j * 2048 + offB);
        #pragma unroll
        for (int i = 0; i < 4; ++i)
            #pragma unroll
            for (int q = 0; q < 4; ++q)
                mma_f16(acc[i][q], ah[i], &bh[q >> 1][(q & 1) * 2]);
    }
}

template<int EPI>
__global__ __launch_bounds__(256, 2)
void gemm_fp16(const __half* __restrict__ A, const __half* __restrict__ B,
               const float* __restrict__ bias, float* __restrict__ C)
{
    extern __shared__ __align__(1024) char smbuf[];
    uint32_t sb = smem_u32(smbuf);
    const int t    = threadIdx.x;
    const int lane = t & 31, wid = t >> 5;
    const int wm   = wid >> 2, wn = wid & 3;
    const int m0   = blockIdx.y * 128;
    const int n0   = blockIdx.x * 128;

    float acc[4][4][4];
    #pragma unroll
    for (int i = 0; i < 4; ++i)
        #pragma unroll
        for (int q = 0; q < 4; ++q)
            #pragma unroll
            for (int k = 0; k < 4; ++k) acc[i][q][k] = 0.f;

    const __half* pA = A + (size_t)m0 * KDIM;
    const __half* pB = B + (size_t)n0 * KDIM;

    load_stage32(sb,          t, 0,  pA, pB);
    load_stage32(sb + STG_SZ, t, BK, pA, pB);

    int bc = 0, bl2 = 2;   // rotating buffers: kt%3, (kt+2)%3
    #pragma unroll 1
    for (int kt = 0; kt < NKCH; ++kt) {
        if (kt == NKCH - 1) asm volatile("cp.async.wait_group 0;" ::: "memory");
        else                asm volatile("cp.async.wait_group 1;" ::: "memory");
        __syncthreads();
        // load into buffer whose compute finished at stage kt-1 (covered by sync)
        if (kt + 2 < NKCH)
            load_stage32(sb + bl2 * STG_SZ, t, (kt + 2) * BK, pA, pB);
        compute_stage(sb + bc * STG_SZ, wm, wn, lane, acc);
        bc  = (bc  == 2) ? 0 : bc  + 1;
        bl2 = (bl2 == 2) ? 0 : bl2 + 1;
    }

    const int mr  = (lane >> 2);
    const int nc0 = (lane & 3) * 2;
    if (EPI == 0) {
        const int which = n0 >> 11;
        const int h     = (n0 >> 7) & 15;
        float* dst = (which == 0) ? (float*)g_q
                   : (which == 1) ? (float*)g_k : (float*)g_v;
        const int b = m0 >> 11;
        #pragma unroll
        for (int i = 0; i < 4; ++i) {
            const int m  = m0 + wm * 64 + i * 16 + mr;
            const int tq = m & 2047;
            #pragma unroll
            for (int q = 0; q < 4; ++q) {
                const int dl = wn * 32 + q * 8 + nc0;
                float2 bs = *(const float2*)&bias[n0 + dl];
                size_t off = ((size_t)(b * 16 + h) * NT + tq) * ND + dl;
                float2 v0, v1;
                v0.x = acc[i][q][0] + bs.x;  v0.y = acc[i][q][1] + bs.y;
                v1.x = acc[i][q][2] + bs.x;  v1.y = acc[i][q][3] + bs.y;
                *(float2*)&dst[off]            = v0;
                *(float2*)&dst[off + 8 * ND]   = v1;
            }
        }
    } else {
        #pragma unroll
        for (int i = 0; i < 4; ++i) {
            const int m = m0 + wm * 64 + i * 16 + mr;
            #pragma unroll
            for (int q = 0; q < 4; ++q) {
                const int n = n0 + wn * 32 + q * 8 + nc0;
                float2 bs = *(const float2*)&bias[n];
                float2 v0, v1;
                v0.x = acc[i][q][0] + bs.x;  v0.y = acc[i][q][1] + bs.y;
                v1.x = acc[i][q][2] + bs.x;  v1.y = acc[i][q][3] + bs.y;
                *(float2*)&C[(size_t)m * NC + n]       = v0;
                *(float2*)&C[(size_t)(m + 8) * NC + n] = v1;
            }
        }
    }
}

// ---------------------------------------------------------------------------
// fp32 -> fp16 convert (x input)
// ---------------------------------------------------------------------------
__global__ void conv_f16_kernel(const float* __restrict__ in,
                                __half* __restrict__ out, int n4)
{
    int i = blockIdx.x * blockDim.x + threadIdx.x;
    if (i >= n4) return;
    float4 v = ((const float4*)in)[i];
    uint32_t* op = (uint32_t*)out;
    op[2 * i]     = packh(v.x, v.y);
    op[2 * i + 1] = packh(v.z, v.w);
}

// ---------------------------------------------------------------------------
// fp32 [K][N] -> transposed fp16 [N][K]  (weights)
// ---------------------------------------------------------------------------
__global__ void transpose_conv_kernel(const float* __restrict__ in,
                                      __half* __restrict__ out,
                                      int K, int N)
{
    __shared__ float tile[32][33];
    const int n0 = blockIdx.x * 32, k0 = blockIdx.y * 32;
    const int tx = threadIdx.x, ty = threadIdx.y;
    #pragma unroll
    for (int i = 0; i < 32; i += 8)
        tile[ty + i][tx] = in[(size_t)(k0 + ty + i) * N + n0 + tx];
    __syncthreads();
    #pragma unroll
    for (int i = 0; i < 32; i += 8) {
        size_t o = (size_t)(n0 + ty + i) * K + k0 + tx;
        out[o] = __float2half_rn(tile[tx][ty + i]);
    }
}

// ---------------------------------------------------------------------------
// RoPE fused with fp16 conversion: q and k -> plain fp16 (same path)
// ---------------------------------------------------------------------------
__global__ void rope_conv_kernel()
{
    const int PER = NBH * NT * 32;  // 4194304
    int idx = blockIdx.x * blockDim.x + threadIdx.x;
    const bool isK = idx >= PER;
    int r = isK ? idx - PER : idx;
    const float* src = isK ? (const float*)g_k : (const float*)g_q;
    __half* dst = isK ? (__half*)g_kh : (__half*)g_qh;
    int fi   = r & 31;
    int tpos = (r >> 5) & (NT - 1);
    int bh   = r >> 16;
    size_t base = ((size_t)bh * NT + tpos) * ND;
    float2 x1 = *(const float2*)&src[base + 2 * fi];
    float2 x2 = *(const float2*)&src[base + 2 * fi + 64];
    float y1x, y1y, y2x, y2y;
    {
        float f = 2.0f * fi;
        float th = powf(10000.0f, -f * (1.0f / 64.0f));
        float s, c; sincosf((float)tpos * th, &s, &c);
        y1x = x1.x * c - x2.x * s;  y2x = x1.x * s + x2.x * c;
    }
    {
        float f = 2.0f * fi + 1.0f;
        float th = powf(10000.0f, -f * (1.0f / 64.0f));
        float s, c; sincosf((float)tpos * th, &s, &c);
        y1y = x1.y * c - x2.y * s;  y2y = x1.y * s + x2.y * c;
    }
    *(uint32_t*)&dst[base + 2 * fi]      = packh(y1x, y1y);
    *(uint32_t*)&dst[base + 2 * fi + 64] = packh(y2x, y2y);
}

// ---------------------------------------------------------------------------
// v fp32 [bh][t][d] -> transposed fp16 [bh][d][t]
// ---------------------------------------------------------------------------
__global__ void vconv_kernel()
{
    __shared__ float tile[32][33];
    const int bh = blockIdx.z;
    const int t0 = blockIdx.x * 32, d0 = blockIdx.y * 32;
    const int tx = threadIdx.x, ty = threadIdx.y;
    const float* src = (const float*)g_v + (size_t)bh * NT * ND;
    #pragma unroll
    for (int i = 0; i < 32; i += 8)
        tile[ty + i][tx] = src[(size_t)(t0 + ty + i) * ND + d0 + tx];
    __syncthreads();
    __half* dh = (__half*)g_vT + (size_t)bh * ND * NT;
    #pragma unroll
    for (int i = 0; i < 32; i += 8) {
        size_t o = (size_t)(d0 + ty + i) * NT + t0 + tx;
        dh[o] = __float2half_rn(tile[tx][ty + i]);
    }
}

// ---------------------------------------------------------------------------
// Flash attention, plain fp16 mma.sync (unchanged from R11).
// smem: 3 x 32KB K/V stages + Q 32KB = 128KB.
// ---------------------------------------------------------------------------
#define ASTG 32768
#define ATTN_SMEM (3*ASTG + 32768)   // 131072

__device__ __forceinline__ void attn_load_kv(uint32_t stg, int t, int bh, int kb)
{
    const size_t koff = ((size_t)bh * NT + kb * 64) * ND;
    #pragma unroll
    for (int i = 0; i < 4; ++i) {
        int idx = t + i * 256;
        int r = idx >> 4, c = idx & 15;
        uint32_t dst = stg + r * 256 + ((c ^ (r & 7)) << 4);
        cp16(dst, (const __half*)g_kh + koff + (size_t)r * ND + c * 8);
    }
    const size_t voff = (size_t)bh * ND * NT + kb * 64;
    #pragma unroll
    for (int i = 0; i < 4; ++i) {
        int idx = t + i * 256;
        int r = idx >> 3, c = idx & 7;
        uint32_t dst = stg + 16384 + r * 128 + ((c ^ (r & 7)) << 4);
        cp16(dst, (const __half*)g_vT + voff + (size_t)r * NT + c * 8);
    }
    asm volatile("cp.async.commit_group;" ::: "memory");
}

__global__ __launch_bounds__(256, 1)
void attn_mma_kernel()
{
    extern __shared__ __align__(1024) char abuf[];
    uint32_t sb = smem_u32(abuf);
    const int t = threadIdx.x, lane = t & 31, w = t >> 5;
    const int lam = lane & 3, ldiv = lane >> 2;
    const int g = lane >> 3, r8 = lane & 7;
    const int qb = 15 - (int)blockIdx.x;   // heavy q-blocks first
    const int bh = blockIdx.y;
    const float C1 = 0.08838834764831845f * 1.4426950408889634f; // scale*log2e

    // Q tile (128 x 128) plain fp16: 128 rows x 16 chunks = 2048 chunks
    const uint32_t qreg = sb + 3 * ASTG;
    const size_t qoff = ((size_t)bh * NT + qb * 128) * ND;
    #pragma unroll
    for (int i = 0; i < 8; ++i) {
        int idx = t + i * 256;
        int r = idx >> 4, c = idx & 15;
        uint32_t dst = qreg + r * 256 + ((c ^ (r & 7)) << 4);
        cp16(dst, (const __half*)g_qh + qoff + (size_t)r * ND + c * 8);
    }
    asm volatile("cp.async.commit_group;" ::: "memory");   // group: Q
    const int nkt = 2 * qb + 2;
    attn_load_kv(sb,        t, bh, 0);
    attn_load_kv(sb + ASTG, t, bh, 1);

    // Hoist Q fragments to registers
    asm volatile("cp.async.wait_group 2;" ::: "memory");
    __syncthreads();
    uint32_t qh[8][4];
    {
        const uint32_t aQ = qreg + (uint32_t)(w * 16 + (g & 1) * 8 + r8) * 256;
        #pragma unroll
        for (int s = 0; s < 8; ++s) {
            uint32_t cA = ((uint32_t)(2 * s + (g >> 1)) ^ (uint32_t)r8) << 4;
            ldm4(qh[s], aQ + cA);
        }
    }

    float oacc[16][4];
    #pragma unroll
    for (int i = 0; i < 16; ++i)
        #pragma unroll
        for (int j = 0; j < 4; ++j) oacc[i][j] = 0.f;
    float m0 = -INFINITY, m1 = -INFINITY, l0 = 0.f, l1 = 0.f;

    const int rowbase = qb * 128 + w * 16;

    int bc = 0, bl2 = 2;
    #pragma unroll 1
    for (int kb = 0; kb < nkt; ++kb) {
        if (kb == nkt - 1) asm volatile("cp.async.wait_group 0;" ::: "memory");
        else               asm volatile("cp.async.wait_group 1;" ::: "memory");
        __syncthreads();
        if (kb + 2 < nkt) attn_load_kv(sb + bl2 * ASTG, t, bh, kb + 2);
        uint32_t stg = sb + bc * ASTG;
        bc  = (bc  == 2) ? 0 : bc  + 1;
        bl2 = (bl2 == 2) ? 0 : bl2 + 1;

        if (kb * 64 <= rowbase + 15) {
            // ---- S = Q K^T (plain fp16) ----
            float sacc[8][4];
            #pragma unroll
            for (int i = 0; i < 8; ++i)
                #pragma unroll
                for (int j = 0; j < 4; ++j) sacc[i][j] = 0.f;

            const uint32_t aK = stg + (uint32_t)((g >> 1) * 8 + r8) * 256;
            #pragma unroll
            for (int s = 0; s < 8; ++s) {
                uint32_t cB = ((uint32_t)(2 * s + (g & 1)) ^ (uint32_t)r8) << 4;
                #pragma unroll
                for (int ng = 0; ng < 4; ++ng) {
                    uint32_t k4[4];
                    ldm4(k4, aK + (uint32_t)ng * (16 * 256) + cB);
                    mma_f16(sacc[ng*2],   qh[s], &k4[0]);
                    mma_f16(sacc[ng*2+1], qh[s], &k4[2]);
                }
            }

            // ---- scale (+ causal mask on diagonal tiles), log2 domain ----
            if (kb >= 2 * qb) {
                #pragma unroll
                for (int nt = 0; nt < 8; ++nt)
                    #pragma unroll
                    for (int j = 0; j < 4; ++j) {
                        int col = kb * 64 + nt * 8 + lam * 2 + (j & 1);
                        int row = rowbase + ldiv + ((j >> 1) << 3);
                        sacc[nt][j] = (col <= row) ? sacc[nt][j] * C1 : -1e30f;
                    }
            } else {
                #pragma unroll
                for (int nt = 0; nt < 8; ++nt)
                    #pragma unroll
                    for (int j = 0; j < 4; ++j) sacc[nt][j] *= C1;
            }

            // ---- online softmax (rows r and r+8) ----
            float mr0 = -1e30f, mr1 = -1e30f;
            #pragma unroll
            for (int nt = 0; nt < 8; ++nt) {
                mr0 = fmaxf(mr0, fmaxf(sacc[nt][0], sacc[nt][1]));
                mr1 = fmaxf(mr1, fmaxf(sacc[nt][2], sacc[nt][3]));
            }
            mr0 = fmaxf(mr0, __shfl_xor_sync(0xffffffffu, mr0, 1));
            mr0 = fmaxf(mr0, __shfl_xor_sync(0xffffffffu, mr0, 2));
            mr1 = fmaxf(mr1, __shfl_xor_sync(0xffffffffu, mr1, 1));
            mr1 = fmaxf(mr1, __shfl_xor_sync(0xffffffffu, mr1, 2));
            float mn0 = fmaxf(m0, mr0), mn1 = fmaxf(m1, mr1);
            float al0 = ex2(m0 - mn0), al1 = ex2(m1 - mn1);
            m0 = mn0; m1 = mn1;
            float ls0 = 0.f, ls1 = 0.f;
            #pragma unroll
            for (int nt = 0; nt < 8; ++nt) {
                float p0 = ex2(sacc[nt][0] - mn0);
                float p1 = ex2(sacc[nt][1] - mn0);
                float p2 = ex2(sacc[nt][2] - mn1);
                float p3 = ex2(sacc[nt][3] - mn1);
                sacc[nt][0] = p0; sacc[nt][1] = p1;
                sacc[nt][2] = p2; sacc[nt][3] = p3;
                ls0 += p0 + p1;  ls1 += p2 + p3;
            }
            ls0 += __shfl_xor_sync(0xffffffffu, ls0, 1);
            ls0 += __shfl_xor_sync(0xffffffffu, ls0, 2);
            ls1 += __shfl_xor_sync(0xffffffffu, ls1, 1);
            ls1 += __shfl_xor_sync(0xffffffffu, ls1, 2);
            l0 = l0 * al0 + ls0;  l1 = l1 * al1 + ls1;
            #pragma unroll
            for (int i = 0; i < 16; ++i) {
                oacc[i][0] *= al0;  oacc[i][1] *= al0;
                oacc[i][2] *= al1;  oacc[i][3] *= al1;
            }

            // ---- O += P V (plain fp16 P) ----
            const uint32_t aV = stg + 16384 + (uint32_t)((g >> 1) * 8 + r8) * 128;
            #pragma unroll
            for (int s2 = 0; s2 < 4; ++s2) {
                uint32_t ph[4];
                ph[0] = packh(sacc[2*s2][0],   sacc[2*s2][1]);
                ph[1] = packh(sacc[2*s2][2],   sacc[2*s2][3]);
                ph[2] = packh(sacc[2*s2+1][0], sacc[2*s2+1][1]);
                ph[3] = packh(sacc[2*s2+1][2], sacc[2*s2+1][3]);
                uint32_t cV = ((uint32_t)(2 * s2 + (g & 1)) ^ (uint32_t)r8) << 4;
                #pragma unroll
                for (int ng = 0; ng < 8; ++ng) {
                    uint32_t v4[4];
                    ldm4(v4, aV + (uint32_t)ng * (16 * 128) + cV);
                    mma_f16(oacc[ng*2],   ph, &v4[0]);
                    mma_f16(oacc[ng*2+1], ph, &v4[2]);
                }
            }
        }
    }

    // ---- finalize: /l, write fp16 att [b,t,h*128+d] ----
    float inv0 = 1.f / l0, inv1 = 1.f / l1;
    const int b = bh >> 4, h = bh & 15;
    const int row0 = qb * 128 + w * 16 + ldiv;
    const size_t obase = ((size_t)b * NT + row0) * NC + h * ND;
    #pragma unroll
    for (int nt = 0; nt < 16; ++nt) {
        const int d = nt * 8 + lam * 2;
        *(uint32_t*)&g_attf[obase + d]          = packh(oacc[nt][0] * inv0, oacc[nt][1] * inv0);
        *(uint32_t*)&g_attf[obase + 8 * NC + d] = packh(oacc[nt][2] * inv1, oacc[nt][3] * inv1);
    }
}

// ---------------------------------------------------------------------------
// Launch
// ---------------------------------------------------------------------------
extern "C" void kernel_launch(void* const* d_in, const int* in_sizes, int n_in,
                              void* d_out, int out_size)
{
    const float* x    = (const float*)d_in[0];
    const float* Wqkv = (const float*)d_in[1];
    const float* bqkv = (const float*)d_in[2];
    const float* Wo   = (const float*)d_in[3];
    const float* bo   = (const float*)d_in[4];
    float* out = (float*)d_out;

    cudaFuncSetAttribute(gemm_fp16<0>,
                         cudaFuncAttributeMaxDynamicSharedMemorySize, GEMM_SMEM);
    cudaFuncSetAttribute(gemm_fp16<1>,
                         cudaFuncAttributeMaxDynamicSharedMemorySize, GEMM_SMEM);
    cudaFuncSetAttribute(attn_mma_kernel,
                         cudaFuncAttributeMaxDynamicSharedMemorySize, ATTN_SMEM);

    __half *xh, *Wh, *Woh, *attf;
    cudaGetSymbolAddress((void**)&xh,   g_xh);
    cudaGetSymbolAddress((void**)&Wh,   g_Wh);
    cudaGetSymbolAddress((void**)&Woh,  g_Woh);
    cudaGetSymbolAddress((void**)&attf, g_attf);

    // 1) conversions: x -> fp16 ; Wqkv^T, Wo^T -> fp16
    conv_f16_kernel<<<16384, 256>>>(x, xh, 4194304);
    transpose_conv_kernel<<<dim3(192, 64), dim3(32, 8)>>>(Wqkv, Wh, 2048, 6144);
    transpose_conv_kernel<<<dim3(64, 64),  dim3(32, 8)>>>(Wo, Woh, 2048, 2048);

    // 2) QKV = x @ Wqkv + bqkv (fp16 mma) -> g_q/g_k/g_v fp32 head-major
    gemm_fp16<0><<<dim3(48, 64), 256, GEMM_SMEM>>>(xh, Wh, bqkv, nullptr);

    // 3) RoPE + fp16 conversion (q and k plain)
    rope_conv_kernel<<<32768, 256>>>();

    // 4) v transpose -> fp16 [bh][d][t]
    vconv_kernel<<<dim3(64, 4, 64), dim3(32, 8)>>>();

    // 5) flash attention (plain fp16 mma.sync) -> g_attf
    attn_mma_kernel<<<dim3(16, 64), 256, ATTN_SMEM>>>();

    // 6) out = att @ Wo + bo (fp16 mma)
    gemm_fp16<1><<<dim3(16, 64), 256, GEMM_SMEM>>>(attf, Woh, bo, out);
}